// round 11
// baseline (speedup 1.0000x reference)
#include <cuda_runtime.h>
#include <cuda_fp16.h>
#include <cstdint>

// ================= static scratch =================
#define NMAX 100352
#define EMAX 1700000

__device__ int   g_deg[NMAX];     // zeroed at load; re-zeroed by k_agg9 each launch
__device__ int   g_off[NMAX + 1];
__device__ int   g_cur[NMAX];
__device__ int   g_csr[EMAX];
__device__ int   g_bsum[128];
__device__ float g_cnt[NMAX];
__device__ float g_ym9[(size_t)NMAX * 9];
__device__ float g_yr9[(size_t)NMAX * 9];
// fp16 activations / means
__device__ __align__(16) __half g_hz[(size_t)NMAX * 128];
__device__ __align__(16) __half g_hA[(size_t)NMAX * 256];
__device__ __align__(16) __half g_hB[(size_t)NMAX * 256];
__device__ __align__(16) __half g_hM[(size_t)NMAX * 256];
// k-paired half2 weights: Wp[k/2][N], elem = (lo=W[2k][n], hi=W[2k+1][n])
__device__ uint32_t g_w1m[64 * 256];
__device__ uint32_t g_w1r[64 * 256];
__device__ uint32_t g_w2m[128 * 256];
__device__ uint32_t g_w2r[128 * 256];
__device__ uint32_t g_w3m[128 * 128];
__device__ uint32_t g_w3r[128 * 128];

// ================= helpers =================
__device__ __forceinline__ uint32_t f2h2(float lo, float hi) {
    uint32_t r;
    asm("cvt.rn.f16x2.f32 %0, %1, %2;" : "=r"(r) : "f"(hi), "f"(lo));
    return r;
}
__device__ __forceinline__ void mma_f16(float* c, uint32_t a0, uint32_t a1, uint32_t a2, uint32_t a3,
                                        uint32_t b0, uint32_t b1) {
    asm volatile("mma.sync.aligned.m16n8k16.row.col.f32.f16.f16.f32 "
                 "{%0,%1,%2,%3}, {%4,%5,%6,%7}, {%8,%9}, {%0,%1,%2,%3};"
                 : "+f"(c[0]), "+f"(c[1]), "+f"(c[2]), "+f"(c[3])
                 : "r"(a0), "r"(a1), "r"(a2), "r"(a3), "r"(b0), "r"(b1));
}
__device__ __forceinline__ uint32_t su32(const void* p) {
    uint32_t a;
    asm("{ .reg .u64 t; cvta.to.shared.u64 t, %1; cvt.u32.u64 %0, t; }" : "=r"(a) : "l"(p));
    return a;
}
__device__ __forceinline__ void cpa16(uint32_t dst, const void* src, bool pred) {
    int sz = pred ? 16 : 0;
    asm volatile("cp.async.cg.shared.global [%0], [%1], 16, %2;" :: "r"(dst), "l"(src), "r"(sz));
}
#define CP_COMMIT() asm volatile("cp.async.commit_group;" ::: "memory")
#define CP_WAIT1()  asm volatile("cp.async.wait_group 1;" ::: "memory")
#define CP_WAIT0()  asm volatile("cp.async.wait_group 0;" ::: "memory")

// ================= CSR build =================
__global__ void k_hist(const int* __restrict__ dst, int E) {
    int e = blockIdx.x * blockDim.x + threadIdx.x;
    if (e < E) atomicAdd(&g_deg[dst[e]], 1);
}
// 3-kernel parallel scan
__global__ void k_scan1(int n) {
    __shared__ int sh[1024];
    int i = blockIdx.x * 1024 + threadIdx.x;
    int d = (i < n) ? g_deg[i] : 0;
    sh[threadIdx.x] = d;
    __syncthreads();
    for (int o = 1; o < 1024; o <<= 1) {
        int v = (threadIdx.x >= o) ? sh[threadIdx.x - o] : 0;
        __syncthreads();
        sh[threadIdx.x] += v;
        __syncthreads();
    }
    if (i < n) g_off[i] = sh[threadIdx.x] - d;   // exclusive within block
    if (threadIdx.x == 1023) g_bsum[blockIdx.x] = sh[1023];
}
__global__ void k_scan2(int nb) {
    __shared__ int sh[128];
    int d = (threadIdx.x < nb) ? g_bsum[threadIdx.x] : 0;
    sh[threadIdx.x] = d;
    __syncthreads();
    for (int o = 1; o < 128; o <<= 1) {
        int v = (threadIdx.x >= o) ? sh[threadIdx.x - o] : 0;
        __syncthreads();
        sh[threadIdx.x] += v;
        __syncthreads();
    }
    if (threadIdx.x < nb) g_bsum[threadIdx.x] = sh[threadIdx.x] - d;  // exclusive
}
__global__ void k_scan3(int n, int E) {
    int i = blockIdx.x * blockDim.x + threadIdx.x;
    if (i == 0) g_off[n] = E;
    if (i >= n) return;
    int off = g_off[i] + g_bsum[i >> 10];
    g_off[i] = off;
    g_cur[i] = off;
    int d = g_deg[i];
    g_cnt[i] = (d > 0) ? (float)d : 1.0f;
}
__global__ void k_scatter(const int* __restrict__ src, const int* __restrict__ dst, int E) {
    int e = blockIdx.x * blockDim.x + threadIdx.x;
    if (e < E) {
        int p = atomicAdd(&g_cur[dst[e]], 1);
        g_csr[p] = src[e];
    }
}

// ================= conversions / packing =================
__global__ void k_z2h(const float* __restrict__ z, __half* __restrict__ zh, int n2) {
    int i = blockIdx.x * blockDim.x + threadIdx.x;
    if (i >= n2) return;
    float2 v = ((const float2*)z)[i];
    ((__half2*)zh)[i] = __floats2half2_rn(v.x, v.y);
}
__global__ void k_packh2(const float* __restrict__ W, uint32_t* __restrict__ Wp, int KH, int N) {
    int i = blockIdx.x * blockDim.x + threadIdx.x;
    if (i >= KH * N) return;
    int kp = i / N, n = i - kp * N;
    Wp[i] = f2h2(W[(size_t)(2 * kp) * N + n], W[(size_t)(2 * kp + 1) * N + n]);
}

// ================= mean aggregation (half in/out, fp32 acc) =================
template <int D>
__global__ void k_aggh(const __half* __restrict__ x, __half* __restrict__ meanp, int n) {
    int gw = (blockIdx.x * blockDim.x + threadIdx.x) >> 5;
    int lane = threadIdx.x & 31;
    if (gw >= n) return;
    int b = g_off[gw], e = g_off[gw + 1];
    constexpr int NH2 = D / 64;
    float2 acc[NH2], acc2[NH2];
#pragma unroll
    for (int h = 0; h < NH2; h++) {
        acc[h] = make_float2(0.f, 0.f);
        acc2[h] = make_float2(0.f, 0.f);
    }
    auto addrow = [&](const __half* rp, float2* a) {
        uint32_t w[NH2];
        if (NH2 == 4) {
            uint4 u = ((const uint4*)rp)[lane];
            w[0] = u.x; w[1] = u.y; w[2] = u.z; w[3] = u.w;
        } else {
            uint2 u = ((const uint2*)rp)[lane];
            w[0] = u.x; w[1] = u.y;
        }
#pragma unroll
        for (int h = 0; h < NH2; h++) {
            float2 f = __half22float2(*(__half2*)&w[h]);
            a[h].x += f.x;
            a[h].y += f.y;
        }
    };
    int j = b;
    for (; j + 1 < e; j += 2) {
        addrow(x + (size_t)g_csr[j] * D, acc);
        addrow(x + (size_t)g_csr[j + 1] * D, acc2);
    }
    if (j < e) addrow(x + (size_t)g_csr[j] * D, acc);

    float inv = 1.0f / g_cnt[gw];
    uint32_t o[NH2];
#pragma unroll
    for (int h = 0; h < NH2; h++) {
        __half2 hv = __floats2half2_rn((acc[h].x + acc2[h].x) * inv, (acc[h].y + acc2[h].y) * inv);
        o[h] = *(uint32_t*)&hv;
    }
    __half* mo = meanp + (size_t)gw * D;
    if (NH2 == 4) ((uint4*)mo)[lane] = make_uint4(o[0], o[1], o[2], o[3]);
    else ((uint2*)mo)[lane] = make_uint2(o[0], o[1]);
}

// ================= fp16 mma fused dual-GEMM + bias + LN + ReLU =================
// K-chunks of 64 halves, 3-stage cp.async pipeline (half the syncs of K=32).
// A staged as halves (pitch 72 halves = 144B; fragment bank = 4g+tq, conflict-free).
// W pre-packed half2 k-pairs (pitch DOUT+8 words; bank = 8tq+g).
template <int DIN, int DOUT>
__launch_bounds__(512)
__global__ void k_gemm_tc(const __half* __restrict__ A0, const __half* __restrict__ A1,
                          const uint32_t* __restrict__ W0p, const uint32_t* __restrict__ W1p,
                          const float* __restrict__ bias, const float* __restrict__ gamma,
                          const float* __restrict__ beta, __half* __restrict__ out, int n) {
    extern __shared__ float sm[];
    constexpr int NCH = DIN / 64;         // 64 k-halves per chunk
    constexpr int TOT = 2 * NCH;
    constexpr int NT = DOUT / 32;
    constexpr int APH = 72;               // A pitch in halves (144 B)
    constexpr int AHSZ = 128 * APH;       // halves per A stage
    constexpr int BPH = DOUT + 8;         // B pitch (half2 words)
    constexpr int BSZ = 32 * BPH;         // words per B stage (32 half2 k-rows)

    __half* Ah = (__half*)sm;
    __half* Ab[3] = { Ah, Ah + AHSZ, Ah + 2 * AHSZ };
    float* after = sm + (3 * AHSZ) / 2;
    uint32_t* Bb[3] = { (uint32_t*)after, (uint32_t*)after + BSZ, (uint32_t*)after + 2 * BSZ };
    float* sp = after + 3 * BSZ;          // bias|gamma|beta
    float* sln = sp + 3 * DOUT;           // [128][4] float2

    int t = threadIdx.x;
    int wid = t >> 5, lane = t & 31;
    int g = lane >> 2, tq = lane & 3;
    int mw = wid & 3, nq = wid >> 2;
    int nbase = nq * (DOUT / 4);
    int row0 = blockIdx.x * 128;

    for (int i = t; i < DOUT; i += 512) {
        sp[i] = bias[i];
        sp[DOUT + i] = gamma[i];
        sp[2 * DOUT + i] = beta[i];
    }
    __syncthreads();

    float acc[2][NT][4];
#pragma unroll
    for (int ms = 0; ms < 2; ms++)
#pragma unroll
        for (int nt = 0; nt < NT; nt++)
#pragma unroll
            for (int j = 0; j < 4; j++) acc[ms][nt][j] = 0.f;

    auto copy_chunk = [&](int c, int ib) {
        const __half* A = (c < NCH) ? A0 : A1;
        const uint32_t* W = (c < NCH) ? W0p : W1p;
        int cc = (c < NCH) ? c : c - NCH;
        int k0 = cc * 64;        // half k base
        int kph = cc * 32;       // half2 W row base
        uint32_t abase = su32(Ab[ib]);
        uint32_t bbase = su32(Bb[ib]);
#pragma unroll
        for (int i = 0; i < 2; i++) {          // A: 128 rows x 128B = 1024 cp16
            int s = t + i * 512;
            int r = s >> 3, seg = s & 7;
            int gr = row0 + r;
            bool ok = gr < n;
            int cr = ok ? gr : (n - 1);
            cpa16(abase + (uint32_t)(r * 144 + seg * 16),
                  A + (size_t)cr * DIN + k0 + seg * 8, ok);
        }
#pragma unroll
        for (int i = 0; i < DOUT / 64; i++) {  // B: 32 rows x DOUT half2
            int s = t + i * 512;
            int kr = s / (DOUT / 4), c4 = s % (DOUT / 4);
            cpa16(bbase + (uint32_t)(kr * BPH + c4 * 4) * 4,
                  W + (size_t)(kph + kr) * DOUT + c4 * 4, true);
        }
    };

    auto mma_chunk = [&](int ib) {
        const __half* As = Ab[ib];
        const uint32_t* Bs = Bb[ib];
#pragma unroll
        for (int ks = 0; ks < 4; ks++) {
            int kb = ks * 16;    // half col base
            int kpb = ks * 8;    // half2 B row base
            uint32_t bf0[NT], bf1[NT];
#pragma unroll
            for (int nt = 0; nt < NT; nt++) {
                int nn = nbase + nt * 8 + g;
                bf0[nt] = Bs[(kpb + tq) * BPH + nn];
                bf1[nt] = Bs[(kpb + tq + 4) * BPH + nn];
            }
#pragma unroll
            for (int ms = 0; ms < 2; ms++) {
                int ar = mw * 32 + ms * 16 + g;
                uint32_t a0 = *(const uint32_t*)&As[ar * APH + kb + 2 * tq];
                uint32_t a1 = *(const uint32_t*)&As[(ar + 8) * APH + kb + 2 * tq];
                uint32_t a2 = *(const uint32_t*)&As[ar * APH + kb + 2 * tq + 8];
                uint32_t a3 = *(const uint32_t*)&As[(ar + 8) * APH + kb + 2 * tq + 8];
#pragma unroll
                for (int nt = 0; nt < NT; nt++)
                    mma_f16(acc[ms][nt], a0, a1, a2, a3, bf0[nt], bf1[nt]);
            }
        }
    };

    copy_chunk(0, 0); CP_COMMIT();
    copy_chunk(1, 1); CP_COMMIT();
    for (int c = 0; c < TOT; c++) {
        if (c < TOT - 1) CP_WAIT1(); else CP_WAIT0();
        __syncthreads();
        if (c + 2 < TOT) { copy_chunk(c + 2, (c + 2) % 3); CP_COMMIT(); }
        mma_chunk(c % 3);
    }

    // ---- epilogue: +bias, LN over DOUT (4 n-quarter partials), ReLU, fp16 out ----
#pragma unroll
    for (int ms = 0; ms < 2; ms++) {
        float s0 = 0.f, ss0 = 0.f, s1 = 0.f, ss1 = 0.f;
#pragma unroll
        for (int nt = 0; nt < NT; nt++) {
            int col = nbase + nt * 8 + 2 * tq;
            float b0 = sp[col], b1 = sp[col + 1];
            acc[ms][nt][0] += b0; acc[ms][nt][1] += b1;
            acc[ms][nt][2] += b0; acc[ms][nt][3] += b1;
            s0 += acc[ms][nt][0] + acc[ms][nt][1];
            ss0 += acc[ms][nt][0] * acc[ms][nt][0] + acc[ms][nt][1] * acc[ms][nt][1];
            s1 += acc[ms][nt][2] + acc[ms][nt][3];
            ss1 += acc[ms][nt][2] * acc[ms][nt][2] + acc[ms][nt][3] * acc[ms][nt][3];
        }
#pragma unroll
        for (int o = 1; o <= 2; o <<= 1) {
            s0 += __shfl_xor_sync(0xffffffffu, s0, o);
            ss0 += __shfl_xor_sync(0xffffffffu, ss0, o);
            s1 += __shfl_xor_sync(0xffffffffu, s1, o);
            ss1 += __shfl_xor_sync(0xffffffffu, ss1, o);
        }
        if (tq == 0) {
            int r0 = mw * 32 + ms * 16 + g;
            ((float2*)sln)[r0 * 4 + nq] = make_float2(s0, ss0);
            ((float2*)sln)[(r0 + 8) * 4 + nq] = make_float2(s1, ss1);
        }
    }
    __syncthreads();
#pragma unroll
    for (int ms = 0; ms < 2; ms++) {
        int rl0 = mw * 32 + ms * 16 + g, rl1 = rl0 + 8;
        float s0 = 0.f, ss0 = 0.f, s1 = 0.f, ss1 = 0.f;
#pragma unroll
        for (int q = 0; q < 4; q++) {
            float2 p0 = ((float2*)sln)[rl0 * 4 + q];
            float2 p1 = ((float2*)sln)[rl1 * 4 + q];
            s0 += p0.x; ss0 += p0.y;
            s1 += p1.x; ss1 += p1.y;
        }
        float mu0 = s0 * (1.0f / DOUT);
        float rs0 = rsqrtf(ss0 * (1.0f / DOUT) - mu0 * mu0 + 1e-5f);
        float mu1 = s1 * (1.0f / DOUT);
        float rs1 = rsqrtf(ss1 * (1.0f / DOUT) - mu1 * mu1 + 1e-5f);
        int grow0 = row0 + rl0, grow1 = row0 + rl1;
#pragma unroll
        for (int nt = 0; nt < NT; nt++) {
            int col = nbase + nt * 8 + 2 * tq;
            float ga0 = sp[DOUT + col], ga1 = sp[DOUT + col + 1];
            float bt0 = sp[2 * DOUT + col], bt1 = sp[2 * DOUT + col + 1];
            if (grow0 < n) {
                float vx = fmaxf((acc[ms][nt][0] - mu0) * rs0 * ga0 + bt0, 0.f);
                float vy = fmaxf((acc[ms][nt][1] - mu0) * rs0 * ga1 + bt1, 0.f);
                *(__half2*)(out + (size_t)grow0 * DOUT + col) = __floats2half2_rn(vx, vy);
            }
            if (grow1 < n) {
                float vx = fmaxf((acc[ms][nt][2] - mu1) * rs1 * ga0 + bt0, 0.f);
                float vy = fmaxf((acc[ms][nt][3] - mu1) * rs1 * ga1 + bt1, 0.f);
                *(__half2*)(out + (size_t)grow1 * DOUT + col) = __floats2half2_rn(vx, vy);
            }
        }
    }
}

// ================= dual-output GEMM: YM = X@W0, YR = X@W1 + b (fp16 out) =================
template <int DIN, int DOUT>
__launch_bounds__(512)
__global__ void k_gemm_dual(const __half* __restrict__ X,
                            const uint32_t* __restrict__ W0p, const uint32_t* __restrict__ W1p,
                            const float* __restrict__ bias,
                            __half* __restrict__ ym, __half* __restrict__ yr, int n) {
    extern __shared__ float sm[];
    constexpr int NCH = DIN / 64;
    constexpr int NT = DOUT / 32;
    constexpr int APH = 72;
    constexpr int AHSZ = 128 * APH;
    constexpr int BPH = DOUT + 8;
    constexpr int BSZ = 32 * BPH;

    __half* Ah = (__half*)sm;
    __half* Ab[3] = { Ah, Ah + AHSZ, Ah + 2 * AHSZ };
    float* after = sm + (3 * AHSZ) / 2;
    uint32_t* B0b[3] = { (uint32_t*)after, (uint32_t*)after + BSZ, (uint32_t*)after + 2 * BSZ };
    uint32_t* B1b[3] = { (uint32_t*)after + 3 * BSZ, (uint32_t*)after + 4 * BSZ, (uint32_t*)after + 5 * BSZ };
    float* sp = after + 6 * BSZ;

    int t = threadIdx.x;
    int wid = t >> 5, lane = t & 31;
    int g = lane >> 2, tq = lane & 3;
    int mw = wid & 3, nq = wid >> 2;
    int nbase = nq * (DOUT / 4);
    int row0 = blockIdx.x * 128;

    for (int i = t; i < DOUT; i += 512) sp[i] = bias[i];
    __syncthreads();

    float accM[2][NT][4], accR[2][NT][4];
#pragma unroll
    for (int ms = 0; ms < 2; ms++)
#pragma unroll
        for (int nt = 0; nt < NT; nt++)
#pragma unroll
            for (int j = 0; j < 4; j++) { accM[ms][nt][j] = 0.f; accR[ms][nt][j] = 0.f; }

    auto copy_chunk = [&](int c, int ib) {
        int k0 = c * 64;
        int kph = c * 32;
        uint32_t abase = su32(Ab[ib]);
        uint32_t b0base = su32(B0b[ib]);
        uint32_t b1base = su32(B1b[ib]);
#pragma unroll
        for (int i = 0; i < 2; i++) {
            int s = t + i * 512;
            int r = s >> 3, seg = s & 7;
            int gr = row0 + r;
            bool ok = gr < n;
            int cr = ok ? gr : (n - 1);
            cpa16(abase + (uint32_t)(r * 144 + seg * 16),
                  X + (size_t)cr * DIN + k0 + seg * 8, ok);
        }
#pragma unroll
        for (int i = 0; i < DOUT / 64; i++) {
            int s = t + i * 512;
            int kr = s / (DOUT / 4), c4 = s % (DOUT / 4);
            size_t wo = (size_t)(kph + kr) * DOUT + c4 * 4;
            uint32_t so = (uint32_t)(kr * BPH + c4 * 4) * 4;
            cpa16(b0base + so, W0p + wo, true);
            cpa16(b1base + so, W1p + wo, true);
        }
    };

    auto mma_chunk = [&](int ib) {
        const __half* As = Ab[ib];
        const uint32_t* B0s = B0b[ib];
        const uint32_t* B1s = B1b[ib];
#pragma unroll
        for (int ks = 0; ks < 4; ks++) {
            int kb = ks * 16;
            int kpb = ks * 8;
            uint32_t bfM0[NT], bfM1[NT], bfR0[NT], bfR1[NT];
#pragma unroll
            for (int nt = 0; nt < NT; nt++) {
                int nn = nbase + nt * 8 + g;
                bfM0[nt] = B0s[(kpb + tq) * BPH + nn];
                bfM1[nt] = B0s[(kpb + tq + 4) * BPH + nn];
                bfR0[nt] = B1s[(kpb + tq) * BPH + nn];
                bfR1[nt] = B1s[(kpb + tq + 4) * BPH + nn];
            }
#pragma unroll
            for (int ms = 0; ms < 2; ms++) {
                int ar = mw * 32 + ms * 16 + g;
                uint32_t a0 = *(const uint32_t*)&As[ar * APH + kb + 2 * tq];
                uint32_t a1 = *(const uint32_t*)&As[(ar + 8) * APH + kb + 2 * tq];
                uint32_t a2 = *(const uint32_t*)&As[ar * APH + kb + 2 * tq + 8];
                uint32_t a3 = *(const uint32_t*)&As[(ar + 8) * APH + kb + 2 * tq + 8];
#pragma unroll
                for (int nt = 0; nt < NT; nt++) {
                    mma_f16(accM[ms][nt], a0, a1, a2, a3, bfM0[nt], bfM1[nt]);
                    mma_f16(accR[ms][nt], a0, a1, a2, a3, bfR0[nt], bfR1[nt]);
                }
            }
        }
    };

    copy_chunk(0, 0); CP_COMMIT();
    copy_chunk(1, 1); CP_COMMIT();
    for (int c = 0; c < NCH; c++) {
        if (c < NCH - 1) CP_WAIT1(); else CP_WAIT0();
        __syncthreads();
        if (c + 2 < NCH) { copy_chunk(c + 2, (c + 2) % 3); CP_COMMIT(); }
        mma_chunk(c % 3);
    }

#pragma unroll
    for (int ms = 0; ms < 2; ms++) {
        int rl0 = mw * 32 + ms * 16 + g, rl1 = rl0 + 8;
        int grow0 = row0 + rl0, grow1 = row0 + rl1;
#pragma unroll
        for (int nt = 0; nt < NT; nt++) {
            int col = nbase + nt * 8 + 2 * tq;
            float b0 = sp[col], b1 = sp[col + 1];
            if (grow0 < n) {
                *(__half2*)(ym + (size_t)grow0 * DOUT + col) = __floats2half2_rn(accM[ms][nt][0], accM[ms][nt][1]);
                *(__half2*)(yr + (size_t)grow0 * DOUT + col) = __floats2half2_rn(accR[ms][nt][0] + b0, accR[ms][nt][1] + b1);
            }
            if (grow1 < n) {
                *(__half2*)(ym + (size_t)grow1 * DOUT + col) = __floats2half2_rn(accM[ms][nt][2], accM[ms][nt][3]);
                *(__half2*)(yr + (size_t)grow1 * DOUT + col) = __floats2half2_rn(accR[ms][nt][2] + b0, accR[ms][nt][3] + b1);
            }
        }
    }
}

// ================= elementwise: out = ReLU(LN(mean + yr)), D=128, warp/row, fp16 =================
__global__ void k_addlnrelu(const __half* __restrict__ meanp, const __half* __restrict__ yr,
                            const float* __restrict__ gamma, const float* __restrict__ beta,
                            __half* __restrict__ out, int n) {
    int row = (blockIdx.x * blockDim.x + threadIdx.x) >> 5;
    int lane = threadIdx.x & 31;
    if (row >= n) return;
    uint2 mu2 = ((const uint2*)(meanp + (size_t)row * 128))[lane];
    uint2 yu2 = ((const uint2*)(yr + (size_t)row * 128))[lane];
    float2 m0 = __half22float2(*(__half2*)&mu2.x), m1 = __half22float2(*(__half2*)&mu2.y);
    float2 y0 = __half22float2(*(__half2*)&yu2.x), y1 = __half22float2(*(__half2*)&yu2.y);
    float v[4] = { m0.x + y0.x, m0.y + y0.y, m1.x + y1.x, m1.y + y1.y };
    float s = v[0] + v[1] + v[2] + v[3];
    float ss = v[0] * v[0] + v[1] * v[1] + v[2] * v[2] + v[3] * v[3];
#pragma unroll
    for (int o = 16; o; o >>= 1) {
        s += __shfl_xor_sync(0xffffffffu, s, o);
        ss += __shfl_xor_sync(0xffffffffu, ss, o);
    }
    float mu = s * (1.0f / 128.0f);
    float var = ss * (1.0f / 128.0f) - mu * mu;
    float rs = rsqrtf(var + 1e-5f);
    float4 g4 = ((const float4*)gamma)[lane];
    float4 b4 = ((const float4*)beta)[lane];
    float o0 = fmaxf((v[0] - mu) * rs * g4.x + b4.x, 0.f);
    float o1 = fmaxf((v[1] - mu) * rs * g4.y + b4.y, 0.f);
    float o2 = fmaxf((v[2] - mu) * rs * g4.z + b4.z, 0.f);
    float o3 = fmaxf((v[3] - mu) * rs * g4.w + b4.w, 0.f);
    __half2 h0 = __floats2half2_rn(o0, o1);
    __half2 h1 = __floats2half2_rn(o2, o3);
    ((uint2*)(out + (size_t)row * 128))[lane] = make_uint2(*(uint32_t*)&h0, *(uint32_t*)&h1);
}

// ================= final layer part 1: ym9 = x@Wm4, yr9 = x@Wr4 + b4 =================
__global__ void k_out_dual(const __half* __restrict__ x,
                           const float* __restrict__ wm, const float* __restrict__ wr,
                           const float* __restrict__ bias,
                           float* __restrict__ ym9, float* __restrict__ yr9, int n) {
    __shared__ float swm[128 * 9];
    __shared__ float swr[128 * 9];
    __shared__ float sb[9];
    for (int i = threadIdx.x; i < 128 * 9; i += blockDim.x) {
        swm[i] = wm[i];
        swr[i] = wr[i];
    }
    if (threadIdx.x < 9) sb[threadIdx.x] = bias[threadIdx.x];
    __syncthreads();

    int gw = (blockIdx.x * blockDim.x + threadIdx.x) >> 5;
    int lane = threadIdx.x & 31;
    if (gw >= n) return;

    uint2 u = ((const uint2*)(x + (size_t)gw * 128))[lane];
    float2 f0 = __half22float2(*(__half2*)&u.x);
    float2 f1 = __half22float2(*(__half2*)&u.y);
    float x4[4] = { f0.x, f0.y, f1.x, f1.y };

    float om[9], orr[9];
#pragma unroll
    for (int j = 0; j < 9; j++) { om[j] = 0.f; orr[j] = 0.f; }
#pragma unroll
    for (int q = 0; q < 4; q++) {
        int k = lane * 4 + q;
#pragma unroll
        for (int j = 0; j < 9; j++) {
            om[j] += x4[q] * swm[k * 9 + j];
            orr[j] += x4[q] * swr[k * 9 + j];
        }
    }
#pragma unroll
    for (int j = 0; j < 9; j++)
#pragma unroll
        for (int s = 16; s; s >>= 1) {
            om[j] += __shfl_xor_sync(0xffffffffu, om[j], s);
            orr[j] += __shfl_xor_sync(0xffffffffu, orr[j], s);
        }
    if (lane < 9) {
        ym9[(size_t)gw * 9 + lane] = om[lane];
        yr9[(size_t)gw * 9 + lane] = orr[lane] + sb[lane];
    }
}

// ================= final layer part 2: out = mean(ym9[src]) + yr9; re-zero g_deg =================
__global__ void k_agg9(const float* __restrict__ ym9, const float* __restrict__ yr9,
                       float* __restrict__ out, int n) {
    int gt = blockIdx.x * blockDim.x + threadIdx.x;
    if (gt < NMAX) g_deg[gt] = 0;
    int gw = gt >> 5;
    int lane = threadIdx.x & 31;
    if (gw >= n) return;
    int b = g_off[gw], e = g_off[gw + 1];
    float acc[9];
#pragma unroll
    for (int j = 0; j < 9; j++) acc[j] = 0.f;
    for (int j = b + lane; j < e; j += 32) {
        const float* row = ym9 + (size_t)g_csr[j] * 9;
#pragma unroll
        for (int c = 0; c < 9; c++) acc[c] += row[c];
    }
#pragma unroll
    for (int c = 0; c < 9; c++)
#pragma unroll
        for (int s = 16; s; s >>= 1) acc[c] += __shfl_xor_sync(0xffffffffu, acc[c], s);
    if (lane < 9) {
        float inv = 1.0f / g_cnt[gw];
        out[(size_t)gw * 9 + lane] = acc[lane] * inv + yr9[(size_t)gw * 9 + lane];
    }
}

// ================= launch =================
extern "C" void kernel_launch(void* const* d_in, const int* in_sizes, int n_in,
                              void* d_out, int out_size) {
    const float* z = (const float*)d_in[0];
    const int* ei = (const int*)d_in[1];
    const float* wm1 = (const float*)d_in[2];
    const float* wr1 = (const float*)d_in[3];
    const float* b1 = (const float*)d_in[4];
    const float* g1 = (const float*)d_in[5];
    const float* be1 = (const float*)d_in[6];
    const float* wm2 = (const float*)d_in[7];
    const float* wr2 = (const float*)d_in[8];
    const float* b2 = (const float*)d_in[9];
    const float* g2 = (const float*)d_in[10];
    const float* be2 = (const float*)d_in[11];
    const float* wm3 = (const float*)d_in[12];
    const float* wr3 = (const float*)d_in[13];
    const float* b3 = (const float*)d_in[14];
    const float* g3 = (const float*)d_in[15];
    const float* be3 = (const float*)d_in[16];
    const float* wm4 = (const float*)d_in[17];
    const float* wr4 = (const float*)d_in[18];
    const float* b4 = (const float*)d_in[19];

    int N = in_sizes[0] / 128;
    int E = in_sizes[1] / 2;
    const int* src = ei;
    const int* dst = ei + E;

    __half *hz, *hA, *hB, *hM;
    float *ym9, *yr9;
    uint32_t *w1m, *w1r, *w2m, *w2r, *w3m, *w3r;
    void* p;
    cudaGetSymbolAddress(&p, g_hz);  hz = (__half*)p;
    cudaGetSymbolAddress(&p, g_hA);  hA = (__half*)p;
    cudaGetSymbolAddress(&p, g_hB);  hB = (__half*)p;
    cudaGetSymbolAddress(&p, g_hM);  hM = (__half*)p;
    cudaGetSymbolAddress(&p, g_ym9); ym9 = (float*)p;
    cudaGetSymbolAddress(&p, g_yr9); yr9 = (float*)p;
    cudaGetSymbolAddress(&p, g_w1m); w1m = (uint32_t*)p;
    cudaGetSymbolAddress(&p, g_w1r); w1r = (uint32_t*)p;
    cudaGetSymbolAddress(&p, g_w2m); w2m = (uint32_t*)p;
    cudaGetSymbolAddress(&p, g_w2r); w2r = (uint32_t*)p;
    cudaGetSymbolAddress(&p, g_w3m); w3m = (uint32_t*)p;
    cudaGetSymbolAddress(&p, g_w3r); w3r = (uint32_t*)p;

    // smem words: A 3*128*72/2=13824; B 3*32*(DOUT+8) (x2 arrays for dual)
    const int SM256 = (13824 + 3 * 32 * 264 + 3 * 256 + 1024) * 4;   // 163840 B
    const int SMD128 = (13824 + 6 * 32 * 136 + 128) * 4;             // 160256 B
    cudaFuncSetAttribute(k_gemm_tc<128, 256>, cudaFuncAttributeMaxDynamicSharedMemorySize, SM256);
    cudaFuncSetAttribute(k_gemm_tc<256, 256>, cudaFuncAttributeMaxDynamicSharedMemorySize, SM256);
    cudaFuncSetAttribute(k_gemm_dual<256, 128>, cudaFuncAttributeMaxDynamicSharedMemorySize, SMD128);

    // CSR build (parallel scan)
    int nb = (N + 1023) / 1024;
    k_hist<<<(E + 255) / 256, 256>>>(dst, E);
    k_scan1<<<nb, 1024>>>(N);
    k_scan2<<<1, 128>>>(nb);
    k_scan3<<<(N + 255) / 256, 256>>>(N, E);
    k_scatter<<<(E + 255) / 256, 256>>>(src, dst, E);

    int aggBlocks = (N + 7) / 8;
    int gemmBlocks = (N + 127) / 128;

    // z -> fp16
    k_z2h<<<(N * 64 + 255) / 256, 256>>>(z, hz, N * 64);
    // Layer 1 agg (mean of z, fp16)
    k_aggh<128><<<aggBlocks, 256>>>(hz, hM, N);

    // weight pack (half2 k-pairs)
    k_packh2<<<(64 * 256 + 255) / 256, 256>>>(wm1, w1m, 64, 256);
    k_packh2<<<(64 * 256 + 255) / 256, 256>>>(wr1, w1r, 64, 256);
    k_packh2<<<(128 * 256 + 255) / 256, 256>>>(wm2, w2m, 128, 256);
    k_packh2<<<(128 * 256 + 255) / 256, 256>>>(wr2, w2r, 128, 256);
    k_packh2<<<(128 * 128 + 255) / 256, 256>>>(wm3, w3m, 128, 128);
    k_packh2<<<(128 * 128 + 255) / 256, 256>>>(wr3, w3r, 128, 128);

    // Layer 1: 128 -> 256 (aggregate-first)
    k_gemm_tc<128, 256><<<gemmBlocks, 512, SM256>>>(hM, hz, w1m, w1r, b1, g1, be1, hA, N);
    // Layer 2: 256 -> 256 (aggregate-first)
    k_aggh<256><<<aggBlocks, 256>>>(hA, hM, N);
    k_gemm_tc<256, 256><<<gemmBlocks, 512, SM256>>>(hM, hA, w2m, w2r, b2, g2, be2, hB, N);
    // Layer 3: 256 -> 128 (aggregate-AFTER): ym->hM, yr->hA
    k_gemm_dual<256, 128><<<gemmBlocks, 512, SMD128>>>(hB, w3m, w3r, b3, hM, hA, N);
    k_aggh<128><<<aggBlocks, 256>>>(hM, hB, N);                  // mean(ym) -> hB
    k_addlnrelu<<<aggBlocks, 256>>>(hB, hA, g3, be3, hM, N);     // x3 -> hM
    // Layer 4: 128 -> 9 (aggregate-AFTER)
    k_out_dual<<<aggBlocks, 256>>>(hM, wm4, wr4, b4, ym9, yr9, N);
    k_agg9<<<aggBlocks, 256>>>(ym9, yr9, (float*)d_out, N);
}

// round 12
// speedup vs baseline: 1.4023x; 1.4023x over previous
#include <cuda_runtime.h>
#include <cuda_fp16.h>
#include <cstdint>

// ================= static scratch =================
#define NMAX 100352
#define EMAX 1700000

__device__ int   g_deg[NMAX];     // zeroed at load; re-zeroed by k_agg9 each launch
__device__ int   g_off[NMAX + 1];
__device__ int   g_cur[NMAX];
__device__ int   g_csr[EMAX];
__device__ int   g_bsum[128];
__device__ float g_cnt[NMAX];
__device__ float g_ym9[(size_t)NMAX * 9];
__device__ float g_yr9[(size_t)NMAX * 9];
// fp16 activations / means
__device__ __align__(16) __half g_hz[(size_t)NMAX * 128];
__device__ __align__(16) __half g_hA[(size_t)NMAX * 256];
__device__ __align__(16) __half g_hB[(size_t)NMAX * 256];
__device__ __align__(16) __half g_hM[(size_t)NMAX * 256];
// k-paired half2 weights: Wp[k/2][N], elem = (lo=W[2k][n], hi=W[2k+1][n])
__device__ uint32_t g_w1m[64 * 256];
__device__ uint32_t g_w1r[64 * 256];
__device__ uint32_t g_w2m[128 * 256];
__device__ uint32_t g_w2r[128 * 256];
__device__ uint32_t g_w3m[128 * 128];
__device__ uint32_t g_w3r[128 * 128];

// ================= helpers =================
__device__ __forceinline__ uint32_t f2h2(float lo, float hi) {
    uint32_t r;
    asm("cvt.rn.f16x2.f32 %0, %1, %2;" : "=r"(r) : "f"(hi), "f"(lo));
    return r;
}
__device__ __forceinline__ void mma_f16(float* c, uint32_t a0, uint32_t a1, uint32_t a2, uint32_t a3,
                                        uint32_t b0, uint32_t b1) {
    asm volatile("mma.sync.aligned.m16n8k16.row.col.f32.f16.f16.f32 "
                 "{%0,%1,%2,%3}, {%4,%5,%6,%7}, {%8,%9}, {%0,%1,%2,%3};"
                 : "+f"(c[0]), "+f"(c[1]), "+f"(c[2]), "+f"(c[3])
                 : "r"(a0), "r"(a1), "r"(a2), "r"(a3), "r"(b0), "r"(b1));
}
__device__ __forceinline__ uint32_t su32(const void* p) {
    uint32_t a;
    asm("{ .reg .u64 t; cvta.to.shared.u64 t, %1; cvt.u32.u64 %0, t; }" : "=r"(a) : "l"(p));
    return a;
}
__device__ __forceinline__ void cpa16(uint32_t dst, const void* src, bool pred) {
    int sz = pred ? 16 : 0;
    asm volatile("cp.async.cg.shared.global [%0], [%1], 16, %2;" :: "r"(dst), "l"(src), "r"(sz));
}
#define CP_COMMIT() asm volatile("cp.async.commit_group;" ::: "memory")
#define CP_WAIT1()  asm volatile("cp.async.wait_group 1;" ::: "memory")
#define CP_WAIT0()  asm volatile("cp.async.wait_group 0;" ::: "memory")

// ================= CSR build =================
__global__ void k_hist(const int* __restrict__ dst, int E) {
    int e = blockIdx.x * blockDim.x + threadIdx.x;
    if (e < E) atomicAdd(&g_deg[dst[e]], 1);
}
// 3-kernel parallel scan
__global__ void k_scan1(int n) {
    __shared__ int sh[1024];
    int i = blockIdx.x * 1024 + threadIdx.x;
    int d = (i < n) ? g_deg[i] : 0;
    sh[threadIdx.x] = d;
    __syncthreads();
    for (int o = 1; o < 1024; o <<= 1) {
        int v = (threadIdx.x >= o) ? sh[threadIdx.x - o] : 0;
        __syncthreads();
        sh[threadIdx.x] += v;
        __syncthreads();
    }
    if (i < n) g_off[i] = sh[threadIdx.x] - d;   // exclusive within block
    if (threadIdx.x == 1023) g_bsum[blockIdx.x] = sh[1023];
}
__global__ void k_scan2(int nb) {
    __shared__ int sh[128];
    int d = (threadIdx.x < nb) ? g_bsum[threadIdx.x] : 0;
    sh[threadIdx.x] = d;
    __syncthreads();
    for (int o = 1; o < 128; o <<= 1) {
        int v = (threadIdx.x >= o) ? sh[threadIdx.x - o] : 0;
        __syncthreads();
        sh[threadIdx.x] += v;
        __syncthreads();
    }
    if (threadIdx.x < nb) g_bsum[threadIdx.x] = sh[threadIdx.x] - d;  // exclusive
}
__global__ void k_scan3(int n, int E) {
    int i = blockIdx.x * blockDim.x + threadIdx.x;
    if (i == 0) g_off[n] = E;
    if (i >= n) return;
    int off = g_off[i] + g_bsum[i >> 10];
    g_off[i] = off;
    g_cur[i] = off;
    int d = g_deg[i];
    g_cnt[i] = (d > 0) ? (float)d : 1.0f;
}
__global__ void k_scatter(const int* __restrict__ src, const int* __restrict__ dst, int E) {
    int e = blockIdx.x * blockDim.x + threadIdx.x;
    if (e < E) {
        int p = atomicAdd(&g_cur[dst[e]], 1);
        g_csr[p] = src[e];
    }
}

// ================= conversions / packing =================
__global__ void k_z2h(const float* __restrict__ z, __half* __restrict__ zh, int n2) {
    int i = blockIdx.x * blockDim.x + threadIdx.x;
    if (i >= n2) return;
    float2 v = ((const float2*)z)[i];
    ((__half2*)zh)[i] = __floats2half2_rn(v.x, v.y);
}
__global__ void k_packh2(const float* __restrict__ W, uint32_t* __restrict__ Wp, int KH, int N) {
    int i = blockIdx.x * blockDim.x + threadIdx.x;
    if (i >= KH * N) return;
    int kp = i / N, n = i - kp * N;
    Wp[i] = f2h2(W[(size_t)(2 * kp) * N + n], W[(size_t)(2 * kp + 1) * N + n]);
}

// ================= mean aggregation (half in/out, fp32 acc) =================
template <int D>
__global__ void k_aggh(const __half* __restrict__ x, __half* __restrict__ meanp, int n) {
    int gw = (blockIdx.x * blockDim.x + threadIdx.x) >> 5;
    int lane = threadIdx.x & 31;
    if (gw >= n) return;
    int b = g_off[gw], e = g_off[gw + 1];
    constexpr int NH2 = D / 64;
    float2 acc[NH2], acc2[NH2];
#pragma unroll
    for (int h = 0; h < NH2; h++) {
        acc[h] = make_float2(0.f, 0.f);
        acc2[h] = make_float2(0.f, 0.f);
    }
    auto addrow = [&](const __half* rp, float2* a) {
        uint32_t w[NH2];
        if (NH2 == 4) {
            uint4 u = ((const uint4*)rp)[lane];
            w[0] = u.x; w[1] = u.y; w[2] = u.z; w[3] = u.w;
        } else {
            uint2 u = ((const uint2*)rp)[lane];
            w[0] = u.x; w[1] = u.y;
        }
#pragma unroll
        for (int h = 0; h < NH2; h++) {
            float2 f = __half22float2(*(__half2*)&w[h]);
            a[h].x += f.x;
            a[h].y += f.y;
        }
    };
    int j = b;
    for (; j + 1 < e; j += 2) {
        addrow(x + (size_t)g_csr[j] * D, acc);
        addrow(x + (size_t)g_csr[j + 1] * D, acc2);
    }
    if (j < e) addrow(x + (size_t)g_csr[j] * D, acc);

    float inv = 1.0f / g_cnt[gw];
    uint32_t o[NH2];
#pragma unroll
    for (int h = 0; h < NH2; h++) {
        __half2 hv = __floats2half2_rn((acc[h].x + acc2[h].x) * inv, (acc[h].y + acc2[h].y) * inv);
        o[h] = *(uint32_t*)&hv;
    }
    __half* mo = meanp + (size_t)gw * D;
    if (NH2 == 4) ((uint4*)mo)[lane] = make_uint4(o[0], o[1], o[2], o[3]);
    else ((uint2*)mo)[lane] = make_uint2(o[0], o[1]);
}

// ================= fp16 mma fused dual-GEMM + bias + LN + ReLU (K=32 chunks) =================
template <int DIN, int DOUT>
__launch_bounds__(512)
__global__ void k_gemm_tc(const __half* __restrict__ A0, const __half* __restrict__ A1,
                          const uint32_t* __restrict__ W0p, const uint32_t* __restrict__ W1p,
                          const float* __restrict__ bias, const float* __restrict__ gamma,
                          const float* __restrict__ beta, __half* __restrict__ out, int n) {
    extern __shared__ float sm[];
    constexpr int NCH = DIN / 32;         // 32 k-halves per chunk
    constexpr int TOT = 2 * NCH;
    constexpr int NT = DOUT / 32;
    constexpr int APH = 40;               // A pitch in halves (80 B)
    constexpr int AHSZ = 128 * APH;       // halves per A stage
    constexpr int BPH = DOUT + 8;         // B pitch (half2 words)
    constexpr int BSZ = 16 * BPH;         // words per B stage

    __half* Ah = (__half*)sm;
    __half* Ab[3] = { Ah, Ah + AHSZ, Ah + 2 * AHSZ };
    float* after = sm + (3 * AHSZ) / 2;
    uint32_t* Bb[3] = { (uint32_t*)after, (uint32_t*)after + BSZ, (uint32_t*)after + 2 * BSZ };
    float* sp = after + 3 * BSZ;          // bias|gamma|beta
    float* sln = sp + 3 * DOUT;           // [128][4] float2

    int t = threadIdx.x;
    int wid = t >> 5, lane = t & 31;
    int g = lane >> 2, tq = lane & 3;
    int mw = wid & 3, nq = wid >> 2;
    int nbase = nq * (DOUT / 4);
    int row0 = blockIdx.x * 128;

    for (int i = t; i < DOUT; i += 512) {
        sp[i] = bias[i];
        sp[DOUT + i] = gamma[i];
        sp[2 * DOUT + i] = beta[i];
    }
    __syncthreads();

    float acc[2][NT][4];
#pragma unroll
    for (int ms = 0; ms < 2; ms++)
#pragma unroll
        for (int nt = 0; nt < NT; nt++)
#pragma unroll
            for (int j = 0; j < 4; j++) acc[ms][nt][j] = 0.f;

    auto copy_chunk = [&](int c, int ib) {
        const __half* A = (c < NCH) ? A0 : A1;
        const uint32_t* W = (c < NCH) ? W0p : W1p;
        int cc = (c < NCH) ? c : c - NCH;
        int k0 = cc * 32;
        int kph = cc * 16;
        uint32_t abase = su32(Ab[ib]);
        uint32_t bbase = su32(Bb[ib]);
        {   // A: 128 rows x 64B = 512 cp16, one per thread
            int r = t >> 2, seg = t & 3;
            int gr = row0 + r;
            bool ok = gr < n;
            int cr = ok ? gr : (n - 1);
            cpa16(abase + (uint32_t)(r * 80 + seg * 16),
                  A + (size_t)cr * DIN + k0 + seg * 8, ok);
        }
#pragma unroll
        for (int i = 0; i < DOUT / 128; i++) { // B: 16 rows x DOUT half2
            int s = t + i * 512;
            int kr = s / (DOUT / 4), c4 = s % (DOUT / 4);
            cpa16(bbase + (uint32_t)(kr * BPH + c4 * 4) * 4,
                  W + (size_t)(kph + kr) * DOUT + c4 * 4, true);
        }
    };

    auto mma_chunk = [&](int ib) {
        const __half* As = Ab[ib];
        const uint32_t* Bs = Bb[ib];
#pragma unroll
        for (int ks = 0; ks < 2; ks++) {
            int kb = ks * 16;
            int kpb = ks * 8;
            uint32_t bf0[NT], bf1[NT];
#pragma unroll
            for (int nt = 0; nt < NT; nt++) {
                int nn = nbase + nt * 8 + g;
                bf0[nt] = Bs[(kpb + tq) * BPH + nn];
                bf1[nt] = Bs[(kpb + tq + 4) * BPH + nn];
            }
#pragma unroll
            for (int ms = 0; ms < 2; ms++) {
                int ar = mw * 32 + ms * 16 + g;
                uint32_t a0 = *(const uint32_t*)&As[ar * APH + kb + 2 * tq];
                uint32_t a1 = *(const uint32_t*)&As[(ar + 8) * APH + kb + 2 * tq];
                uint32_t a2 = *(const uint32_t*)&As[ar * APH + kb + 2 * tq + 8];
                uint32_t a3 = *(const uint32_t*)&As[(ar + 8) * APH + kb + 2 * tq + 8];
#pragma unroll
                for (int nt = 0; nt < NT; nt++)
                    mma_f16(acc[ms][nt], a0, a1, a2, a3, bf0[nt], bf1[nt]);
            }
        }
    };

    copy_chunk(0, 0); CP_COMMIT();
    copy_chunk(1, 1); CP_COMMIT();
    for (int c = 0; c < TOT; c++) {
        if (c < TOT - 1) CP_WAIT1(); else CP_WAIT0();
        __syncthreads();
        if (c + 2 < TOT) { copy_chunk(c + 2, (c + 2) % 3); CP_COMMIT(); }
        mma_chunk(c % 3);
    }

    // ---- epilogue: +bias, LN over DOUT (4 n-quarter partials), ReLU, fp16 out ----
#pragma unroll
    for (int ms = 0; ms < 2; ms++) {
        float s0 = 0.f, ss0 = 0.f, s1 = 0.f, ss1 = 0.f;
#pragma unroll
        for (int nt = 0; nt < NT; nt++) {
            int col = nbase + nt * 8 + 2 * tq;
            float b0 = sp[col], b1 = sp[col + 1];
            acc[ms][nt][0] += b0; acc[ms][nt][1] += b1;
            acc[ms][nt][2] += b0; acc[ms][nt][3] += b1;
            s0 += acc[ms][nt][0] + acc[ms][nt][1];
            ss0 += acc[ms][nt][0] * acc[ms][nt][0] + acc[ms][nt][1] * acc[ms][nt][1];
            s1 += acc[ms][nt][2] + acc[ms][nt][3];
            ss1 += acc[ms][nt][2] * acc[ms][nt][2] + acc[ms][nt][3] * acc[ms][nt][3];
        }
#pragma unroll
        for (int o = 1; o <= 2; o <<= 1) {
            s0 += __shfl_xor_sync(0xffffffffu, s0, o);
            ss0 += __shfl_xor_sync(0xffffffffu, ss0, o);
            s1 += __shfl_xor_sync(0xffffffffu, s1, o);
            ss1 += __shfl_xor_sync(0xffffffffu, ss1, o);
        }
        if (tq == 0) {
            int r0 = mw * 32 + ms * 16 + g;
            ((float2*)sln)[r0 * 4 + nq] = make_float2(s0, ss0);
            ((float2*)sln)[(r0 + 8) * 4 + nq] = make_float2(s1, ss1);
        }
    }
    __syncthreads();
#pragma unroll
    for (int ms = 0; ms < 2; ms++) {
        int rl0 = mw * 32 + ms * 16 + g, rl1 = rl0 + 8;
        float s0 = 0.f, ss0 = 0.f, s1 = 0.f, ss1 = 0.f;
#pragma unroll
        for (int q = 0; q < 4; q++) {
            float2 p0 = ((float2*)sln)[rl0 * 4 + q];
            float2 p1 = ((float2*)sln)[rl1 * 4 + q];
            s0 += p0.x; ss0 += p0.y;
            s1 += p1.x; ss1 += p1.y;
        }
        float mu0 = s0 * (1.0f / DOUT);
        float rs0 = rsqrtf(ss0 * (1.0f / DOUT) - mu0 * mu0 + 1e-5f);
        float mu1 = s1 * (1.0f / DOUT);
        float rs1 = rsqrtf(ss1 * (1.0f / DOUT) - mu1 * mu1 + 1e-5f);
        int grow0 = row0 + rl0, grow1 = row0 + rl1;
#pragma unroll
        for (int nt = 0; nt < NT; nt++) {
            int col = nbase + nt * 8 + 2 * tq;
            float ga0 = sp[DOUT + col], ga1 = sp[DOUT + col + 1];
            float bt0 = sp[2 * DOUT + col], bt1 = sp[2 * DOUT + col + 1];
            if (grow0 < n) {
                float vx = fmaxf((acc[ms][nt][0] - mu0) * rs0 * ga0 + bt0, 0.f);
                float vy = fmaxf((acc[ms][nt][1] - mu0) * rs0 * ga1 + bt1, 0.f);
                *(__half2*)(out + (size_t)grow0 * DOUT + col) = __floats2half2_rn(vx, vy);
            }
            if (grow1 < n) {
                float vx = fmaxf((acc[ms][nt][2] - mu1) * rs1 * ga0 + bt0, 0.f);
                float vy = fmaxf((acc[ms][nt][3] - mu1) * rs1 * ga1 + bt1, 0.f);
                *(__half2*)(out + (size_t)grow1 * DOUT + col) = __floats2half2_rn(vx, vy);
            }
        }
    }
}

// ================= dual-output GEMM: YM = X@W0, YR = X@W1 + b (fp16 out, K=32) =================
template <int DIN, int DOUT>
__launch_bounds__(512)
__global__ void k_gemm_dual(const __half* __restrict__ X,
                            const uint32_t* __restrict__ W0p, const uint32_t* __restrict__ W1p,
                            const float* __restrict__ bias,
                            __half* __restrict__ ym, __half* __restrict__ yr, int n) {
    extern __shared__ float sm[];
    constexpr int NCH = DIN / 32;
    constexpr int NT = DOUT / 32;
    constexpr int APH = 40;
    constexpr int AHSZ = 128 * APH;
    constexpr int BPH = DOUT + 8;
    constexpr int BSZ = 16 * BPH;

    __half* Ah = (__half*)sm;
    __half* Ab[3] = { Ah, Ah + AHSZ, Ah + 2 * AHSZ };
    float* after = sm + (3 * AHSZ) / 2;
    uint32_t* B0b[3] = { (uint32_t*)after, (uint32_t*)after + BSZ, (uint32_t*)after + 2 * BSZ };
    uint32_t* B1b[3] = { (uint32_t*)after + 3 * BSZ, (uint32_t*)after + 4 * BSZ, (uint32_t*)after + 5 * BSZ };
    float* sp = after + 6 * BSZ;

    int t = threadIdx.x;
    int wid = t >> 5, lane = t & 31;
    int g = lane >> 2, tq = lane & 3;
    int mw = wid & 3, nq = wid >> 2;
    int nbase = nq * (DOUT / 4);
    int row0 = blockIdx.x * 128;

    for (int i = t; i < DOUT; i += 512) sp[i] = bias[i];
    __syncthreads();

    float accM[2][NT][4], accR[2][NT][4];
#pragma unroll
    for (int ms = 0; ms < 2; ms++)
#pragma unroll
        for (int nt = 0; nt < NT; nt++)
#pragma unroll
            for (int j = 0; j < 4; j++) { accM[ms][nt][j] = 0.f; accR[ms][nt][j] = 0.f; }

    auto copy_chunk = [&](int c, int ib) {
        int k0 = c * 32;
        int kph = c * 16;
        uint32_t abase = su32(Ab[ib]);
        uint32_t b0base = su32(B0b[ib]);
        uint32_t b1base = su32(B1b[ib]);
        {
            int r = t >> 2, seg = t & 3;
            int gr = row0 + r;
            bool ok = gr < n;
            int cr = ok ? gr : (n - 1);
            cpa16(abase + (uint32_t)(r * 80 + seg * 16),
                  X + (size_t)cr * DIN + k0 + seg * 8, ok);
        }
        {
            int kr = t / (DOUT / 4), c4 = t % (DOUT / 4);
            size_t wo = (size_t)(kph + kr) * DOUT + c4 * 4;
            uint32_t so = (uint32_t)(kr * BPH + c4 * 4) * 4;
            cpa16(b0base + so, W0p + wo, true);
            cpa16(b1base + so, W1p + wo, true);
        }
    };

    auto mma_chunk = [&](int ib) {
        const __half* As = Ab[ib];
        const uint32_t* B0s = B0b[ib];
        const uint32_t* B1s = B1b[ib];
#pragma unroll
        for (int ks = 0; ks < 2; ks++) {
            int kb = ks * 16;
            int kpb = ks * 8;
            uint32_t bfM0[NT], bfM1[NT], bfR0[NT], bfR1[NT];
#pragma unroll
            for (int nt = 0; nt < NT; nt++) {
                int nn = nbase + nt * 8 + g;
                bfM0[nt] = B0s[(kpb + tq) * BPH + nn];
                bfM1[nt] = B0s[(kpb + tq + 4) * BPH + nn];
                bfR0[nt] = B1s[(kpb + tq) * BPH + nn];
                bfR1[nt] = B1s[(kpb + tq + 4) * BPH + nn];
            }
#pragma unroll
            for (int ms = 0; ms < 2; ms++) {
                int ar = mw * 32 + ms * 16 + g;
                uint32_t a0 = *(const uint32_t*)&As[ar * APH + kb + 2 * tq];
                uint32_t a1 = *(const uint32_t*)&As[(ar + 8) * APH + kb + 2 * tq];
                uint32_t a2 = *(const uint32_t*)&As[ar * APH + kb + 2 * tq + 8];
                uint32_t a3 = *(const uint32_t*)&As[(ar + 8) * APH + kb + 2 * tq + 8];
#pragma unroll
                for (int nt = 0; nt < NT; nt++) {
                    mma_f16(accM[ms][nt], a0, a1, a2, a3, bfM0[nt], bfM1[nt]);
                    mma_f16(accR[ms][nt], a0, a1, a2, a3, bfR0[nt], bfR1[nt]);
                }
            }
        }
    };

    copy_chunk(0, 0); CP_COMMIT();
    copy_chunk(1, 1); CP_COMMIT();
    for (int c = 0; c < NCH; c++) {
        if (c < NCH - 1) CP_WAIT1(); else CP_WAIT0();
        __syncthreads();
        if (c + 2 < NCH) { copy_chunk(c + 2, (c + 2) % 3); CP_COMMIT(); }
        mma_chunk(c % 3);
    }

#pragma unroll
    for (int ms = 0; ms < 2; ms++) {
        int rl0 = mw * 32 + ms * 16 + g, rl1 = rl0 + 8;
        int grow0 = row0 + rl0, grow1 = row0 + rl1;
#pragma unroll
        for (int nt = 0; nt < NT; nt++) {
            int col = nbase + nt * 8 + 2 * tq;
            float b0 = sp[col], b1 = sp[col + 1];
            if (grow0 < n) {
                *(__half2*)(ym + (size_t)grow0 * DOUT + col) = __floats2half2_rn(accM[ms][nt][0], accM[ms][nt][1]);
                *(__half2*)(yr + (size_t)grow0 * DOUT + col) = __floats2half2_rn(accR[ms][nt][0] + b0, accR[ms][nt][1] + b1);
            }
            if (grow1 < n) {
                *(__half2*)(ym + (size_t)grow1 * DOUT + col) = __floats2half2_rn(accM[ms][nt][2], accM[ms][nt][3]);
                *(__half2*)(yr + (size_t)grow1 * DOUT + col) = __floats2half2_rn(accR[ms][nt][2] + b0, accR[ms][nt][3] + b1);
            }
        }
    }
}

// ===== fused: x3 = ReLU(LN(mean + yr)); ym9 = x3@Wm4; yr9 = x3@Wr4 + b4 =====
// warp per row; LN kept in fp32 registers (no fp16 round-trip).
__global__ void k_lnout(const __half* __restrict__ meanp, const __half* __restrict__ yr,
                        const float* __restrict__ gamma, const float* __restrict__ beta,
                        const float* __restrict__ wm, const float* __restrict__ wr,
                        const float* __restrict__ bias,
                        float* __restrict__ ym9, float* __restrict__ yr9, int n) {
    __shared__ float swm[128 * 9];
    __shared__ float swr[128 * 9];
    __shared__ float sb[9];
    for (int i = threadIdx.x; i < 128 * 9; i += blockDim.x) {
        swm[i] = wm[i];
        swr[i] = wr[i];
    }
    if (threadIdx.x < 9) sb[threadIdx.x] = bias[threadIdx.x];
    __syncthreads();

    int row = (blockIdx.x * blockDim.x + threadIdx.x) >> 5;
    int lane = threadIdx.x & 31;
    if (row >= n) return;

    uint2 mu2 = ((const uint2*)(meanp + (size_t)row * 128))[lane];
    uint2 yu2 = ((const uint2*)(yr + (size_t)row * 128))[lane];
    float2 m0 = __half22float2(*(__half2*)&mu2.x), m1 = __half22float2(*(__half2*)&mu2.y);
    float2 y0 = __half22float2(*(__half2*)&yu2.x), y1 = __half22float2(*(__half2*)&yu2.y);
    float v[4] = { m0.x + y0.x, m0.y + y0.y, m1.x + y1.x, m1.y + y1.y };
    float s = v[0] + v[1] + v[2] + v[3];
    float ss = v[0] * v[0] + v[1] * v[1] + v[2] * v[2] + v[3] * v[3];
#pragma unroll
    for (int o = 16; o; o >>= 1) {
        s += __shfl_xor_sync(0xffffffffu, s, o);
        ss += __shfl_xor_sync(0xffffffffu, ss, o);
    }
    float mu = s * (1.0f / 128.0f);
    float var = ss * (1.0f / 128.0f) - mu * mu;
    float rs = rsqrtf(var + 1e-5f);
    float4 g4 = ((const float4*)gamma)[lane];
    float4 b4 = ((const float4*)beta)[lane];
    float x4[4];
    x4[0] = fmaxf((v[0] - mu) * rs * g4.x + b4.x, 0.f);
    x4[1] = fmaxf((v[1] - mu) * rs * g4.y + b4.y, 0.f);
    x4[2] = fmaxf((v[2] - mu) * rs * g4.z + b4.z, 0.f);
    x4[3] = fmaxf((v[3] - mu) * rs * g4.w + b4.w, 0.f);

    float om[9], orr[9];
#pragma unroll
    for (int j = 0; j < 9; j++) { om[j] = 0.f; orr[j] = 0.f; }
#pragma unroll
    for (int q = 0; q < 4; q++) {
        int k = lane * 4 + q;
#pragma unroll
        for (int j = 0; j < 9; j++) {
            om[j] += x4[q] * swm[k * 9 + j];
            orr[j] += x4[q] * swr[k * 9 + j];
        }
    }
#pragma unroll
    for (int j = 0; j < 9; j++)
#pragma unroll
        for (int o = 16; o; o >>= 1) {
            om[j] += __shfl_xor_sync(0xffffffffu, om[j], o);
            orr[j] += __shfl_xor_sync(0xffffffffu, orr[j], o);
        }
    if (lane < 9) {
        ym9[(size_t)row * 9 + lane] = om[lane];
        yr9[(size_t)row * 9 + lane] = orr[lane] + sb[lane];
    }
}

// ================= final: out = mean(ym9[src]) + yr9; re-zero g_deg =================
__global__ void k_agg9(const float* __restrict__ ym9, const float* __restrict__ yr9,
                       float* __restrict__ out, int n) {
    int gt = blockIdx.x * blockDim.x + threadIdx.x;
    if (gt < NMAX) g_deg[gt] = 0;
    int gw = gt >> 5;
    int lane = threadIdx.x & 31;
    if (gw >= n) return;
    int b = g_off[gw], e = g_off[gw + 1];
    float acc[9];
#pragma unroll
    for (int j = 0; j < 9; j++) acc[j] = 0.f;
    for (int j = b + lane; j < e; j += 32) {
        const float* row = ym9 + (size_t)g_csr[j] * 9;
#pragma unroll
        for (int c = 0; c < 9; c++) acc[c] += row[c];
    }
#pragma unroll
    for (int c = 0; c < 9; c++)
#pragma unroll
        for (int s = 16; s; s >>= 1) acc[c] += __shfl_xor_sync(0xffffffffu, acc[c], s);
    if (lane < 9) {
        float inv = 1.0f / g_cnt[gw];
        out[(size_t)gw * 9 + lane] = acc[lane] * inv + yr9[(size_t)gw * 9 + lane];
    }
}

// ================= launch =================
extern "C" void kernel_launch(void* const* d_in, const int* in_sizes, int n_in,
                              void* d_out, int out_size) {
    const float* z = (const float*)d_in[0];
    const int* ei = (const int*)d_in[1];
    const float* wm1 = (const float*)d_in[2];
    const float* wr1 = (const float*)d_in[3];
    const float* b1 = (const float*)d_in[4];
    const float* g1 = (const float*)d_in[5];
    const float* be1 = (const float*)d_in[6];
    const float* wm2 = (const float*)d_in[7];
    const float* wr2 = (const float*)d_in[8];
    const float* b2 = (const float*)d_in[9];
    const float* g2 = (const float*)d_in[10];
    const float* be2 = (const float*)d_in[11];
    const float* wm3 = (const float*)d_in[12];
    const float* wr3 = (const float*)d_in[13];
    const float* b3 = (const float*)d_in[14];
    const float* g3 = (const float*)d_in[15];
    const float* be3 = (const float*)d_in[16];
    const float* wm4 = (const float*)d_in[17];
    const float* wr4 = (const float*)d_in[18];
    const float* b4 = (const float*)d_in[19];

    int N = in_sizes[0] / 128;
    int E = in_sizes[1] / 2;
    const int* src = ei;
    const int* dst = ei + E;

    __half *hz, *hA, *hB, *hM;
    float *ym9, *yr9;
    uint32_t *w1m, *w1r, *w2m, *w2r, *w3m, *w3r;
    void* p;
    cudaGetSymbolAddress(&p, g_hz);  hz = (__half*)p;
    cudaGetSymbolAddress(&p, g_hA);  hA = (__half*)p;
    cudaGetSymbolAddress(&p, g_hB);  hB = (__half*)p;
    cudaGetSymbolAddress(&p, g_hM);  hM = (__half*)p;
    cudaGetSymbolAddress(&p, g_ym9); ym9 = (float*)p;
    cudaGetSymbolAddress(&p, g_yr9); yr9 = (float*)p;
    cudaGetSymbolAddress(&p, g_w1m); w1m = (uint32_t*)p;
    cudaGetSymbolAddress(&p, g_w1r); w1r = (uint32_t*)p;
    cudaGetSymbolAddress(&p, g_w2m); w2m = (uint32_t*)p;
    cudaGetSymbolAddress(&p, g_w2r); w2r = (uint32_t*)p;
    cudaGetSymbolAddress(&p, g_w3m); w3m = (uint32_t*)p;
    cudaGetSymbolAddress(&p, g_w3r); w3r = (uint32_t*)p;

    // smem words: A 3*128*40/2=7680; B 3*16*(DOUT+8) (x2 arrays for dual)
    const int SM256 = (7680 + 3 * 16 * 264 + 3 * 256 + 1024) * 4;
    const int SMD128 = (7680 + 6 * 16 * 136 + 128) * 4;
    cudaFuncSetAttribute(k_gemm_tc<128, 256>, cudaFuncAttributeMaxDynamicSharedMemorySize, SM256);
    cudaFuncSetAttribute(k_gemm_tc<256, 256>, cudaFuncAttributeMaxDynamicSharedMemorySize, SM256);
    cudaFuncSetAttribute(k_gemm_dual<256, 128>, cudaFuncAttributeMaxDynamicSharedMemorySize, SMD128);

    // CSR build (parallel scan)
    int nb = (N + 1023) / 1024;
    k_hist<<<(E + 255) / 256, 256>>>(dst, E);
    k_scan1<<<nb, 1024>>>(N);
    k_scan2<<<1, 128>>>(nb);
    k_scan3<<<(N + 255) / 256, 256>>>(N, E);
    k_scatter<<<(E + 255) / 256, 256>>>(src, dst, E);

    int aggBlocks = (N + 7) / 8;
    int gemmBlocks = (N + 127) / 128;

    // z -> fp16
    k_z2h<<<(N * 64 + 255) / 256, 256>>>(z, hz, N * 64);
    // Layer 1 agg (mean of z, fp16)
    k_aggh<128><<<aggBlocks, 256>>>(hz, hM, N);

    // weight pack (half2 k-pairs)
    k_packh2<<<(64 * 256 + 255) / 256, 256>>>(wm1, w1m, 64, 256);
    k_packh2<<<(64 * 256 + 255) / 256, 256>>>(wr1, w1r, 64, 256);
    k_packh2<<<(128 * 256 + 255) / 256, 256>>>(wm2, w2m, 128, 256);
    k_packh2<<<(128 * 256 + 255) / 256, 256>>>(wr2, w2r, 128, 256);
    k_packh2<<<(128 * 128 + 255) / 256, 256>>>(wm3, w3m, 128, 128);
    k_packh2<<<(128 * 128 + 255) / 256, 256>>>(wr3, w3r, 128, 128);

    // Layer 1: 128 -> 256 (aggregate-first)
    k_gemm_tc<128, 256><<<gemmBlocks, 512, SM256>>>(hM, hz, w1m, w1r, b1, g1, be1, hA, N);
    // Layer 2: 256 -> 256 (aggregate-first)
    k_aggh<256><<<aggBlocks, 256>>>(hA, hM, N);
    k_gemm_tc<256, 256><<<gemmBlocks, 512, SM256>>>(hM, hA, w2m, w2r, b2, g2, be2, hB, N);
    // Layer 3: 256 -> 128 (aggregate-AFTER): ym->hM, yr->hA
    k_gemm_dual<256, 128><<<gemmBlocks, 512, SMD128>>>(hB, w3m, w3r, b3, hM, hA, N);
    k_aggh<128><<<aggBlocks, 256>>>(hM, hB, N);                  // mean(ym) -> hB
    // Layer 3 LN + Layer 4 projection fused
    k_lnout<<<aggBlocks, 256>>>(hB, hA, g3, be3, wm4, wr4, b4, ym9, yr9, N);
    k_agg9<<<aggBlocks, 256>>>(ym9, yr9, (float*)d_out, N);
}

// round 13
// speedup vs baseline: 1.5073x; 1.0749x over previous
#include <cuda_runtime.h>
#include <cuda_fp16.h>
#include <cstdint>

// ================= static scratch =================
#define NMAX 100352
#define EMAX 1700000

__device__ int   g_deg[NMAX];     // zeroed at load; re-zeroed by k_agg9 each launch
__device__ int   g_off[NMAX + 1];
__device__ int   g_cur[NMAX];
__device__ int   g_csr[EMAX];
__device__ int   g_bsum[128];
__device__ float g_cnt[NMAX];
__device__ float g_ym9[(size_t)NMAX * 9];
__device__ float g_yr9[(size_t)NMAX * 9];
// fp16 activations / means
__device__ __align__(16) __half g_hz[(size_t)NMAX * 128];
__device__ __align__(16) __half g_hA[(size_t)NMAX * 256];
__device__ __align__(16) __half g_hB[(size_t)NMAX * 256];
__device__ __align__(16) __half g_hM[(size_t)NMAX * 256];
// k16-frag packed weights: Wq[(k/16)*4 + tq][n] = uint2{ h2(16g+2tq,+1), h2(16g+2tq+8,+9) }
__device__ uint2 g_w1m[(128 / 4) * 256];
__device__ uint2 g_w1r[(128 / 4) * 256];
__device__ uint2 g_w2m[(256 / 4) * 256];
__device__ uint2 g_w2r[(256 / 4) * 256];
__device__ uint2 g_w3m[(256 / 4) * 128];
__device__ uint2 g_w3r[(256 / 4) * 128];

// ================= helpers =================
__device__ __forceinline__ uint32_t f2h2(float lo, float hi) {
    uint32_t r;
    asm("cvt.rn.f16x2.f32 %0, %1, %2;" : "=r"(r) : "f"(hi), "f"(lo));
    return r;
}
__device__ __forceinline__ void mma_f16(float* c, uint32_t a0, uint32_t a1, uint32_t a2, uint32_t a3,
                                        uint32_t b0, uint32_t b1) {
    asm volatile("mma.sync.aligned.m16n8k16.row.col.f32.f16.f16.f32 "
                 "{%0,%1,%2,%3}, {%4,%5,%6,%7}, {%8,%9}, {%0,%1,%2,%3};"
                 : "+f"(c[0]), "+f"(c[1]), "+f"(c[2]), "+f"(c[3])
                 : "r"(a0), "r"(a1), "r"(a2), "r"(a3), "r"(b0), "r"(b1));
}
__device__ __forceinline__ uint32_t su32(const void* p) {
    uint32_t a;
    asm("{ .reg .u64 t; cvta.to.shared.u64 t, %1; cvt.u32.u64 %0, t; }" : "=r"(a) : "l"(p));
    return a;
}
__device__ __forceinline__ void cpa16(uint32_t dst, const void* src, bool pred) {
    int sz = pred ? 16 : 0;
    asm volatile("cp.async.cg.shared.global [%0], [%1], 16, %2;" :: "r"(dst), "l"(src), "r"(sz));
}
#define CP_COMMIT() asm volatile("cp.async.commit_group;" ::: "memory")
#define CP_WAIT1()  asm volatile("cp.async.wait_group 1;" ::: "memory")
#define CP_WAIT0()  asm volatile("cp.async.wait_group 0;" ::: "memory")

// ================= CSR build =================
__global__ void k_hist(const int* __restrict__ dst, int E) {
    int e = blockIdx.x * blockDim.x + threadIdx.x;
    if (e < E) atomicAdd(&g_deg[dst[e]], 1);
}
__global__ void k_scan1(int n) {
    __shared__ int sh[1024];
    int i = blockIdx.x * 1024 + threadIdx.x;
    int d = (i < n) ? g_deg[i] : 0;
    sh[threadIdx.x] = d;
    __syncthreads();
    for (int o = 1; o < 1024; o <<= 1) {
        int v = (threadIdx.x >= o) ? sh[threadIdx.x - o] : 0;
        __syncthreads();
        sh[threadIdx.x] += v;
        __syncthreads();
    }
    if (i < n) g_off[i] = sh[threadIdx.x] - d;
    if (threadIdx.x == 1023) g_bsum[blockIdx.x] = sh[1023];
}
__global__ void k_scan2(int nb) {
    __shared__ int sh[128];
    int d = (threadIdx.x < nb) ? g_bsum[threadIdx.x] : 0;
    sh[threadIdx.x] = d;
    __syncthreads();
    for (int o = 1; o < 128; o <<= 1) {
        int v = (threadIdx.x >= o) ? sh[threadIdx.x - o] : 0;
        __syncthreads();
        sh[threadIdx.x] += v;
        __syncthreads();
    }
    if (threadIdx.x < nb) g_bsum[threadIdx.x] = sh[threadIdx.x] - d;
}
__global__ void k_scan3(int n, int E) {
    int i = blockIdx.x * blockDim.x + threadIdx.x;
    if (i == 0) g_off[n] = E;
    if (i >= n) return;
    int off = g_off[i] + g_bsum[i >> 10];
    g_off[i] = off;
    g_cur[i] = off;
    int d = g_deg[i];
    g_cnt[i] = (d > 0) ? (float)d : 1.0f;
}
__global__ void k_scatter(const int* __restrict__ src, const int* __restrict__ dst, int E) {
    int e = blockIdx.x * blockDim.x + threadIdx.x;
    if (e < E) {
        int p = atomicAdd(&g_cur[dst[e]], 1);
        g_csr[p] = src[e];
    }
}

// ================= conversions / packing =================
__global__ void k_z2h(const float* __restrict__ z, __half* __restrict__ zh, int n2) {
    int i = blockIdx.x * blockDim.x + threadIdx.x;
    if (i >= n2) return;
    float2 v = ((const float2*)z)[i];
    ((__half2*)zh)[i] = __floats2half2_rn(v.x, v.y);
}
// pack W [DIN][N] fp32 -> Wq [(DIN/16)*4][N] uint2 (k16 mma B fragment pairs)
__global__ void k_packq(const float* __restrict__ W, uint2* __restrict__ Wq, int DIN, int N) {
    int i = blockIdx.x * blockDim.x + threadIdx.x;
    int total = (DIN / 4) * N;
    if (i >= total) return;
    int r = i / N, n = i - r * N;
    int kg = r >> 2, tq = r & 3;
    int k0 = kg * 16 + 2 * tq;
    uint2 v;
    v.x = f2h2(W[(size_t)k0 * N + n], W[(size_t)(k0 + 1) * N + n]);
    v.y = f2h2(W[(size_t)(k0 + 8) * N + n], W[(size_t)(k0 + 9) * N + n]);
    Wq[i] = v;
}

// ================= mean aggregation (half in/out, fp32 acc) =================
template <int D>
__global__ void k_aggh(const __half* __restrict__ x, __half* __restrict__ meanp, int n) {
    int gw = (blockIdx.x * blockDim.x + threadIdx.x) >> 5;
    int lane = threadIdx.x & 31;
    if (gw >= n) return;
    int b = g_off[gw], e = g_off[gw + 1];
    constexpr int NH2 = D / 64;
    float2 acc[NH2], acc2[NH2];
#pragma unroll
    for (int h = 0; h < NH2; h++) {
        acc[h] = make_float2(0.f, 0.f);
        acc2[h] = make_float2(0.f, 0.f);
    }
    auto addrow = [&](const __half* rp, float2* a) {
        uint32_t w[NH2];
        if (NH2 == 4) {
            uint4 u = ((const uint4*)rp)[lane];
            w[0] = u.x; w[1] = u.y; w[2] = u.z; w[3] = u.w;
        } else {
            uint2 u = ((const uint2*)rp)[lane];
            w[0] = u.x; w[1] = u.y;
        }
#pragma unroll
        for (int h = 0; h < NH2; h++) {
            float2 f = __half22float2(*(__half2*)&w[h]);
            a[h].x += f.x;
            a[h].y += f.y;
        }
    };
    int j = b;
    for (; j + 1 < e; j += 2) {
        addrow(x + (size_t)g_csr[j] * D, acc);
        addrow(x + (size_t)g_csr[j + 1] * D, acc2);
    }
    if (j < e) addrow(x + (size_t)g_csr[j] * D, acc);

    float inv = 1.0f / g_cnt[gw];
    uint32_t o[NH2];
#pragma unroll
    for (int h = 0; h < NH2; h++) {
        __half2 hv = __floats2half2_rn((acc[h].x + acc2[h].x) * inv, (acc[h].y + acc2[h].y) * inv);
        o[h] = *(uint32_t*)&hv;
    }
    __half* mo = meanp + (size_t)gw * D;
    if (NH2 == 4) ((uint4*)mo)[lane] = make_uint4(o[0], o[1], o[2], o[3]);
    else ((uint2*)mo)[lane] = make_uint2(o[0], o[1]);
}

// ================= fp16 mma fused dual-GEMM + bias + LN + ReLU (K=32 chunks) =================
// B fragments pre-paired: one LDS.64 yields (b0,b1). Pitch BP2 = DOUT+4 uint2
// (== 4 mod 16 -> per-phase double-banks 4tq+g all distinct, conflict-free).
template <int DIN, int DOUT>
__launch_bounds__(512)
__global__ void k_gemm_tc(const __half* __restrict__ A0, const __half* __restrict__ A1,
                          const uint2* __restrict__ W0q, const uint2* __restrict__ W1q,
                          const float* __restrict__ bias, const float* __restrict__ gamma,
                          const float* __restrict__ beta, __half* __restrict__ out, int n) {
    extern __shared__ float sm[];
    constexpr int NCH = DIN / 32;         // 32 k-halves per chunk
    constexpr int TOT = 2 * NCH;
    constexpr int NT = DOUT / 32;
    constexpr int APH = 40;               // A pitch in halves (80 B)
    constexpr int AHSZ = 128 * APH;
    constexpr int BP2 = DOUT + 4;         // B pitch (uint2)
    constexpr int BSZ2 = 8 * BP2;         // uint2 per B stage (8 frag-rows)

    __half* Ah = (__half*)sm;
    __half* Ab[3] = { Ah, Ah + AHSZ, Ah + 2 * AHSZ };
    float* after = sm + (3 * AHSZ) / 2;
    uint2* Bb[3] = { (uint2*)after, (uint2*)after + BSZ2, (uint2*)after + 2 * BSZ2 };
    float* sp = after + 3 * BSZ2 * 2;     // bias|gamma|beta
    float* sln = sp + 3 * DOUT;           // [128][4] float2

    int t = threadIdx.x;
    int wid = t >> 5, lane = t & 31;
    int g = lane >> 2, tq = lane & 3;
    int mw = wid & 3, nq = wid >> 2;
    int nbase = nq * (DOUT / 4);
    int row0 = blockIdx.x * 128;

    for (int i = t; i < DOUT; i += 512) {
        sp[i] = bias[i];
        sp[DOUT + i] = gamma[i];
        sp[2 * DOUT + i] = beta[i];
    }
    __syncthreads();

    float acc[2][NT][4];
#pragma unroll
    for (int ms = 0; ms < 2; ms++)
#pragma unroll
        for (int nt = 0; nt < NT; nt++)
#pragma unroll
            for (int j = 0; j < 4; j++) acc[ms][nt][j] = 0.f;

    auto copy_chunk = [&](int c, int ib) {
        const __half* A = (c < NCH) ? A0 : A1;
        const uint2* W = (c < NCH) ? W0q : W1q;
        int cc = (c < NCH) ? c : c - NCH;
        int k0 = cc * 32;
        uint32_t abase = su32(Ab[ib]);
        uint32_t bbase = su32(Bb[ib]);
        {   // A: 128 rows x 64B = 512 cp16, one per thread
            int r = t >> 2, seg = t & 3;
            int gr = row0 + r;
            bool ok = gr < n;
            int cr = ok ? gr : (n - 1);
            cpa16(abase + (uint32_t)(r * 80 + seg * 16),
                  A + (size_t)cr * DIN + k0 + seg * 8, ok);
        }
#pragma unroll
        for (int i = 0; i < DOUT / 128; i++) { // B: 8 frag-rows x DOUT uint2 (16B = 2 uint2)
            int s = t + i * 512;
            int kr = s / (DOUT / 2), c2 = (s % (DOUT / 2)) * 2;
            cpa16(bbase + (uint32_t)(kr * BP2 + c2) * 8,
                  W + (size_t)(cc * 8 + kr) * DOUT + c2, true);
        }
    };

    auto mma_chunk = [&](int ib) {
        const __half* As = Ab[ib];
        const uint2* Bs = Bb[ib];
#pragma unroll
        for (int ks = 0; ks < 2; ks++) {
            int kb = ks * 16;
            uint2 bf[NT];
#pragma unroll
            for (int nt = 0; nt < NT; nt++)
                bf[nt] = Bs[(ks * 4 + tq) * BP2 + nbase + nt * 8 + g];
#pragma unroll
            for (int ms = 0; ms < 2; ms++) {
                int ar = mw * 32 + ms * 16 + g;
                uint32_t a0 = *(const uint32_t*)&As[ar * APH + kb + 2 * tq];
                uint32_t a1 = *(const uint32_t*)&As[(ar + 8) * APH + kb + 2 * tq];
                uint32_t a2 = *(const uint32_t*)&As[ar * APH + kb + 2 * tq + 8];
                uint32_t a3 = *(const uint32_t*)&As[(ar + 8) * APH + kb + 2 * tq + 8];
#pragma unroll
                for (int nt = 0; nt < NT; nt++)
                    mma_f16(acc[ms][nt], a0, a1, a2, a3, bf[nt].x, bf[nt].y);
            }
        }
    };

    copy_chunk(0, 0); CP_COMMIT();
    copy_chunk(1, 1); CP_COMMIT();
    for (int c = 0; c < TOT; c++) {
        if (c < TOT - 1) CP_WAIT1(); else CP_WAIT0();
        __syncthreads();
        if (c + 2 < TOT) { copy_chunk(c + 2, (c + 2) % 3); CP_COMMIT(); }
        mma_chunk(c % 3);
    }

    // ---- epilogue: +bias, LN over DOUT (4 n-quarter partials), ReLU, fp16 out ----
#pragma unroll
    for (int ms = 0; ms < 2; ms++) {
        float s0 = 0.f, ss0 = 0.f, s1 = 0.f, ss1 = 0.f;
#pragma unroll
        for (int nt = 0; nt < NT; nt++) {
            int col = nbase + nt * 8 + 2 * tq;
            float b0 = sp[col], b1 = sp[col + 1];
            acc[ms][nt][0] += b0; acc[ms][nt][1] += b1;
            acc[ms][nt][2] += b0; acc[ms][nt][3] += b1;
            s0 += acc[ms][nt][0] + acc[ms][nt][1];
            ss0 += acc[ms][nt][0] * acc[ms][nt][0] + acc[ms][nt][1] * acc[ms][nt][1];
            s1 += acc[ms][nt][2] + acc[ms][nt][3];
            ss1 += acc[ms][nt][2] * acc[ms][nt][2] + acc[ms][nt][3] * acc[ms][nt][3];
        }
#pragma unroll
        for (int o = 1; o <= 2; o <<= 1) {
            s0 += __shfl_xor_sync(0xffffffffu, s0, o);
            ss0 += __shfl_xor_sync(0xffffffffu, ss0, o);
            s1 += __shfl_xor_sync(0xffffffffu, s1, o);
            ss1 += __shfl_xor_sync(0xffffffffu, ss1, o);
        }
        if (tq == 0) {
            int r0 = mw * 32 + ms * 16 + g;
            ((float2*)sln)[r0 * 4 + nq] = make_float2(s0, ss0);
            ((float2*)sln)[(r0 + 8) * 4 + nq] = make_float2(s1, ss1);
        }
    }
    __syncthreads();
#pragma unroll
    for (int ms = 0; ms < 2; ms++) {
        int rl0 = mw * 32 + ms * 16 + g, rl1 = rl0 + 8;
        float s0 = 0.f, ss0 = 0.f, s1 = 0.f, ss1 = 0.f;
#pragma unroll
        for (int q = 0; q < 4; q++) {
            float2 p0 = ((float2*)sln)[rl0 * 4 + q];
            float2 p1 = ((float2*)sln)[rl1 * 4 + q];
            s0 += p0.x; ss0 += p0.y;
            s1 += p1.x; ss1 += p1.y;
        }
        float mu0 = s0 * (1.0f / DOUT);
        float rs0 = rsqrtf(ss0 * (1.0f / DOUT) - mu0 * mu0 + 1e-5f);
        float mu1 = s1 * (1.0f / DOUT);
        float rs1 = rsqrtf(ss1 * (1.0f / DOUT) - mu1 * mu1 + 1e-5f);
        int grow0 = row0 + rl0, grow1 = row0 + rl1;
#pragma unroll
        for (int nt = 0; nt < NT; nt++) {
            int col = nbase + nt * 8 + 2 * tq;
            float ga0 = sp[DOUT + col], ga1 = sp[DOUT + col + 1];
            float bt0 = sp[2 * DOUT + col], bt1 = sp[2 * DOUT + col + 1];
            if (grow0 < n) {
                float vx = fmaxf((acc[ms][nt][0] - mu0) * rs0 * ga0 + bt0, 0.f);
                float vy = fmaxf((acc[ms][nt][1] - mu0) * rs0 * ga1 + bt1, 0.f);
                *(__half2*)(out + (size_t)grow0 * DOUT + col) = __floats2half2_rn(vx, vy);
            }
            if (grow1 < n) {
                float vx = fmaxf((acc[ms][nt][2] - mu1) * rs1 * ga0 + bt0, 0.f);
                float vy = fmaxf((acc[ms][nt][3] - mu1) * rs1 * ga1 + bt1, 0.f);
                *(__half2*)(out + (size_t)grow1 * DOUT + col) = __floats2half2_rn(vx, vy);
            }
        }
    }
}

// ================= dual-output GEMM: YM = X@W0, YR = X@W1 + b (fp16 out) =================
template <int DIN, int DOUT>
__launch_bounds__(512)
__global__ void k_gemm_dual(const __half* __restrict__ X,
                            const uint2* __restrict__ W0q, const uint2* __restrict__ W1q,
                            const float* __restrict__ bias,
                            __half* __restrict__ ym, __half* __restrict__ yr, int n) {
    extern __shared__ float sm[];
    constexpr int NCH = DIN / 32;
    constexpr int NT = DOUT / 32;
    constexpr int APH = 40;
    constexpr int AHSZ = 128 * APH;
    constexpr int BP2 = DOUT + 4;
    constexpr int BSZ2 = 8 * BP2;

    __half* Ah = (__half*)sm;
    __half* Ab[3] = { Ah, Ah + AHSZ, Ah + 2 * AHSZ };
    float* after = sm + (3 * AHSZ) / 2;
    uint2* B0b[3] = { (uint2*)after, (uint2*)after + BSZ2, (uint2*)after + 2 * BSZ2 };
    uint2* B1b[3] = { (uint2*)after + 3 * BSZ2, (uint2*)after + 4 * BSZ2, (uint2*)after + 5 * BSZ2 };
    float* sp = after + 6 * BSZ2 * 2;

    int t = threadIdx.x;
    int wid = t >> 5, lane = t & 31;
    int g = lane >> 2, tq = lane & 3;
    int mw = wid & 3, nq = wid >> 2;
    int nbase = nq * (DOUT / 4);
    int row0 = blockIdx.x * 128;

    for (int i = t; i < DOUT; i += 512) sp[i] = bias[i];
    __syncthreads();

    float accM[2][NT][4], accR[2][NT][4];
#pragma unroll
    for (int ms = 0; ms < 2; ms++)
#pragma unroll
        for (int nt = 0; nt < NT; nt++)
#pragma unroll
            for (int j = 0; j < 4; j++) { accM[ms][nt][j] = 0.f; accR[ms][nt][j] = 0.f; }

    auto copy_chunk = [&](int c, int ib) {
        int k0 = c * 32;
        uint32_t abase = su32(Ab[ib]);
        uint32_t b0base = su32(B0b[ib]);
        uint32_t b1base = su32(B1b[ib]);
        {
            int r = t >> 2, seg = t & 3;
            int gr = row0 + r;
            bool ok = gr < n;
            int cr = ok ? gr : (n - 1);
            cpa16(abase + (uint32_t)(r * 80 + seg * 16),
                  X + (size_t)cr * DIN + k0 + seg * 8, ok);
        }
        {   // B: 8 frag-rows x DOUT(=128) uint2 = 512 x 16B per array
            int kr = t / (DOUT / 2), c2 = (t % (DOUT / 2)) * 2;
            size_t wo = (size_t)(c * 8 + kr) * DOUT + c2;
            uint32_t so = (uint32_t)(kr * BP2 + c2) * 8;
            cpa16(b0base + so, W0q + wo, true);
            cpa16(b1base + so, W1q + wo, true);
        }
    };

    auto mma_chunk = [&](int ib) {
        const __half* As = Ab[ib];
        const uint2* B0s = B0b[ib];
        const uint2* B1s = B1b[ib];
#pragma unroll
        for (int ks = 0; ks < 2; ks++) {
            int kb = ks * 16;
            uint2 bfM[NT], bfR[NT];
#pragma unroll
            for (int nt = 0; nt < NT; nt++) {
                int bi = (ks * 4 + tq) * BP2 + nbase + nt * 8 + g;
                bfM[nt] = B0s[bi];
                bfR[nt] = B1s[bi];
            }
#pragma unroll
            for (int ms = 0; ms < 2; ms++) {
                int ar = mw * 32 + ms * 16 + g;
                uint32_t a0 = *(const uint32_t*)&As[ar * APH + kb + 2 * tq];
                uint32_t a1 = *(const uint32_t*)&As[(ar + 8) * APH + kb + 2 * tq];
                uint32_t a2 = *(const uint32_t*)&As[ar * APH + kb + 2 * tq + 8];
                uint32_t a3 = *(const uint32_t*)&As[(ar + 8) * APH + kb + 2 * tq + 8];
#pragma unroll
                for (int nt = 0; nt < NT; nt++) {
                    mma_f16(accM[ms][nt], a0, a1, a2, a3, bfM[nt].x, bfM[nt].y);
                    mma_f16(accR[ms][nt], a0, a1, a2, a3, bfR[nt].x, bfR[nt].y);
                }
            }
        }
    };

    copy_chunk(0, 0); CP_COMMIT();
    copy_chunk(1, 1); CP_COMMIT();
    for (int c = 0; c < NCH; c++) {
        if (c < NCH - 1) CP_WAIT1(); else CP_WAIT0();
        __syncthreads();
        if (c + 2 < NCH) { copy_chunk(c + 2, (c + 2) % 3); CP_COMMIT(); }
        mma_chunk(c % 3);
    }

#pragma unroll
    for (int ms = 0; ms < 2; ms++) {
        int rl0 = mw * 32 + ms * 16 + g, rl1 = rl0 + 8;
        int grow0 = row0 + rl0, grow1 = row0 + rl1;
#pragma unroll
        for (int nt = 0; nt < NT; nt++) {
            int col = nbase + nt * 8 + 2 * tq;
            float b0 = sp[col], b1 = sp[col + 1];
            if (grow0 < n) {
                *(__half2*)(ym + (size_t)grow0 * DOUT + col) = __floats2half2_rn(accM[ms][nt][0], accM[ms][nt][1]);
                *(__half2*)(yr + (size_t)grow0 * DOUT + col) = __floats2half2_rn(accR[ms][nt][0] + b0, accR[ms][nt][1] + b1);
            }
            if (grow1 < n) {
                *(__half2*)(ym + (size_t)grow1 * DOUT + col) = __floats2half2_rn(accM[ms][nt][2], accM[ms][nt][3]);
                *(__half2*)(yr + (size_t)grow1 * DOUT + col) = __floats2half2_rn(accR[ms][nt][2] + b0, accR[ms][nt][3] + b1);
            }
        }
    }
}

// ===== fused: x3 = ReLU(LN(mean + yr)); ym9 = x3@Wm4; yr9 = x3@Wr4 + b4 =====
__global__ void k_lnout(const __half* __restrict__ meanp, const __half* __restrict__ yr,
                        const float* __restrict__ gamma, const float* __restrict__ beta,
                        const float* __restrict__ wm, const float* __restrict__ wr,
                        const float* __restrict__ bias,
                        float* __restrict__ ym9, float* __restrict__ yr9, int n) {
    __shared__ float swm[128 * 9];
    __shared__ float swr[128 * 9];
    __shared__ float sb[9];
    for (int i = threadIdx.x; i < 128 * 9; i += blockDim.x) {
        swm[i] = wm[i];
        swr[i] = wr[i];
    }
    if (threadIdx.x < 9) sb[threadIdx.x] = bias[threadIdx.x];
    __syncthreads();

    int row = (blockIdx.x * blockDim.x + threadIdx.x) >> 5;
    int lane = threadIdx.x & 31;
    if (row >= n) return;

    uint2 mu2 = ((const uint2*)(meanp + (size_t)row * 128))[lane];
    uint2 yu2 = ((const uint2*)(yr + (size_t)row * 128))[lane];
    float2 m0 = __half22float2(*(__half2*)&mu2.x), m1 = __half22float2(*(__half2*)&mu2.y);
    float2 y0 = __half22float2(*(__half2*)&yu2.x), y1 = __half22float2(*(__half2*)&yu2.y);
    float v[4] = { m0.x + y0.x, m0.y + y0.y, m1.x + y1.x, m1.y + y1.y };
    float s = v[0] + v[1] + v[2] + v[3];
    float ss = v[0] * v[0] + v[1] * v[1] + v[2] * v[2] + v[3] * v[3];
#pragma unroll
    for (int o = 16; o; o >>= 1) {
        s += __shfl_xor_sync(0xffffffffu, s, o);
        ss += __shfl_xor_sync(0xffffffffu, ss, o);
    }
    float mu = s * (1.0f / 128.0f);
    float var = ss * (1.0f / 128.0f) - mu * mu;
    float rs = rsqrtf(var + 1e-5f);
    float4 g4 = ((const float4*)gamma)[lane];
    float4 b4 = ((const float4*)beta)[lane];
    float x4[4];
    x4[0] = fmaxf((v[0] - mu) * rs * g4.x + b4.x, 0.f);
    x4[1] = fmaxf((v[1] - mu) * rs * g4.y + b4.y, 0.f);
    x4[2] = fmaxf((v[2] - mu) * rs * g4.z + b4.z, 0.f);
    x4[3] = fmaxf((v[3] - mu) * rs * g4.w + b4.w, 0.f);

    float om[9], orr[9];
#pragma unroll
    for (int j = 0; j < 9; j++) { om[j] = 0.f; orr[j] = 0.f; }
#pragma unroll
    for (int q = 0; q < 4; q++) {
        int k = lane * 4 + q;
#pragma unroll
        for (int j = 0; j < 9; j++) {
            om[j] += x4[q] * swm[k * 9 + j];
            orr[j] += x4[q] * swr[k * 9 + j];
        }
    }
#pragma unroll
    for (int j = 0; j < 9; j++)
#pragma unroll
        for (int o = 16; o; o >>= 1) {
            om[j] += __shfl_xor_sync(0xffffffffu, om[j], o);
            orr[j] += __shfl_xor_sync(0xffffffffu, orr[j], o);
        }
    if (lane < 9) {
        ym9[(size_t)row * 9 + lane] = om[lane];
        yr9[(size_t)row * 9 + lane] = orr[lane] + sb[lane];
    }
}

// ================= final: out = mean(ym9[src]) + yr9; re-zero g_deg =================
__global__ void k_agg9(const float* __restrict__ ym9, const float* __restrict__ yr9,
                       float* __restrict__ out, int n) {
    int gt = blockIdx.x * blockDim.x + threadIdx.x;
    if (gt < NMAX) g_deg[gt] = 0;
    int gw = gt >> 5;
    int lane = threadIdx.x & 31;
    if (gw >= n) return;
    int b = g_off[gw], e = g_off[gw + 1];
    float acc[9];
#pragma unroll
    for (int j = 0; j < 9; j++) acc[j] = 0.f;
    for (int j = b + lane; j < e; j += 32) {
        const float* row = ym9 + (size_t)g_csr[j] * 9;
#pragma unroll
        for (int c = 0; c < 9; c++) acc[c] += row[c];
    }
#pragma unroll
    for (int c = 0; c < 9; c++)
#pragma unroll
        for (int s = 16; s; s >>= 1) acc[c] += __shfl_xor_sync(0xffffffffu, acc[c], s);
    if (lane < 9) {
        float inv = 1.0f / g_cnt[gw];
        out[(size_t)gw * 9 + lane] = acc[lane] * inv + yr9[(size_t)gw * 9 + lane];
    }
}

// ================= launch =================
extern "C" void kernel_launch(void* const* d_in, const int* in_sizes, int n_in,
                              void* d_out, int out_size) {
    const float* z = (const float*)d_in[0];
    const int* ei = (const int*)d_in[1];
    const float* wm1 = (const float*)d_in[2];
    const float* wr1 = (const float*)d_in[3];
    const float* b1 = (const float*)d_in[4];
    const float* g1 = (const float*)d_in[5];
    const float* be1 = (const float*)d_in[6];
    const float* wm2 = (const float*)d_in[7];
    const float* wr2 = (const float*)d_in[8];
    const float* b2 = (const float*)d_in[9];
    const float* g2 = (const float*)d_in[10];
    const float* be2 = (const float*)d_in[11];
    const float* wm3 = (const float*)d_in[12];
    const float* wr3 = (const float*)d_in[13];
    const float* b3 = (const float*)d_in[14];
    const float* g3 = (const float*)d_in[15];
    const float* be3 = (const float*)d_in[16];
    const float* wm4 = (const float*)d_in[17];
    const float* wr4 = (const float*)d_in[18];
    const float* b4 = (const float*)d_in[19];

    int N = in_sizes[0] / 128;
    int E = in_sizes[1] / 2;
    const int* src = ei;
    const int* dst = ei + E;

    __half *hz, *hA, *hB, *hM;
    float *ym9, *yr9;
    uint2 *w1m, *w1r, *w2m, *w2r, *w3m, *w3r;
    void* p;
    cudaGetSymbolAddress(&p, g_hz);  hz = (__half*)p;
    cudaGetSymbolAddress(&p, g_hA);  hA = (__half*)p;
    cudaGetSymbolAddress(&p, g_hB);  hB = (__half*)p;
    cudaGetSymbolAddress(&p, g_hM);  hM = (__half*)p;
    cudaGetSymbolAddress(&p, g_ym9); ym9 = (float*)p;
    cudaGetSymbolAddress(&p, g_yr9); yr9 = (float*)p;
    cudaGetSymbolAddress(&p, g_w1m); w1m = (uint2*)p;
    cudaGetSymbolAddress(&p, g_w1r); w1r = (uint2*)p;
    cudaGetSymbolAddress(&p, g_w2m); w2m = (uint2*)p;
    cudaGetSymbolAddress(&p, g_w2r); w2r = (uint2*)p;
    cudaGetSymbolAddress(&p, g_w3m); w3m = (uint2*)p;
    cudaGetSymbolAddress(&p, g_w3r); w3r = (uint2*)p;

    // smem words: A 7680; B 3(or 6) stages x 8*(DOUT+4)*2 words
    const int SM256 = (7680 + 48 * (256 + 4) + 3 * 256 + 1024) * 4;
    const int SMD128 = (7680 + 96 * (128 + 4) + 128) * 4;
    cudaFuncSetAttribute(k_gemm_tc<128, 256>, cudaFuncAttributeMaxDynamicSharedMemorySize, SM256);
    cudaFuncSetAttribute(k_gemm_tc<256, 256>, cudaFuncAttributeMaxDynamicSharedMemorySize, SM256);
    cudaFuncSetAttribute(k_gemm_dual<256, 128>, cudaFuncAttributeMaxDynamicSharedMemorySize, SMD128);

    // CSR build (parallel scan)
    int nb = (N + 1023) / 1024;
    k_hist<<<(E + 255) / 256, 256>>>(dst, E);
    k_scan1<<<nb, 1024>>>(N);
    k_scan2<<<1, 128>>>(nb);
    k_scan3<<<(N + 255) / 256, 256>>>(N, E);
    k_scatter<<<(E + 255) / 256, 256>>>(src, dst, E);

    int aggBlocks = (N + 7) / 8;
    int gemmBlocks = (N + 127) / 128;

    // z -> fp16
    k_z2h<<<(N * 64 + 255) / 256, 256>>>(z, hz, N * 64);
    // Layer 1 agg (mean of z, fp16)
    k_aggh<128><<<aggBlocks, 256>>>(hz, hM, N);

    // weight pack (k16 fragment uint2)
    k_packq<<<(32 * 256 + 255) / 256, 256>>>(wm1, w1m, 128, 256);
    k_packq<<<(32 * 256 + 255) / 256, 256>>>(wr1, w1r, 128, 256);
    k_packq<<<(64 * 256 + 255) / 256, 256>>>(wm2, w2m, 256, 256);
    k_packq<<<(64 * 256 + 255) / 256, 256>>>(wr2, w2r, 256, 256);
    k_packq<<<(64 * 128 + 255) / 256, 256>>>(wm3, w3m, 256, 128);
    k_packq<<<(64 * 128 + 255) / 256, 256>>>(wr3, w3r, 256, 128);

    // Layer 1: 128 -> 256 (aggregate-first)
    k_gemm_tc<128, 256><<<gemmBlocks, 512, SM256>>>(hM, hz, w1m, w1r, b1, g1, be1, hA, N);
    // Layer 2: 256 -> 256 (aggregate-first)
    k_aggh<256><<<aggBlocks, 256>>>(hA, hM, N);
    k_gemm_tc<256, 256><<<gemmBlocks, 512, SM256>>>(hM, hA, w2m, w2r, b2, g2, be2, hB, N);
    // Layer 3: 256 -> 128 (aggregate-AFTER): ym->hM, yr->hA
    k_gemm_dual<256, 128><<<gemmBlocks, 512, SMD128>>>(hB, w3m, w3r, b3, hM, hA, N);
    k_aggh<128><<<aggBlocks, 256>>>(hM, hB, N);                  // mean(ym) -> hB
    // Layer 3 LN + Layer 4 projection fused
    k_lnout<<<aggBlocks, 256>>>(hB, hA, g3, be3, wm4, wr4, b4, ym9, yr9, N);
    k_agg9<<<aggBlocks, 256>>>(ym9, yr9, (float*)d_out, N);
}

// round 14
// speedup vs baseline: 1.5730x; 1.0436x over previous
#include <cuda_runtime.h>
#include <cuda_fp16.h>
#include <cstdint>

// ================= static scratch =================
#define NMAX 100352
#define EMAX 1700000

__device__ int   g_deg[NMAX];     // zeroed at load; re-zeroed by k_agg9 each launch
__device__ int   g_off[NMAX + 1];
__device__ int   g_cur[NMAX];
__device__ int   g_csr[EMAX];
__device__ int   g_bsum[128];
__device__ float g_cnt[NMAX];
__device__ float g_ym9[(size_t)NMAX * 9];
__device__ float g_yr9[(size_t)NMAX * 9];
// fp16 activations / means
__device__ __align__(16) __half g_hz[(size_t)NMAX * 128];
__device__ __align__(16) __half g_hA[(size_t)NMAX * 256];
__device__ __align__(16) __half g_hB[(size_t)NMAX * 256];
__device__ __align__(16) __half g_hM[(size_t)NMAX * 256];
// k16-frag packed weights: Wq[(k/16)*4 + tq][n] = uint2{ h2(16g+2tq,+1), h2(16g+2tq+8,+9) }
__device__ uint2 g_w1m[(128 / 4) * 256];
__device__ uint2 g_w1r[(128 / 4) * 256];
__device__ uint2 g_w2m[(256 / 4) * 256];
__device__ uint2 g_w2r[(256 / 4) * 256];
__device__ uint2 g_w3m[(256 / 4) * 128];
__device__ uint2 g_w3r[(256 / 4) * 128];

// ================= helpers =================
__device__ __forceinline__ uint32_t f2h2(float lo, float hi) {
    uint32_t r;
    asm("cvt.rn.f16x2.f32 %0, %1, %2;" : "=r"(r) : "f"(hi), "f"(lo));
    return r;
}
__device__ __forceinline__ void mma_f16(float* c, uint32_t a0, uint32_t a1, uint32_t a2, uint32_t a3,
                                        uint32_t b0, uint32_t b1) {
    asm volatile("mma.sync.aligned.m16n8k16.row.col.f32.f16.f16.f32 "
                 "{%0,%1,%2,%3}, {%4,%5,%6,%7}, {%8,%9}, {%0,%1,%2,%3};"
                 : "+f"(c[0]), "+f"(c[1]), "+f"(c[2]), "+f"(c[3])
                 : "r"(a0), "r"(a1), "r"(a2), "r"(a3), "r"(b0), "r"(b1));
}
__device__ __forceinline__ void ldsm_x4(uint32_t& r0, uint32_t& r1, uint32_t& r2, uint32_t& r3,
                                        uint32_t addr) {
    asm volatile("ldmatrix.sync.aligned.m8n8.x4.shared.b16 {%0,%1,%2,%3}, [%4];"
                 : "=r"(r0), "=r"(r1), "=r"(r2), "=r"(r3) : "r"(addr));
}
__device__ __forceinline__ uint32_t su32(const void* p) {
    uint32_t a;
    asm("{ .reg .u64 t; cvta.to.shared.u64 t, %1; cvt.u32.u64 %0, t; }" : "=r"(a) : "l"(p));
    return a;
}
__device__ __forceinline__ void cpa16(uint32_t dst, const void* src, bool pred) {
    int sz = pred ? 16 : 0;
    asm volatile("cp.async.cg.shared.global [%0], [%1], 16, %2;" :: "r"(dst), "l"(src), "r"(sz));
}
#define CP_COMMIT() asm volatile("cp.async.commit_group;" ::: "memory")
#define CP_WAIT1()  asm volatile("cp.async.wait_group 1;" ::: "memory")
#define CP_WAIT0()  asm volatile("cp.async.wait_group 0;" ::: "memory")

// ================= CSR build =================
__global__ void k_hist(const int* __restrict__ dst, int E) {
    int e = blockIdx.x * blockDim.x + threadIdx.x;
    if (e < E) atomicAdd(&g_deg[dst[e]], 1);
}
__global__ void k_scan1(int n) {
    __shared__ int sh[1024];
    int i = blockIdx.x * 1024 + threadIdx.x;
    int d = (i < n) ? g_deg[i] : 0;
    sh[threadIdx.x] = d;
    __syncthreads();
    for (int o = 1; o < 1024; o <<= 1) {
        int v = (threadIdx.x >= o) ? sh[threadIdx.x - o] : 0;
        __syncthreads();
        sh[threadIdx.x] += v;
        __syncthreads();
    }
    if (i < n) g_off[i] = sh[threadIdx.x] - d;
    if (threadIdx.x == 1023) g_bsum[blockIdx.x] = sh[1023];
}
__global__ void k_scan2(int nb) {
    __shared__ int sh[128];
    int d = (threadIdx.x < nb) ? g_bsum[threadIdx.x] : 0;
    sh[threadIdx.x] = d;
    __syncthreads();
    for (int o = 1; o < 128; o <<= 1) {
        int v = (threadIdx.x >= o) ? sh[threadIdx.x - o] : 0;
        __syncthreads();
        sh[threadIdx.x] += v;
        __syncthreads();
    }
    if (threadIdx.x < nb) g_bsum[threadIdx.x] = sh[threadIdx.x] - d;
}
__global__ void k_scan3(int n, int E) {
    int i = blockIdx.x * blockDim.x + threadIdx.x;
    if (i == 0) g_off[n] = E;
    if (i >= n) return;
    int off = g_off[i] + g_bsum[i >> 10];
    g_off[i] = off;
    g_cur[i] = off;
    int d = g_deg[i];
    g_cnt[i] = (d > 0) ? (float)d : 1.0f;
}
__global__ void k_scatter(const int* __restrict__ src, const int* __restrict__ dst, int E) {
    int e = blockIdx.x * blockDim.x + threadIdx.x;
    if (e < E) {
        int p = atomicAdd(&g_cur[dst[e]], 1);
        g_csr[p] = src[e];
    }
}

// ================= conversions / packing =================
__global__ void k_z2h(const float* __restrict__ z, __half* __restrict__ zh, int n2) {
    int i = blockIdx.x * blockDim.x + threadIdx.x;
    if (i >= n2) return;
    float2 v = ((const float2*)z)[i];
    ((__half2*)zh)[i] = __floats2half2_rn(v.x, v.y);
}
// pack W [DIN][N] fp32 -> Wq [(DIN/16)*4][N] uint2 (k16 mma B fragment pairs)
__global__ void k_packq(const float* __restrict__ W, uint2* __restrict__ Wq, int DIN, int N) {
    int i = blockIdx.x * blockDim.x + threadIdx.x;
    int total = (DIN / 4) * N;
    if (i >= total) return;
    int r = i / N, n = i - r * N;
    int kg = r >> 2, tq = r & 3;
    int k0 = kg * 16 + 2 * tq;
    uint2 v;
    v.x = f2h2(W[(size_t)k0 * N + n], W[(size_t)(k0 + 1) * N + n]);
    v.y = f2h2(W[(size_t)(k0 + 8) * N + n], W[(size_t)(k0 + 9) * N + n]);
    Wq[i] = v;
}

// ================= mean aggregation (half in/out, fp32 acc) =================
template <int D>
__global__ void k_aggh(const __half* __restrict__ x, __half* __restrict__ meanp, int n) {
    int gw = (blockIdx.x * blockDim.x + threadIdx.x) >> 5;
    int lane = threadIdx.x & 31;
    if (gw >= n) return;
    int b = g_off[gw], e = g_off[gw + 1];
    constexpr int NH2 = D / 64;
    float2 acc[NH2], acc2[NH2];
#pragma unroll
    for (int h = 0; h < NH2; h++) {
        acc[h] = make_float2(0.f, 0.f);
        acc2[h] = make_float2(0.f, 0.f);
    }
    auto addrow = [&](const __half* rp, float2* a) {
        uint32_t w[NH2];
        if (NH2 == 4) {
            uint4 u = ((const uint4*)rp)[lane];
            w[0] = u.x; w[1] = u.y; w[2] = u.z; w[3] = u.w;
        } else {
            uint2 u = ((const uint2*)rp)[lane];
            w[0] = u.x; w[1] = u.y;
        }
#pragma unroll
        for (int h = 0; h < NH2; h++) {
            float2 f = __half22float2(*(__half2*)&w[h]);
            a[h].x += f.x;
            a[h].y += f.y;
        }
    };
    int j = b;
    for (; j + 1 < e; j += 2) {
        addrow(x + (size_t)g_csr[j] * D, acc);
        addrow(x + (size_t)g_csr[j + 1] * D, acc2);
    }
    if (j < e) addrow(x + (size_t)g_csr[j] * D, acc);

    float inv = 1.0f / g_cnt[gw];
    uint32_t o[NH2];
#pragma unroll
    for (int h = 0; h < NH2; h++) {
        __half2 hv = __floats2half2_rn((acc[h].x + acc2[h].x) * inv, (acc[h].y + acc2[h].y) * inv);
        o[h] = *(uint32_t*)&hv;
    }
    __half* mo = meanp + (size_t)gw * D;
    if (NH2 == 4) ((uint4*)mo)[lane] = make_uint4(o[0], o[1], o[2], o[3]);
    else ((uint2*)mo)[lane] = make_uint2(o[0], o[1]);
}

// ================= fp16 mma fused dual-GEMM + bias + LN + ReLU (K=32 chunks) =================
// B fragments pre-paired (one LDS.64); A fragments via ldmatrix.x4 (one LDSM per 16x16).
template <int DIN, int DOUT>
__launch_bounds__(512)
__global__ void k_gemm_tc(const __half* __restrict__ A0, const __half* __restrict__ A1,
                          const uint2* __restrict__ W0q, const uint2* __restrict__ W1q,
                          const float* __restrict__ bias, const float* __restrict__ gamma,
                          const float* __restrict__ beta, __half* __restrict__ out, int n) {
    extern __shared__ float sm[];
    constexpr int NCH = DIN / 32;         // 32 k-halves per chunk
    constexpr int TOT = 2 * NCH;
    constexpr int NT = DOUT / 32;
    constexpr int APH = 40;               // A pitch in halves (80 B)
    constexpr int AHSZ = 128 * APH;
    constexpr int BP2 = DOUT + 4;         // B pitch (uint2)
    constexpr int BSZ2 = 8 * BP2;

    __half* Ah = (__half*)sm;
    __half* Ab[3] = { Ah, Ah + AHSZ, Ah + 2 * AHSZ };
    float* after = sm + (3 * AHSZ) / 2;
    uint2* Bb[3] = { (uint2*)after, (uint2*)after + BSZ2, (uint2*)after + 2 * BSZ2 };
    float* sp = after + 3 * BSZ2 * 2;
    float* sln = sp + 3 * DOUT;

    int t = threadIdx.x;
    int wid = t >> 5, lane = t & 31;
    int g = lane >> 2, tq = lane & 3;
    int mw = wid & 3, nq = wid >> 2;
    int nbase = nq * (DOUT / 4);
    int row0 = blockIdx.x * 128;
    // ldmatrix per-lane offset (bytes): row = lane&15, col = (lane&16)>>1
    uint32_t poff = (uint32_t)(((lane & 15) * APH + ((lane & 16) >> 1)) * 2);
    uint32_t abase_s[3] = { su32(Ab[0]), su32(Ab[1]), su32(Ab[2]) };

    for (int i = t; i < DOUT; i += 512) {
        sp[i] = bias[i];
        sp[DOUT + i] = gamma[i];
        sp[2 * DOUT + i] = beta[i];
    }
    __syncthreads();

    float acc[2][NT][4];
#pragma unroll
    for (int ms = 0; ms < 2; ms++)
#pragma unroll
        for (int nt = 0; nt < NT; nt++)
#pragma unroll
            for (int j = 0; j < 4; j++) acc[ms][nt][j] = 0.f;

    auto copy_chunk = [&](int c, int ib) {
        const __half* A = (c < NCH) ? A0 : A1;
        const uint2* W = (c < NCH) ? W0q : W1q;
        int cc = (c < NCH) ? c : c - NCH;
        int k0 = cc * 32;
        uint32_t abase = abase_s[ib];
        uint32_t bbase = su32(Bb[ib]);
        {
            int r = t >> 2, seg = t & 3;
            int gr = row0 + r;
            bool ok = gr < n;
            int cr = ok ? gr : (n - 1);
            cpa16(abase + (uint32_t)(r * 80 + seg * 16),
                  A + (size_t)cr * DIN + k0 + seg * 8, ok);
        }
#pragma unroll
        for (int i = 0; i < DOUT / 128; i++) {
            int s = t + i * 512;
            int kr = s / (DOUT / 2), c2 = (s % (DOUT / 2)) * 2;
            cpa16(bbase + (uint32_t)(kr * BP2 + c2) * 8,
                  W + (size_t)(cc * 8 + kr) * DOUT + c2, true);
        }
    };

    auto mma_chunk = [&](int ib) {
        const uint2* Bs = Bb[ib];
        uint32_t abase = abase_s[ib];
#pragma unroll
        for (int ks = 0; ks < 2; ks++) {
            int kb = ks * 16;
            uint2 bf[NT];
#pragma unroll
            for (int nt = 0; nt < NT; nt++)
                bf[nt] = Bs[(ks * 4 + tq) * BP2 + nbase + nt * 8 + g];
#pragma unroll
            for (int ms = 0; ms < 2; ms++) {
                int ar0 = mw * 32 + ms * 16;
                uint32_t a0, a1, a2, a3;
                ldsm_x4(a0, a1, a2, a3, abase + (uint32_t)((ar0 * APH + kb) * 2) + poff);
#pragma unroll
                for (int nt = 0; nt < NT; nt++)
                    mma_f16(acc[ms][nt], a0, a1, a2, a3, bf[nt].x, bf[nt].y);
            }
        }
    };

    copy_chunk(0, 0); CP_COMMIT();
    copy_chunk(1, 1); CP_COMMIT();
    for (int c = 0; c < TOT; c++) {
        if (c < TOT - 1) CP_WAIT1(); else CP_WAIT0();
        __syncthreads();
        if (c + 2 < TOT) { copy_chunk(c + 2, (c + 2) % 3); CP_COMMIT(); }
        mma_chunk(c % 3);
    }

    // ---- epilogue: +bias, LN over DOUT (4 n-quarter partials), ReLU, fp16 out ----
#pragma unroll
    for (int ms = 0; ms < 2; ms++) {
        float s0 = 0.f, ss0 = 0.f, s1 = 0.f, ss1 = 0.f;
#pragma unroll
        for (int nt = 0; nt < NT; nt++) {
            int col = nbase + nt * 8 + 2 * tq;
            float b0 = sp[col], b1 = sp[col + 1];
            acc[ms][nt][0] += b0; acc[ms][nt][1] += b1;
            acc[ms][nt][2] += b0; acc[ms][nt][3] += b1;
            s0 += acc[ms][nt][0] + acc[ms][nt][1];
            ss0 += acc[ms][nt][0] * acc[ms][nt][0] + acc[ms][nt][1] * acc[ms][nt][1];
            s1 += acc[ms][nt][2] + acc[ms][nt][3];
            ss1 += acc[ms][nt][2] * acc[ms][nt][2] + acc[ms][nt][3] * acc[ms][nt][3];
        }
#pragma unroll
        for (int o = 1; o <= 2; o <<= 1) {
            s0 += __shfl_xor_sync(0xffffffffu, s0, o);
            ss0 += __shfl_xor_sync(0xffffffffu, ss0, o);
            s1 += __shfl_xor_sync(0xffffffffu, s1, o);
            ss1 += __shfl_xor_sync(0xffffffffu, ss1, o);
        }
        if (tq == 0) {
            int r0 = mw * 32 + ms * 16 + g;
            ((float2*)sln)[r0 * 4 + nq] = make_float2(s0, ss0);
            ((float2*)sln)[(r0 + 8) * 4 + nq] = make_float2(s1, ss1);
        }
    }
    __syncthreads();
#pragma unroll
    for (int ms = 0; ms < 2; ms++) {
        int rl0 = mw * 32 + ms * 16 + g, rl1 = rl0 + 8;
        float s0 = 0.f, ss0 = 0.f, s1 = 0.f, ss1 = 0.f;
#pragma unroll
        for (int q = 0; q < 4; q++) {
            float2 p0 = ((float2*)sln)[rl0 * 4 + q];
            float2 p1 = ((float2*)sln)[rl1 * 4 + q];
            s0 += p0.x; ss0 += p0.y;
            s1 += p1.x; ss1 += p1.y;
        }
        float mu0 = s0 * (1.0f / DOUT);
        float rs0 = rsqrtf(ss0 * (1.0f / DOUT) - mu0 * mu0 + 1e-5f);
        float mu1 = s1 * (1.0f / DOUT);
        float rs1 = rsqrtf(ss1 * (1.0f / DOUT) - mu1 * mu1 + 1e-5f);
        int grow0 = row0 + rl0, grow1 = row0 + rl1;
#pragma unroll
        for (int nt = 0; nt < NT; nt++) {
            int col = nbase + nt * 8 + 2 * tq;
            float ga0 = sp[DOUT + col], ga1 = sp[DOUT + col + 1];
            float bt0 = sp[2 * DOUT + col], bt1 = sp[2 * DOUT + col + 1];
            if (grow0 < n) {
                float vx = fmaxf((acc[ms][nt][0] - mu0) * rs0 * ga0 + bt0, 0.f);
                float vy = fmaxf((acc[ms][nt][1] - mu0) * rs0 * ga1 + bt1, 0.f);
                *(__half2*)(out + (size_t)grow0 * DOUT + col) = __floats2half2_rn(vx, vy);
            }
            if (grow1 < n) {
                float vx = fmaxf((acc[ms][nt][2] - mu1) * rs1 * ga0 + bt0, 0.f);
                float vy = fmaxf((acc[ms][nt][3] - mu1) * rs1 * ga1 + bt1, 0.f);
                *(__half2*)(out + (size_t)grow1 * DOUT + col) = __floats2half2_rn(vx, vy);
            }
        }
    }
}

// ================= dual-output GEMM: YM = X@W0, YR = X@W1 + b (fp16 out) =================
template <int DIN, int DOUT>
__launch_bounds__(512)
__global__ void k_gemm_dual(const __half* __restrict__ X,
                            const uint2* __restrict__ W0q, const uint2* __restrict__ W1q,
                            const float* __restrict__ bias,
                            __half* __restrict__ ym, __half* __restrict__ yr, int n) {
    extern __shared__ float sm[];
    constexpr int NCH = DIN / 32;
    constexpr int NT = DOUT / 32;
    constexpr int APH = 40;
    constexpr int AHSZ = 128 * APH;
    constexpr int BP2 = DOUT + 4;
    constexpr int BSZ2 = 8 * BP2;

    __half* Ah = (__half*)sm;
    __half* Ab[3] = { Ah, Ah + AHSZ, Ah + 2 * AHSZ };
    float* after = sm + (3 * AHSZ) / 2;
    uint2* B0b[3] = { (uint2*)after, (uint2*)after + BSZ2, (uint2*)after + 2 * BSZ2 };
    uint2* B1b[3] = { (uint2*)after + 3 * BSZ2, (uint2*)after + 4 * BSZ2, (uint2*)after + 5 * BSZ2 };
    float* sp = after + 6 * BSZ2 * 2;

    int t = threadIdx.x;
    int wid = t >> 5, lane = t & 31;
    int g = lane >> 2, tq = lane & 3;
    int mw = wid & 3, nq = wid >> 2;
    int nbase = nq * (DOUT / 4);
    int row0 = blockIdx.x * 128;
    uint32_t poff = (uint32_t)(((lane & 15) * APH + ((lane & 16) >> 1)) * 2);
    uint32_t abase_s[3] = { su32(Ab[0]), su32(Ab[1]), su32(Ab[2]) };

    for (int i = t; i < DOUT; i += 512) sp[i] = bias[i];
    __syncthreads();

    float accM[2][NT][4], accR[2][NT][4];
#pragma unroll
    for (int ms = 0; ms < 2; ms++)
#pragma unroll
        for (int nt = 0; nt < NT; nt++)
#pragma unroll
            for (int j = 0; j < 4; j++) { accM[ms][nt][j] = 0.f; accR[ms][nt][j] = 0.f; }

    auto copy_chunk = [&](int c, int ib) {
        int k0 = c * 32;
        uint32_t abase = abase_s[ib];
        uint32_t b0base = su32(B0b[ib]);
        uint32_t b1base = su32(B1b[ib]);
        {
            int r = t >> 2, seg = t & 3;
            int gr = row0 + r;
            bool ok = gr < n;
            int cr = ok ? gr : (n - 1);
            cpa16(abase + (uint32_t)(r * 80 + seg * 16),
                  X + (size_t)cr * DIN + k0 + seg * 8, ok);
        }
        {
            int kr = t / (DOUT / 2), c2 = (t % (DOUT / 2)) * 2;
            size_t wo = (size_t)(c * 8 + kr) * DOUT + c2;
            uint32_t so = (uint32_t)(kr * BP2 + c2) * 8;
            cpa16(b0base + so, W0q + wo, true);
            cpa16(b1base + so, W1q + wo, true);
        }
    };

    auto mma_chunk = [&](int ib) {
        const uint2* B0s = B0b[ib];
        const uint2* B1s = B1b[ib];
        uint32_t abase = abase_s[ib];
#pragma unroll
        for (int ks = 0; ks < 2; ks++) {
            int kb = ks * 16;
            uint2 bfM[NT], bfR[NT];
#pragma unroll
            for (int nt = 0; nt < NT; nt++) {
                int bi = (ks * 4 + tq) * BP2 + nbase + nt * 8 + g;
                bfM[nt] = B0s[bi];
                bfR[nt] = B1s[bi];
            }
#pragma unroll
            for (int ms = 0; ms < 2; ms++) {
                int ar0 = mw * 32 + ms * 16;
                uint32_t a0, a1, a2, a3;
                ldsm_x4(a0, a1, a2, a3, abase + (uint32_t)((ar0 * APH + kb) * 2) + poff);
#pragma unroll
                for (int nt = 0; nt < NT; nt++) {
                    mma_f16(accM[ms][nt], a0, a1, a2, a3, bfM[nt].x, bfM[nt].y);
                    mma_f16(accR[ms][nt], a0, a1, a2, a3, bfR[nt].x, bfR[nt].y);
                }
            }
        }
    };

    copy_chunk(0, 0); CP_COMMIT();
    copy_chunk(1, 1); CP_COMMIT();
    for (int c = 0; c < NCH; c++) {
        if (c < NCH - 1) CP_WAIT1(); else CP_WAIT0();
        __syncthreads();
        if (c + 2 < NCH) { copy_chunk(c + 2, (c + 2) % 3); CP_COMMIT(); }
        mma_chunk(c % 3);
    }

#pragma unroll
    for (int ms = 0; ms < 2; ms++) {
        int rl0 = mw * 32 + ms * 16 + g, rl1 = rl0 + 8;
        int grow0 = row0 + rl0, grow1 = row0 + rl1;
#pragma unroll
        for (int nt = 0; nt < NT; nt++) {
            int col = nbase + nt * 8 + 2 * tq;
            float b0 = sp[col], b1 = sp[col + 1];
            if (grow0 < n) {
                *(__half2*)(ym + (size_t)grow0 * DOUT + col) = __floats2half2_rn(accM[ms][nt][0], accM[ms][nt][1]);
                *(__half2*)(yr + (size_t)grow0 * DOUT + col) = __floats2half2_rn(accR[ms][nt][0] + b0, accR[ms][nt][1] + b1);
            }
            if (grow1 < n) {
                *(__half2*)(ym + (size_t)grow1 * DOUT + col) = __floats2half2_rn(accM[ms][nt][2], accM[ms][nt][3]);
                *(__half2*)(yr + (size_t)grow1 * DOUT + col) = __floats2half2_rn(accR[ms][nt][2] + b0, accR[ms][nt][3] + b1);
            }
        }
    }
}

// ===== fused: x3 = ReLU(LN(mean + yr)); ym9 = x3@Wm4; yr9 = x3@Wr4 + b4 =====
__global__ void k_lnout(const __half* __restrict__ meanp, const __half* __restrict__ yr,
                        const float* __restrict__ gamma, const float* __restrict__ beta,
                        const float* __restrict__ wm, const float* __restrict__ wr,
                        const float* __restrict__ bias,
                        float* __restrict__ ym9, float* __restrict__ yr9, int n) {
    __shared__ float swm[128 * 9];
    __shared__ float swr[128 * 9];
    __shared__ float sb[9];
    for (int i = threadIdx.x; i < 128 * 9; i += blockDim.x) {
        swm[i] = wm[i];
        swr[i] = wr[i];
    }
    if (threadIdx.x < 9) sb[threadIdx.x] = bias[threadIdx.x];
    __syncthreads();

    int row = (blockIdx.x * blockDim.x + threadIdx.x) >> 5;
    int lane = threadIdx.x & 31;
    if (row >= n) return;

    uint2 mu2 = ((const uint2*)(meanp + (size_t)row * 128))[lane];
    uint2 yu2 = ((const uint2*)(yr + (size_t)row * 128))[lane];
    float2 m0 = __half22float2(*(__half2*)&mu2.x), m1 = __half22float2(*(__half2*)&mu2.y);
    float2 y0 = __half22float2(*(__half2*)&yu2.x), y1 = __half22float2(*(__half2*)&yu2.y);
    float v[4] = { m0.x + y0.x, m0.y + y0.y, m1.x + y1.x, m1.y + y1.y };
    float s = v[0] + v[1] + v[2] + v[3];
    float ss = v[0] * v[0] + v[1] * v[1] + v[2] * v[2] + v[3] * v[3];
#pragma unroll
    for (int o = 16; o; o >>= 1) {
        s += __shfl_xor_sync(0xffffffffu, s, o);
        ss += __shfl_xor_sync(0xffffffffu, ss, o);
    }
    float mu = s * (1.0f / 128.0f);
    float var = ss * (1.0f / 128.0f) - mu * mu;
    float rs = rsqrtf(var + 1e-5f);
    float4 g4 = ((const float4*)gamma)[lane];
    float4 b4 = ((const float4*)beta)[lane];
    float x4[4];
    x4[0] = fmaxf((v[0] - mu) * rs * g4.x + b4.x, 0.f);
    x4[1] = fmaxf((v[1] - mu) * rs * g4.y + b4.y, 0.f);
    x4[2] = fmaxf((v[2] - mu) * rs * g4.z + b4.z, 0.f);
    x4[3] = fmaxf((v[3] - mu) * rs * g4.w + b4.w, 0.f);

    float om[9], orr[9];
#pragma unroll
    for (int j = 0; j < 9; j++) { om[j] = 0.f; orr[j] = 0.f; }
#pragma unroll
    for (int q = 0; q < 4; q++) {
        int k = lane * 4 + q;
#pragma unroll
        for (int j = 0; j < 9; j++) {
            om[j] += x4[q] * swm[k * 9 + j];
            orr[j] += x4[q] * swr[k * 9 + j];
        }
    }
#pragma unroll
    for (int j = 0; j < 9; j++)
#pragma unroll
        for (int o = 16; o; o >>= 1) {
            om[j] += __shfl_xor_sync(0xffffffffu, om[j], o);
            orr[j] += __shfl_xor_sync(0xffffffffu, orr[j], o);
        }
    if (lane < 9) {
        ym9[(size_t)row * 9 + lane] = om[lane];
        yr9[(size_t)row * 9 + lane] = orr[lane] + sb[lane];
    }
}

// ================= final: out = mean(ym9[src]) + yr9; re-zero g_deg =================
__global__ void k_agg9(const float* __restrict__ ym9, const float* __restrict__ yr9,
                       float* __restrict__ out, int n) {
    int gt = blockIdx.x * blockDim.x + threadIdx.x;
    if (gt < NMAX) g_deg[gt] = 0;
    int gw = gt >> 5;
    int lane = threadIdx.x & 31;
    if (gw >= n) return;
    int b = g_off[gw], e = g_off[gw + 1];
    float acc[9];
#pragma unroll
    for (int j = 0; j < 9; j++) acc[j] = 0.f;
    for (int j = b + lane; j < e; j += 32) {
        const float* row = ym9 + (size_t)g_csr[j] * 9;
#pragma unroll
        for (int c = 0; c < 9; c++) acc[c] += row[c];
    }
#pragma unroll
    for (int c = 0; c < 9; c++)
#pragma unroll
        for (int s = 16; s; s >>= 1) acc[c] += __shfl_xor_sync(0xffffffffu, acc[c], s);
    if (lane < 9) {
        float inv = 1.0f / g_cnt[gw];
        out[(size_t)gw * 9 + lane] = acc[lane] * inv + yr9[(size_t)gw * 9 + lane];
    }
}

// ================= launch =================
extern "C" void kernel_launch(void* const* d_in, const int* in_sizes, int n_in,
                              void* d_out, int out_size) {
    const float* z = (const float*)d_in[0];
    const int* ei = (const int*)d_in[1];
    const float* wm1 = (const float*)d_in[2];
    const float* wr1 = (const float*)d_in[3];
    const float* b1 = (const float*)d_in[4];
    const float* g1 = (const float*)d_in[5];
    const float* be1 = (const float*)d_in[6];
    const float* wm2 = (const float*)d_in[7];
    const float* wr2 = (const float*)d_in[8];
    const float* b2 = (const float*)d_in[9];
    const float* g2 = (const float*)d_in[10];
    const float* be2 = (const float*)d_in[11];
    const float* wm3 = (const float*)d_in[12];
    const float* wr3 = (const float*)d_in[13];
    const float* b3 = (const float*)d_in[14];
    const float* g3 = (const float*)d_in[15];
    const float* be3 = (const float*)d_in[16];
    const float* wm4 = (const float*)d_in[17];
    const float* wr4 = (const float*)d_in[18];
    const float* b4 = (const float*)d_in[19];

    int N = in_sizes[0] / 128;
    int E = in_sizes[1] / 2;
    const int* src = ei;
    const int* dst = ei + E;

    __half *hz, *hA, *hB, *hM;
    float *ym9, *yr9;
    uint2 *w1m, *w1r, *w2m, *w2r, *w3m, *w3r;
    void* p;
    cudaGetSymbolAddress(&p, g_hz);  hz = (__half*)p;
    cudaGetSymbolAddress(&p, g_hA);  hA = (__half*)p;
    cudaGetSymbolAddress(&p, g_hB);  hB = (__half*)p;
    cudaGetSymbolAddress(&p, g_hM);  hM = (__half*)p;
    cudaGetSymbolAddress(&p, g_ym9); ym9 = (float*)p;
    cudaGetSymbolAddress(&p, g_yr9); yr9 = (float*)p;
    cudaGetSymbolAddress(&p, g_w1m); w1m = (uint2*)p;
    cudaGetSymbolAddress(&p, g_w1r); w1r = (uint2*)p;
    cudaGetSymbolAddress(&p, g_w2m); w2m = (uint2*)p;
    cudaGetSymbolAddress(&p, g_w2r); w2r = (uint2*)p;
    cudaGetSymbolAddress(&p, g_w3m); w3m = (uint2*)p;
    cudaGetSymbolAddress(&p, g_w3r); w3r = (uint2*)p;

    const int SM256 = (7680 + 48 * (256 + 4) + 3 * 256 + 1024) * 4;
    const int SMD128 = (7680 + 96 * (128 + 4) + 128) * 4;
    cudaFuncSetAttribute(k_gemm_tc<128, 256>, cudaFuncAttributeMaxDynamicSharedMemorySize, SM256);
    cudaFuncSetAttribute(k_gemm_tc<256, 256>, cudaFuncAttributeMaxDynamicSharedMemorySize, SM256);
    cudaFuncSetAttribute(k_gemm_dual<256, 128>, cudaFuncAttributeMaxDynamicSharedMemorySize, SMD128);

    // CSR build (parallel scan)
    int nb = (N + 1023) / 1024;
    k_hist<<<(E + 255) / 256, 256>>>(dst, E);
    k_scan1<<<nb, 1024>>>(N);
    k_scan2<<<1, 128>>>(nb);
    k_scan3<<<(N + 255) / 256, 256>>>(N, E);
    k_scatter<<<(E + 255) / 256, 256>>>(src, dst, E);

    int aggBlocks = (N + 7) / 8;
    int gemmBlocks = (N + 127) / 128;

    // z -> fp16
    k_z2h<<<(N * 64 + 255) / 256, 256>>>(z, hz, N * 64);
    // Layer 1 agg (mean of z, fp16)
    k_aggh<128><<<aggBlocks, 256>>>(hz, hM, N);

    // weight pack (k16 fragment uint2)
    k_packq<<<(32 * 256 + 255) / 256, 256>>>(wm1, w1m, 128, 256);
    k_packq<<<(32 * 256 + 255) / 256, 256>>>(wr1, w1r, 128, 256);
    k_packq<<<(64 * 256 + 255) / 256, 256>>>(wm2, w2m, 256, 256);
    k_packq<<<(64 * 256 + 255) / 256, 256>>>(wr2, w2r, 256, 256);
    k_packq<<<(64 * 128 + 255) / 256, 256>>>(wm3, w3m, 256, 128);
    k_packq<<<(64 * 128 + 255) / 256, 256>>>(wr3, w3r, 256, 128);

    // Layer 1: 128 -> 256 (aggregate-first)
    k_gemm_tc<128, 256><<<gemmBlocks, 512, SM256>>>(hM, hz, w1m, w1r, b1, g1, be1, hA, N);
    // Layer 2: 256 -> 256 (aggregate-first)
    k_aggh<256><<<aggBlocks, 256>>>(hA, hM, N);
    k_gemm_tc<256, 256><<<gemmBlocks, 512, SM256>>>(hM, hA, w2m, w2r, b2, g2, be2, hB, N);
    // Layer 3: 256 -> 128 (aggregate-AFTER): ym->hM, yr->hA
    k_gemm_dual<256, 128><<<gemmBlocks, 512, SMD128>>>(hB, w3m, w3r, b3, hM, hA, N);
    k_aggh<128><<<aggBlocks, 256>>>(hM, hB, N);                  // mean(ym) -> hB
    // Layer 3 LN + Layer 4 projection fused
    k_lnout<<<aggBlocks, 256>>>(hB, hA, g3, be3, wm4, wr4, b4, ym9, yr9, N);
    k_agg9<<<aggBlocks, 256>>>(ym9, yr9, (float*)d_out, N);
}

// round 15
// speedup vs baseline: 1.5955x; 1.0143x over previous
#include <cuda_runtime.h>
#include <cuda_fp16.h>
#include <cstdint>

// ================= static scratch =================
#define NMAX 100352
#define EMAX 1700000

__device__ int   g_deg[NMAX];     // zeroed at load; re-zeroed by k_agg9 each launch
__device__ int   g_off[NMAX + 1];
__device__ int   g_cur[NMAX];
__device__ int   g_csr[EMAX];
__device__ int   g_bsum[128];
__device__ float g_cnt[NMAX];
__device__ float g_ym9[(size_t)NMAX * 9];
__device__ float g_yr9[(size_t)NMAX * 9];
// fp16 activations / means
__device__ __align__(16) __half g_hz[(size_t)NMAX * 128];
__device__ __align__(16) __half g_hA[(size_t)NMAX * 256];
__device__ __align__(16) __half g_hB[(size_t)NMAX * 256];
__device__ __align__(16) __half g_hM[(size_t)NMAX * 256];
// k16-frag packed weights
__device__ uint2 g_w1m[(128 / 4) * 256];
__device__ uint2 g_w1r[(128 / 4) * 256];
__device__ uint2 g_w2m[(256 / 4) * 256];
__device__ uint2 g_w2r[(256 / 4) * 256];
__device__ uint2 g_w3m[(256 / 4) * 128];
__device__ uint2 g_w3r[(256 / 4) * 128];

// ================= helpers =================
__device__ __forceinline__ uint32_t f2h2(float lo, float hi) {
    uint32_t r;
    asm("cvt.rn.f16x2.f32 %0, %1, %2;" : "=r"(r) : "f"(hi), "f"(lo));
    return r;
}
__device__ __forceinline__ void mma_f16(float* c, uint32_t a0, uint32_t a1, uint32_t a2, uint32_t a3,
                                        uint32_t b0, uint32_t b1) {
    asm volatile("mma.sync.aligned.m16n8k16.row.col.f32.f16.f16.f32 "
                 "{%0,%1,%2,%3}, {%4,%5,%6,%7}, {%8,%9}, {%0,%1,%2,%3};"
                 : "+f"(c[0]), "+f"(c[1]), "+f"(c[2]), "+f"(c[3])
                 : "r"(a0), "r"(a1), "r"(a2), "r"(a3), "r"(b0), "r"(b1));
}
__device__ __forceinline__ void ldsm_x4(uint32_t& r0, uint32_t& r1, uint32_t& r2, uint32_t& r3,
                                        uint32_t addr) {
    asm volatile("ldmatrix.sync.aligned.m8n8.x4.shared.b16 {%0,%1,%2,%3}, [%4];"
                 : "=r"(r0), "=r"(r1), "=r"(r2), "=r"(r3) : "r"(addr));
}
__device__ __forceinline__ uint32_t su32(const void* p) {
    uint32_t a;
    asm("{ .reg .u64 t; cvta.to.shared.u64 t, %1; cvt.u32.u64 %0, t; }" : "=r"(a) : "l"(p));
    return a;
}
__device__ __forceinline__ void cpa16(uint32_t dst, const void* src, bool pred) {
    int sz = pred ? 16 : 0;
    asm volatile("cp.async.cg.shared.global [%0], [%1], 16, %2;" :: "r"(dst), "l"(src), "r"(sz));
}
#define CP_COMMIT() asm volatile("cp.async.commit_group;" ::: "memory")
#define CP_WAIT2()  asm volatile("cp.async.wait_group 2;" ::: "memory")
#define CP_WAIT1()  asm volatile("cp.async.wait_group 1;" ::: "memory")
#define CP_WAIT0()  asm volatile("cp.async.wait_group 0;" ::: "memory")

// ================= fused prep: hist + z->fp16 + weight packing =================
__device__ __forceinline__ void packq_one(const float* __restrict__ W, uint2* __restrict__ Wq,
                                          int N, int i) {
    int r = i / N, n = i - r * N;
    int kg = r >> 2, tq = r & 3;
    int k0 = kg * 16 + 2 * tq;
    uint2 v;
    v.x = f2h2(W[(size_t)k0 * N + n], W[(size_t)(k0 + 1) * N + n]);
    v.y = f2h2(W[(size_t)(k0 + 8) * N + n], W[(size_t)(k0 + 9) * N + n]);
    Wq[i] = v;
}
__global__ void k_prep(const int* __restrict__ dst, int E,
                       const float* __restrict__ z, int n2,
                       const float* __restrict__ wm1, const float* __restrict__ wr1,
                       const float* __restrict__ wm2, const float* __restrict__ wr2,
                       const float* __restrict__ wm3, const float* __restrict__ wr3,
                       int histB, int zB) {
    int b = blockIdx.x;
    if (b < histB) {
        int e = b * 256 + threadIdx.x;
        if (e < E) atomicAdd(&g_deg[dst[e]], 1);
    } else if (b < histB + zB) {
        int i = (b - histB) * 256 + threadIdx.x;
        if (i < n2) {
            float2 v = ((const float2*)z)[i];
            ((__half2*)g_hz)[i] = __floats2half2_rn(v.x, v.y);
        }
    } else {
        int i = (b - histB - zB) * 256 + threadIdx.x;   // 0..65535
        if (i < 8192) packq_one(wm1, g_w1m, 256, i);
        else if (i < 16384) packq_one(wr1, g_w1r, 256, i - 8192);
        else if (i < 32768) packq_one(wm2, g_w2m, 256, i - 16384);
        else if (i < 49152) packq_one(wr2, g_w2r, 256, i - 32768);
        else if (i < 57344) packq_one(wm3, g_w3m, 128, i - 49152);
        else packq_one(wr3, g_w3r, 128, i - 57344);
    }
}

// ================= CSR scan / scatter =================
__global__ void k_scan1(int n) {
    __shared__ int sh[1024];
    int i = blockIdx.x * 1024 + threadIdx.x;
    int d = (i < n) ? g_deg[i] : 0;
    sh[threadIdx.x] = d;
    __syncthreads();
    for (int o = 1; o < 1024; o <<= 1) {
        int v = (threadIdx.x >= o) ? sh[threadIdx.x - o] : 0;
        __syncthreads();
        sh[threadIdx.x] += v;
        __syncthreads();
    }
    if (i < n) g_off[i] = sh[threadIdx.x] - d;
    if (threadIdx.x == 1023) g_bsum[blockIdx.x] = sh[1023];
}
__global__ void k_scan2(int nb) {
    __shared__ int sh[128];
    int d = (threadIdx.x < nb) ? g_bsum[threadIdx.x] : 0;
    sh[threadIdx.x] = d;
    __syncthreads();
    for (int o = 1; o < 128; o <<= 1) {
        int v = (threadIdx.x >= o) ? sh[threadIdx.x - o] : 0;
        __syncthreads();
        sh[threadIdx.x] += v;
        __syncthreads();
    }
    if (threadIdx.x < nb) g_bsum[threadIdx.x] = sh[threadIdx.x] - d;
}
__global__ void k_scan3(int n, int E) {
    int i = blockIdx.x * blockDim.x + threadIdx.x;
    if (i == 0) g_off[n] = E;
    if (i >= n) return;
    int off = g_off[i] + g_bsum[i >> 10];
    g_off[i] = off;
    g_cur[i] = off;
    int d = g_deg[i];
    g_cnt[i] = (d > 0) ? (float)d : 1.0f;
}
__global__ void k_scatter(const int* __restrict__ src, const int* __restrict__ dst, int E) {
    int e = blockIdx.x * blockDim.x + threadIdx.x;
    if (e < E) {
        int p = atomicAdd(&g_cur[dst[e]], 1);
        g_csr[p] = src[e];
    }
}

// ================= mean aggregation (half in/out, fp32 acc) =================
template <int D>
__global__ void k_aggh(const __half* __restrict__ x, __half* __restrict__ meanp, int n) {
    int gw = (blockIdx.x * blockDim.x + threadIdx.x) >> 5;
    int lane = threadIdx.x & 31;
    if (gw >= n) return;
    int b = g_off[gw], e = g_off[gw + 1];
    constexpr int NH2 = D / 64;
    float2 acc[NH2], acc2[NH2];
#pragma unroll
    for (int h = 0; h < NH2; h++) {
        acc[h] = make_float2(0.f, 0.f);
        acc2[h] = make_float2(0.f, 0.f);
    }
    auto addrow = [&](const __half* rp, float2* a) {
        uint32_t w[NH2];
        if (NH2 == 4) {
            uint4 u = ((const uint4*)rp)[lane];
            w[0] = u.x; w[1] = u.y; w[2] = u.z; w[3] = u.w;
        } else {
            uint2 u = ((const uint2*)rp)[lane];
            w[0] = u.x; w[1] = u.y;
        }
#pragma unroll
        for (int h = 0; h < NH2; h++) {
            float2 f = __half22float2(*(__half2*)&w[h]);
            a[h].x += f.x;
            a[h].y += f.y;
        }
    };
    int j = b;
    for (; j + 1 < e; j += 2) {
        addrow(x + (size_t)g_csr[j] * D, acc);
        addrow(x + (size_t)g_csr[j + 1] * D, acc2);
    }
    if (j < e) addrow(x + (size_t)g_csr[j] * D, acc);

    float inv = 1.0f / g_cnt[gw];
    uint32_t o[NH2];
#pragma unroll
    for (int h = 0; h < NH2; h++) {
        __half2 hv = __floats2half2_rn((acc[h].x + acc2[h].x) * inv, (acc[h].y + acc2[h].y) * inv);
        o[h] = *(uint32_t*)&hv;
    }
    __half* mo = meanp + (size_t)gw * D;
    if (NH2 == 4) ((uint4*)mo)[lane] = make_uint4(o[0], o[1], o[2], o[3]);
    else ((uint2*)mo)[lane] = make_uint2(o[0], o[1]);
}

// ================= fp16 mma fused dual-GEMM + bias + LN + ReLU =================
// K=32 chunks, 4-stage cp.async pipeline (wait_group 2 -> 2-chunk latency cover).
template <int DIN, int DOUT>
__launch_bounds__(512)
__global__ void k_gemm_tc(const __half* __restrict__ A0, const __half* __restrict__ A1,
                          const uint2* __restrict__ W0q, const uint2* __restrict__ W1q,
                          const float* __restrict__ bias, const float* __restrict__ gamma,
                          const float* __restrict__ beta, __half* __restrict__ out, int n) {
    extern __shared__ float sm[];
    constexpr int NCH = DIN / 32;
    constexpr int TOT = 2 * NCH;
    constexpr int NT = DOUT / 32;
    constexpr int APH = 40;
    constexpr int AHSZ = 128 * APH;       // halves per A stage
    constexpr int BP2 = DOUT + 4;         // B pitch (uint2)
    constexpr int BSZ2 = 8 * BP2;

    __half* Ah = (__half*)sm;
    __half* Ab[4] = { Ah, Ah + AHSZ, Ah + 2 * AHSZ, Ah + 3 * AHSZ };
    float* after = sm + (4 * AHSZ) / 2;
    uint2* Bb[4] = { (uint2*)after, (uint2*)after + BSZ2, (uint2*)after + 2 * BSZ2,
                     (uint2*)after + 3 * BSZ2 };
    float* sp = after + 4 * BSZ2 * 2;
    float* sln = sp + 3 * DOUT;

    int t = threadIdx.x;
    int wid = t >> 5, lane = t & 31;
    int g = lane >> 2, tq = lane & 3;
    int mw = wid & 3, nq = wid >> 2;
    int nbase = nq * (DOUT / 4);
    int row0 = blockIdx.x * 128;
    uint32_t poff = (uint32_t)(((lane & 15) * APH + ((lane & 16) >> 1)) * 2);
    uint32_t abase_s[4] = { su32(Ab[0]), su32(Ab[1]), su32(Ab[2]), su32(Ab[3]) };

    for (int i = t; i < DOUT; i += 512) {
        sp[i] = bias[i];
        sp[DOUT + i] = gamma[i];
        sp[2 * DOUT + i] = beta[i];
    }
    __syncthreads();

    float acc[2][NT][4];
#pragma unroll
    for (int ms = 0; ms < 2; ms++)
#pragma unroll
        for (int nt = 0; nt < NT; nt++)
#pragma unroll
            for (int j = 0; j < 4; j++) acc[ms][nt][j] = 0.f;

    auto copy_chunk = [&](int c, int ib) {
        const __half* A = (c < NCH) ? A0 : A1;
        const uint2* W = (c < NCH) ? W0q : W1q;
        int cc = (c < NCH) ? c : c - NCH;
        int k0 = cc * 32;
        uint32_t abase = abase_s[ib];
        uint32_t bbase = su32(Bb[ib]);
        {
            int r = t >> 2, seg = t & 3;
            int gr = row0 + r;
            bool ok = gr < n;
            int cr = ok ? gr : (n - 1);
            cpa16(abase + (uint32_t)(r * 80 + seg * 16),
                  A + (size_t)cr * DIN + k0 + seg * 8, ok);
        }
#pragma unroll
        for (int i = 0; i < DOUT / 128; i++) {
            int s = t + i * 512;
            int kr = s / (DOUT / 2), c2 = (s % (DOUT / 2)) * 2;
            cpa16(bbase + (uint32_t)(kr * BP2 + c2) * 8,
                  W + (size_t)(cc * 8 + kr) * DOUT + c2, true);
        }
    };

    auto mma_chunk = [&](int ib) {
        const uint2* Bs = Bb[ib];
        uint32_t abase = abase_s[ib];
#pragma unroll
        for (int ks = 0; ks < 2; ks++) {
            int kb = ks * 16;
            uint2 bf[NT];
#pragma unroll
            for (int nt = 0; nt < NT; nt++)
                bf[nt] = Bs[(ks * 4 + tq) * BP2 + nbase + nt * 8 + g];
#pragma unroll
            for (int ms = 0; ms < 2; ms++) {
                int ar0 = mw * 32 + ms * 16;
                uint32_t a0, a1, a2, a3;
                ldsm_x4(a0, a1, a2, a3, abase + (uint32_t)((ar0 * APH + kb) * 2) + poff);
#pragma unroll
                for (int nt = 0; nt < NT; nt++)
                    mma_f16(acc[ms][nt], a0, a1, a2, a3, bf[nt].x, bf[nt].y);
            }
        }
    };

    copy_chunk(0, 0); CP_COMMIT();
    copy_chunk(1, 1); CP_COMMIT();
    copy_chunk(2, 2); CP_COMMIT();
    for (int c = 0; c < TOT; c++) {
        if (c < TOT - 2) CP_WAIT2();
        else if (c < TOT - 1) CP_WAIT1();
        else CP_WAIT0();
        __syncthreads();
        if (c + 3 < TOT) { copy_chunk(c + 3, (c + 3) & 3); CP_COMMIT(); }
        mma_chunk(c & 3);
    }

    // ---- epilogue: +bias, LN over DOUT (4 n-quarter partials), ReLU, fp16 out ----
#pragma unroll
    for (int ms = 0; ms < 2; ms++) {
        float s0 = 0.f, ss0 = 0.f, s1 = 0.f, ss1 = 0.f;
#pragma unroll
        for (int nt = 0; nt < NT; nt++) {
            int col = nbase + nt * 8 + 2 * tq;
            float b0 = sp[col], b1 = sp[col + 1];
            acc[ms][nt][0] += b0; acc[ms][nt][1] += b1;
            acc[ms][nt][2] += b0; acc[ms][nt][3] += b1;
            s0 += acc[ms][nt][0] + acc[ms][nt][1];
            ss0 += acc[ms][nt][0] * acc[ms][nt][0] + acc[ms][nt][1] * acc[ms][nt][1];
            s1 += acc[ms][nt][2] + acc[ms][nt][3];
            ss1 += acc[ms][nt][2] * acc[ms][nt][2] + acc[ms][nt][3] * acc[ms][nt][3];
        }
#pragma unroll
        for (int o = 1; o <= 2; o <<= 1) {
            s0 += __shfl_xor_sync(0xffffffffu, s0, o);
            ss0 += __shfl_xor_sync(0xffffffffu, ss0, o);
            s1 += __shfl_xor_sync(0xffffffffu, s1, o);
            ss1 += __shfl_xor_sync(0xffffffffu, ss1, o);
        }
        if (tq == 0) {
            int r0 = mw * 32 + ms * 16 + g;
            ((float2*)sln)[r0 * 4 + nq] = make_float2(s0, ss0);
            ((float2*)sln)[(r0 + 8) * 4 + nq] = make_float2(s1, ss1);
        }
    }
    __syncthreads();
#pragma unroll
    for (int ms = 0; ms < 2; ms++) {
        int rl0 = mw * 32 + ms * 16 + g, rl1 = rl0 + 8;
        float s0 = 0.f, ss0 = 0.f, s1 = 0.f, ss1 = 0.f;
#pragma unroll
        for (int q = 0; q < 4; q++) {
            float2 p0 = ((float2*)sln)[rl0 * 4 + q];
            float2 p1 = ((float2*)sln)[rl1 * 4 + q];
            s0 += p0.x; ss0 += p0.y;
            s1 += p1.x; ss1 += p1.y;
        }
        float mu0 = s0 * (1.0f / DOUT);
        float rs0 = rsqrtf(ss0 * (1.0f / DOUT) - mu0 * mu0 + 1e-5f);
        float mu1 = s1 * (1.0f / DOUT);
        float rs1 = rsqrtf(ss1 * (1.0f / DOUT) - mu1 * mu1 + 1e-5f);
        int grow0 = row0 + rl0, grow1 = row0 + rl1;
#pragma unroll
        for (int nt = 0; nt < NT; nt++) {
            int col = nbase + nt * 8 + 2 * tq;
            float ga0 = sp[DOUT + col], ga1 = sp[DOUT + col + 1];
            float bt0 = sp[2 * DOUT + col], bt1 = sp[2 * DOUT + col + 1];
            if (grow0 < n) {
                float vx = fmaxf((acc[ms][nt][0] - mu0) * rs0 * ga0 + bt0, 0.f);
                float vy = fmaxf((acc[ms][nt][1] - mu0) * rs0 * ga1 + bt1, 0.f);
                *(__half2*)(out + (size_t)grow0 * DOUT + col) = __floats2half2_rn(vx, vy);
            }
            if (grow1 < n) {
                float vx = fmaxf((acc[ms][nt][2] - mu1) * rs1 * ga0 + bt0, 0.f);
                float vy = fmaxf((acc[ms][nt][3] - mu1) * rs1 * ga1 + bt1, 0.f);
                *(__half2*)(out + (size_t)grow1 * DOUT + col) = __floats2half2_rn(vx, vy);
            }
        }
    }
}

// ================= dual-output GEMM: YM = X@W0, YR = X@W1 + b (fp16 out) =================
template <int DIN, int DOUT>
__launch_bounds__(512)
__global__ void k_gemm_dual(const __half* __restrict__ X,
                            const uint2* __restrict__ W0q, const uint2* __restrict__ W1q,
                            const float* __restrict__ bias,
                            __half* __restrict__ ym, __half* __restrict__ yr, int n) {
    extern __shared__ float sm[];
    constexpr int NCH = DIN / 32;
    constexpr int NT = DOUT / 32;
    constexpr int APH = 40;
    constexpr int AHSZ = 128 * APH;
    constexpr int BP2 = DOUT + 4;
    constexpr int BSZ2 = 8 * BP2;

    __half* Ah = (__half*)sm;
    __half* Ab[4] = { Ah, Ah + AHSZ, Ah + 2 * AHSZ, Ah + 3 * AHSZ };
    float* after = sm + (4 * AHSZ) / 2;
    uint2* B0b[4] = { (uint2*)after, (uint2*)after + BSZ2, (uint2*)after + 2 * BSZ2,
                      (uint2*)after + 3 * BSZ2 };
    uint2* B1b[4] = { (uint2*)after + 4 * BSZ2, (uint2*)after + 5 * BSZ2,
                      (uint2*)after + 6 * BSZ2, (uint2*)after + 7 * BSZ2 };
    float* sp = after + 8 * BSZ2 * 2;

    int t = threadIdx.x;
    int wid = t >> 5, lane = t & 31;
    int g = lane >> 2, tq = lane & 3;
    int mw = wid & 3, nq = wid >> 2;
    int nbase = nq * (DOUT / 4);
    int row0 = blockIdx.x * 128;
    uint32_t poff = (uint32_t)(((lane & 15) * APH + ((lane & 16) >> 1)) * 2);
    uint32_t abase_s[4] = { su32(Ab[0]), su32(Ab[1]), su32(Ab[2]), su32(Ab[3]) };

    for (int i = t; i < DOUT; i += 512) sp[i] = bias[i];
    __syncthreads();

    float accM[2][NT][4], accR[2][NT][4];
#pragma unroll
    for (int ms = 0; ms < 2; ms++)
#pragma unroll
        for (int nt = 0; nt < NT; nt++)
#pragma unroll
            for (int j = 0; j < 4; j++) { accM[ms][nt][j] = 0.f; accR[ms][nt][j] = 0.f; }

    auto copy_chunk = [&](int c, int ib) {
        int k0 = c * 32;
        uint32_t abase = abase_s[ib];
        uint32_t b0base = su32(B0b[ib]);
        uint32_t b1base = su32(B1b[ib]);
        {
            int r = t >> 2, seg = t & 3;
            int gr = row0 + r;
            bool ok = gr < n;
            int cr = ok ? gr : (n - 1);
            cpa16(abase + (uint32_t)(r * 80 + seg * 16),
                  X + (size_t)cr * DIN + k0 + seg * 8, ok);
        }
        {
            int kr = t / (DOUT / 2), c2 = (t % (DOUT / 2)) * 2;
            size_t wo = (size_t)(c * 8 + kr) * DOUT + c2;
            uint32_t so = (uint32_t)(kr * BP2 + c2) * 8;
            cpa16(b0base + so, W0q + wo, true);
            cpa16(b1base + so, W1q + wo, true);
        }
    };

    auto mma_chunk = [&](int ib) {
        const uint2* B0s = B0b[ib];
        const uint2* B1s = B1b[ib];
        uint32_t abase = abase_s[ib];
#pragma unroll
        for (int ks = 0; ks < 2; ks++) {
            int kb = ks * 16;
            uint2 bfM[NT], bfR[NT];
#pragma unroll
            for (int nt = 0; nt < NT; nt++) {
                int bi = (ks * 4 + tq) * BP2 + nbase + nt * 8 + g;
                bfM[nt] = B0s[bi];
                bfR[nt] = B1s[bi];
            }
#pragma unroll
            for (int ms = 0; ms < 2; ms++) {
                int ar0 = mw * 32 + ms * 16;
                uint32_t a0, a1, a2, a3;
                ldsm_x4(a0, a1, a2, a3, abase + (uint32_t)((ar0 * APH + kb) * 2) + poff);
#pragma unroll
                for (int nt = 0; nt < NT; nt++) {
                    mma_f16(accM[ms][nt], a0, a1, a2, a3, bfM[nt].x, bfM[nt].y);
                    mma_f16(accR[ms][nt], a0, a1, a2, a3, bfR[nt].x, bfR[nt].y);
                }
            }
        }
    };

    copy_chunk(0, 0); CP_COMMIT();
    copy_chunk(1, 1); CP_COMMIT();
    copy_chunk(2, 2); CP_COMMIT();
    for (int c = 0; c < NCH; c++) {
        if (c < NCH - 2) CP_WAIT2();
        else if (c < NCH - 1) CP_WAIT1();
        else CP_WAIT0();
        __syncthreads();
        if (c + 3 < NCH) { copy_chunk(c + 3, (c + 3) & 3); CP_COMMIT(); }
        mma_chunk(c & 3);
    }

#pragma unroll
    for (int ms = 0; ms < 2; ms++) {
        int rl0 = mw * 32 + ms * 16 + g, rl1 = rl0 + 8;
        int grow0 = row0 + rl0, grow1 = row0 + rl1;
#pragma unroll
        for (int nt = 0; nt < NT; nt++) {
            int col = nbase + nt * 8 + 2 * tq;
            float b0 = sp[col], b1 = sp[col + 1];
            if (grow0 < n) {
                *(__half2*)(ym + (size_t)grow0 * DOUT + col) = __floats2half2_rn(accM[ms][nt][0], accM[ms][nt][1]);
                *(__half2*)(yr + (size_t)grow0 * DOUT + col) = __floats2half2_rn(accR[ms][nt][0] + b0, accR[ms][nt][1] + b1);
            }
            if (grow1 < n) {
                *(__half2*)(ym + (size_t)grow1 * DOUT + col) = __floats2half2_rn(accM[ms][nt][2], accM[ms][nt][3]);
                *(__half2*)(yr + (size_t)grow1 * DOUT + col) = __floats2half2_rn(accR[ms][nt][2] + b0, accR[ms][nt][3] + b1);
            }
        }
    }
}

// ===== fused: x3 = ReLU(LN(mean + yr)); ym9 = x3@Wm4; yr9 = x3@Wr4 + b4 =====
__global__ void k_lnout(const __half* __restrict__ meanp, const __half* __restrict__ yr,
                        const float* __restrict__ gamma, const float* __restrict__ beta,
                        const float* __restrict__ wm, const float* __restrict__ wr,
                        const float* __restrict__ bias,
                        float* __restrict__ ym9, float* __restrict__ yr9, int n) {
    __shared__ float swm[128 * 9];
    __shared__ float swr[128 * 9];
    __shared__ float sb[9];
    for (int i = threadIdx.x; i < 128 * 9; i += blockDim.x) {
        swm[i] = wm[i];
        swr[i] = wr[i];
    }
    if (threadIdx.x < 9) sb[threadIdx.x] = bias[threadIdx.x];
    __syncthreads();

    int row = (blockIdx.x * blockDim.x + threadIdx.x) >> 5;
    int lane = threadIdx.x & 31;
    if (row >= n) return;

    uint2 mu2 = ((const uint2*)(meanp + (size_t)row * 128))[lane];
    uint2 yu2 = ((const uint2*)(yr + (size_t)row * 128))[lane];
    float2 m0 = __half22float2(*(__half2*)&mu2.x), m1 = __half22float2(*(__half2*)&mu2.y);
    float2 y0 = __half22float2(*(__half2*)&yu2.x), y1 = __half22float2(*(__half2*)&yu2.y);
    float v[4] = { m0.x + y0.x, m0.y + y0.y, m1.x + y1.x, m1.y + y1.y };
    float s = v[0] + v[1] + v[2] + v[3];
    float ss = v[0] * v[0] + v[1] * v[1] + v[2] * v[2] + v[3] * v[3];
#pragma unroll
    for (int o = 16; o; o >>= 1) {
        s += __shfl_xor_sync(0xffffffffu, s, o);
        ss += __shfl_xor_sync(0xffffffffu, ss, o);
    }
    float mu = s * (1.0f / 128.0f);
    float var = ss * (1.0f / 128.0f) - mu * mu;
    float rs = rsqrtf(var + 1e-5f);
    float4 g4 = ((const float4*)gamma)[lane];
    float4 b4 = ((const float4*)beta)[lane];
    float x4[4];
    x4[0] = fmaxf((v[0] - mu) * rs * g4.x + b4.x, 0.f);
    x4[1] = fmaxf((v[1] - mu) * rs * g4.y + b4.y, 0.f);
    x4[2] = fmaxf((v[2] - mu) * rs * g4.z + b4.z, 0.f);
    x4[3] = fmaxf((v[3] - mu) * rs * g4.w + b4.w, 0.f);

    float om[9], orr[9];
#pragma unroll
    for (int j = 0; j < 9; j++) { om[j] = 0.f; orr[j] = 0.f; }
#pragma unroll
    for (int q = 0; q < 4; q++) {
        int k = lane * 4 + q;
#pragma unroll
        for (int j = 0; j < 9; j++) {
            om[j] += x4[q] * swm[k * 9 + j];
            orr[j] += x4[q] * swr[k * 9 + j];
        }
    }
#pragma unroll
    for (int j = 0; j < 9; j++)
#pragma unroll
        for (int o = 16; o; o >>= 1) {
            om[j] += __shfl_xor_sync(0xffffffffu, om[j], o);
            orr[j] += __shfl_xor_sync(0xffffffffu, orr[j], o);
        }
    if (lane < 9) {
        ym9[(size_t)row * 9 + lane] = om[lane];
        yr9[(size_t)row * 9 + lane] = orr[lane] + sb[lane];
    }
}

// ================= final: out = mean(ym9[src]) + yr9; re-zero g_deg =================
__global__ void k_agg9(const float* __restrict__ ym9, const float* __restrict__ yr9,
                       float* __restrict__ out, int n) {
    int gt = blockIdx.x * blockDim.x + threadIdx.x;
    if (gt < NMAX) g_deg[gt] = 0;
    int gw = gt >> 5;
    int lane = threadIdx.x & 31;
    if (gw >= n) return;
    int b = g_off[gw], e = g_off[gw + 1];
    float acc[9];
#pragma unroll
    for (int j = 0; j < 9; j++) acc[j] = 0.f;
    for (int j = b + lane; j < e; j += 32) {
        const float* row = ym9 + (size_t)g_csr[j] * 9;
#pragma unroll
        for (int c = 0; c < 9; c++) acc[c] += row[c];
    }
#pragma unroll
    for (int c = 0; c < 9; c++)
#pragma unroll
        for (int s = 16; s; s >>= 1) acc[c] += __shfl_xor_sync(0xffffffffu, acc[c], s);
    if (lane < 9) {
        float inv = 1.0f / g_cnt[gw];
        out[(size_t)gw * 9 + lane] = acc[lane] * inv + yr9[(size_t)gw * 9 + lane];
    }
}

// ================= launch =================
extern "C" void kernel_launch(void* const* d_in, const int* in_sizes, int n_in,
                              void* d_out, int out_size) {
    const float* z = (const float*)d_in[0];
    const int* ei = (const int*)d_in[1];
    const float* wm1 = (const float*)d_in[2];
    const float* wr1 = (const float*)d_in[3];
    const float* b1 = (const float*)d_in[4];
    const float* g1 = (const float*)d_in[5];
    const float* be1 = (const float*)d_in[6];
    const float* wm2 = (const float*)d_in[7];
    const float* wr2 = (const float*)d_in[8];
    const float* b2 = (const float*)d_in[9];
    const float* g2 = (const float*)d_in[10];
    const float* be2 = (const float*)d_in[11];
    const float* wm3 = (const float*)d_in[12];
    const float* wr3 = (const float*)d_in[13];
    const float* b3 = (const float*)d_in[14];
    const float* g3 = (const float*)d_in[15];
    const float* be3 = (const float*)d_in[16];
    const float* wm4 = (const float*)d_in[17];
    const float* wr4 = (const float*)d_in[18];
    const float* b4 = (const float*)d_in[19];

    int N = in_sizes[0] / 128;
    int E = in_sizes[1] / 2;
    const int* src = ei;
    const int* dst = ei + E;

    __half *hz, *hA, *hB, *hM;
    float *ym9, *yr9;
    uint2 *w1m, *w1r, *w2m, *w2r, *w3m, *w3r;
    void* p;
    cudaGetSymbolAddress(&p, g_hz);  hz = (__half*)p;
    cudaGetSymbolAddress(&p, g_hA);  hA = (__half*)p;
    cudaGetSymbolAddress(&p, g_hB);  hB = (__half*)p;
    cudaGetSymbolAddress(&p, g_hM);  hM = (__half*)p;
    cudaGetSymbolAddress(&p, g_ym9); ym9 = (float*)p;
    cudaGetSymbolAddress(&p, g_yr9); yr9 = (float*)p;
    cudaGetSymbolAddress(&p, g_w1m); w1m = (uint2*)p;
    cudaGetSymbolAddress(&p, g_w1r); w1r = (uint2*)p;
    cudaGetSymbolAddress(&p, g_w2m); w2m = (uint2*)p;
    cudaGetSymbolAddress(&p, g_w2r); w2r = (uint2*)p;
    cudaGetSymbolAddress(&p, g_w3m); w3m = (uint2*)p;
    cudaGetSymbolAddress(&p, g_w3r); w3r = (uint2*)p;

    // smem words: A 4*2560=10240; B 4(or 8) stages x 8*(DOUT+4)*2 words
    const int SM256 = (10240 + 64 * (256 + 4) + 3 * 256 + 1024) * 4;   // 114688 B
    const int SMD128 = (10240 + 128 * (128 + 4) + 128) * 4;            // 109056 B
    cudaFuncSetAttribute(k_gemm_tc<128, 256>, cudaFuncAttributeMaxDynamicSharedMemorySize, SM256);
    cudaFuncSetAttribute(k_gemm_tc<256, 256>, cudaFuncAttributeMaxDynamicSharedMemorySize, SM256);
    cudaFuncSetAttribute(k_gemm_dual<256, 128>, cudaFuncAttributeMaxDynamicSharedMemorySize, SMD128);

    // fused prep: hist + z->fp16 + weight packs (independent memory streams)
    int histB = (E + 255) / 256;
    int zB = (N * 64 + 255) / 256;
    k_prep<<<histB + zB + 256, 256>>>(dst, E, z, N * 64, wm1, wr1, wm2, wr2, wm3, wr3, histB, zB);

    // CSR scan + scatter
    int nb = (N + 1023) / 1024;
    k_scan1<<<nb, 1024>>>(N);
    k_scan2<<<1, 128>>>(nb);
    k_scan3<<<(N + 255) / 256, 256>>>(N, E);
    k_scatter<<<(E + 255) / 256, 256>>>(src, dst, E);

    int aggBlocks = (N + 7) / 8;
    int gemmBlocks = (N + 127) / 128;

    // Layer 1 agg (mean of z, fp16)
    k_aggh<128><<<aggBlocks, 256>>>(hz, hM, N);
    // Layer 1: 128 -> 256 (aggregate-first)
    k_gemm_tc<128, 256><<<gemmBlocks, 512, SM256>>>(hM, hz, w1m, w1r, b1, g1, be1, hA, N);
    // Layer 2: 256 -> 256 (aggregate-first)
    k_aggh<256><<<aggBlocks, 256>>>(hA, hM, N);
    k_gemm_tc<256, 256><<<gemmBlocks, 512, SM256>>>(hM, hA, w2m, w2r, b2, g2, be2, hB, N);
    // Layer 3: 256 -> 128 (aggregate-AFTER): ym->hM, yr->hA
    k_gemm_dual<256, 128><<<gemmBlocks, 512, SMD128>>>(hB, w3m, w3r, b3, hM, hA, N);
    k_aggh<128><<<aggBlocks, 256>>>(hM, hB, N);                  // mean(ym) -> hB
    // Layer 3 LN + Layer 4 projection fused
    k_lnout<<<aggBlocks, 256>>>(hB, hA, g3, be3, wm4, wr4, b4, ym9, yr9, N);
    k_agg9<<<aggBlocks, 256>>>(ym9, yr9, (float*)d_out, N);
}

// round 16
// speedup vs baseline: 1.7334x; 1.0864x over previous
#include <cuda_runtime.h>
#include <cuda_fp16.h>
#include <cstdint>

// ================= static scratch =================
#define NMAX 100352
#define EMAX 1700000

__device__ int   g_deg[NMAX];     // zeroed at load; re-zeroed by k_agg9 each launch
__device__ int   g_off[NMAX + 1];
__device__ int   g_cur[NMAX];
__device__ int   g_csr[EMAX];
__device__ int   g_bsum[128];
__device__ float g_cnt[NMAX];
__device__ float g_ym9[(size_t)NMAX * 9];
__device__ float g_yr9[(size_t)NMAX * 9];
// fp16 activations / means
__device__ __align__(16) __half g_hz[(size_t)NMAX * 128];
__device__ __align__(16) __half g_hA[(size_t)NMAX * 256];
__device__ __align__(16) __half g_hB[(size_t)NMAX * 256];
__device__ __align__(16) __half g_hM[(size_t)NMAX * 256];
// k16-frag packed weights
__device__ uint2 g_w1m[(128 / 4) * 256];
__device__ uint2 g_w1r[(128 / 4) * 256];
__device__ uint2 g_w2m[(256 / 4) * 256];
__device__ uint2 g_w2r[(256 / 4) * 256];
__device__ uint2 g_w3m[(256 / 4) * 128];
__device__ uint2 g_w3r[(256 / 4) * 128];

// ================= helpers =================
__device__ __forceinline__ uint32_t f2h2(float lo, float hi) {
    uint32_t r;
    asm("cvt.rn.f16x2.f32 %0, %1, %2;" : "=r"(r) : "f"(hi), "f"(lo));
    return r;
}
__device__ __forceinline__ void mma_f16(float* c, uint32_t a0, uint32_t a1, uint32_t a2, uint32_t a3,
                                        uint32_t b0, uint32_t b1) {
    asm volatile("mma.sync.aligned.m16n8k16.row.col.f32.f16.f16.f32 "
                 "{%0,%1,%2,%3}, {%4,%5,%6,%7}, {%8,%9}, {%0,%1,%2,%3};"
                 : "+f"(c[0]), "+f"(c[1]), "+f"(c[2]), "+f"(c[3])
                 : "r"(a0), "r"(a1), "r"(a2), "r"(a3), "r"(b0), "r"(b1));
}
__device__ __forceinline__ void ldsm_x4(uint32_t& r0, uint32_t& r1, uint32_t& r2, uint32_t& r3,
                                        uint32_t addr) {
    asm volatile("ldmatrix.sync.aligned.m8n8.x4.shared.b16 {%0,%1,%2,%3}, [%4];"
                 : "=r"(r0), "=r"(r1), "=r"(r2), "=r"(r3) : "r"(addr));
}
__device__ __forceinline__ uint32_t su32(const void* p) {
    uint32_t a;
    asm("{ .reg .u64 t; cvta.to.shared.u64 t, %1; cvt.u32.u64 %0, t; }" : "=r"(a) : "l"(p));
    return a;
}
__device__ __forceinline__ void cpa16(uint32_t dst, const void* src, bool pred) {
    int sz = pred ? 16 : 0;
    asm volatile("cp.async.cg.shared.global [%0], [%1], 16, %2;" :: "r"(dst), "l"(src), "r"(sz));
}
#define CP_COMMIT() asm volatile("cp.async.commit_group;" ::: "memory")
#define CP_WAIT1()  asm volatile("cp.async.wait_group 1;" ::: "memory")
#define CP_WAIT0()  asm volatile("cp.async.wait_group 0;" ::: "memory")

// ================= fused prep: hist + z->fp16 + weight packing =================
__device__ __forceinline__ void packq_one(const float* __restrict__ W, uint2* __restrict__ Wq,
                                          int N, int i) {
    int r = i / N, n = i - r * N;
    int kg = r >> 2, tq = r & 3;
    int k0 = kg * 16 + 2 * tq;
    uint2 v;
    v.x = f2h2(W[(size_t)k0 * N + n], W[(size_t)(k0 + 1) * N + n]);
    v.y = f2h2(W[(size_t)(k0 + 8) * N + n], W[(size_t)(k0 + 9) * N + n]);
    Wq[i] = v;
}
__global__ void k_prep(const int* __restrict__ dst, int E,
                       const float* __restrict__ z, int n2,
                       const float* __restrict__ wm1, const float* __restrict__ wr1,
                       const float* __restrict__ wm2, const float* __restrict__ wr2,
                       const float* __restrict__ wm3, const float* __restrict__ wr3,
                       int histB, int zB) {
    int b = blockIdx.x;
    if (b < histB) {
        int e = b * 256 + threadIdx.x;
        if (e < E) atomicAdd(&g_deg[dst[e]], 1);
    } else if (b < histB + zB) {
        int i = (b - histB) * 256 + threadIdx.x;
        if (i < n2) {
            float2 v = ((const float2*)z)[i];
            ((__half2*)g_hz)[i] = __floats2half2_rn(v.x, v.y);
        }
    } else {
        int i = (b - histB - zB) * 256 + threadIdx.x;   // 0..65535
        if (i < 8192) packq_one(wm1, g_w1m, 256, i);
        else if (i < 16384) packq_one(wr1, g_w1r, 256, i - 8192);
        else if (i < 32768) packq_one(wm2, g_w2m, 256, i - 16384);
        else if (i < 49152) packq_one(wr2, g_w2r, 256, i - 32768);
        else if (i < 57344) packq_one(wm3, g_w3m, 128, i - 49152);
        else packq_one(wr3, g_w3r, 128, i - 57344);
    }
}

// ================= CSR scan / scatter =================
__global__ void k_scan1(int n) {
    __shared__ int sh[1024];
    int i = blockIdx.x * 1024 + threadIdx.x;
    int d = (i < n) ? g_deg[i] : 0;
    sh[threadIdx.x] = d;
    __syncthreads();
    for (int o = 1; o < 1024; o <<= 1) {
        int v = (threadIdx.x >= o) ? sh[threadIdx.x - o] : 0;
        __syncthreads();
        sh[threadIdx.x] += v;
        __syncthreads();
    }
    if (i < n) g_off[i] = sh[threadIdx.x] - d;
    if (threadIdx.x == 1023) g_bsum[blockIdx.x] = sh[1023];
}
__global__ void k_scan2(int nb) {
    __shared__ int sh[128];
    int d = (threadIdx.x < nb) ? g_bsum[threadIdx.x] : 0;
    sh[threadIdx.x] = d;
    __syncthreads();
    for (int o = 1; o < 128; o <<= 1) {
        int v = (threadIdx.x >= o) ? sh[threadIdx.x - o] : 0;
        __syncthreads();
        sh[threadIdx.x] += v;
        __syncthreads();
    }
    if (threadIdx.x < nb) g_bsum[threadIdx.x] = sh[threadIdx.x] - d;
}
__global__ void k_scan3(int n, int E) {
    int i = blockIdx.x * blockDim.x + threadIdx.x;
    if (i == 0) g_off[n] = E;
    if (i >= n) return;
    int off = g_off[i] + g_bsum[i >> 10];
    g_off[i] = off;
    g_cur[i] = off;
    int d = g_deg[i];
    g_cnt[i] = (d > 0) ? (float)d : 1.0f;
}
__global__ void k_scatter(const int* __restrict__ src, const int* __restrict__ dst, int E) {
    int e = blockIdx.x * blockDim.x + threadIdx.x;
    if (e < E) {
        int p = atomicAdd(&g_cur[dst[e]], 1);
        g_csr[p] = src[e];
    }
}

// ================= mean aggregation (half in/out, fp32 acc) =================
template <int D>
__global__ void k_aggh(const __half* __restrict__ x, __half* __restrict__ meanp, int n) {
    int gw = (blockIdx.x * blockDim.x + threadIdx.x) >> 5;
    int lane = threadIdx.x & 31;
    if (gw >= n) return;
    int b = g_off[gw], e = g_off[gw + 1];
    constexpr int NH2 = D / 64;
    float2 acc[NH2], acc2[NH2];
#pragma unroll
    for (int h = 0; h < NH2; h++) {
        acc[h] = make_float2(0.f, 0.f);
        acc2[h] = make_float2(0.f, 0.f);
    }
    auto addrow = [&](const __half* rp, float2* a) {
        uint32_t w[NH2];
        if (NH2 == 4) {
            uint4 u = ((const uint4*)rp)[lane];
            w[0] = u.x; w[1] = u.y; w[2] = u.z; w[3] = u.w;
        } else {
            uint2 u = ((const uint2*)rp)[lane];
            w[0] = u.x; w[1] = u.y;
        }
#pragma unroll
        for (int h = 0; h < NH2; h++) {
            float2 f = __half22float2(*(__half2*)&w[h]);
            a[h].x += f.x;
            a[h].y += f.y;
        }
    };
    int j = b;
    for (; j + 1 < e; j += 2) {
        addrow(x + (size_t)g_csr[j] * D, acc);
        addrow(x + (size_t)g_csr[j + 1] * D, acc2);
    }
    if (j < e) addrow(x + (size_t)g_csr[j] * D, acc);

    float inv = 1.0f / g_cnt[gw];
    uint32_t o[NH2];
#pragma unroll
    for (int h = 0; h < NH2; h++) {
        __half2 hv = __floats2half2_rn((acc[h].x + acc2[h].x) * inv, (acc[h].y + acc2[h].y) * inv);
        o[h] = *(uint32_t*)&hv;
    }
    __half* mo = meanp + (size_t)gw * D;
    if (NH2 == 4) ((uint4*)mo)[lane] = make_uint4(o[0], o[1], o[2], o[3]);
    else ((uint2*)mo)[lane] = make_uint2(o[0], o[1]);
}

// ================= fp16 mma fused dual-GEMM + bias + LN + ReLU =================
// M=64 tiles, 256 threads (8 warps = Wm2 x Wn4), 3-stage pipeline, 2 CTAs/SM.
template <int DIN, int DOUT>
__launch_bounds__(256, 2)
__global__ void k_gemm_tc(const __half* __restrict__ A0, const __half* __restrict__ A1,
                          const uint2* __restrict__ W0q, const uint2* __restrict__ W1q,
                          const float* __restrict__ bias, const float* __restrict__ gamma,
                          const float* __restrict__ beta, __half* __restrict__ out, int n) {
    extern __shared__ float sm[];
    constexpr int NCH = DIN / 32;
    constexpr int TOT = 2 * NCH;
    constexpr int NT = DOUT / 32;
    constexpr int APH = 40;
    constexpr int AHSZ = 64 * APH;        // halves per A stage
    constexpr int BP2 = DOUT + 4;         // B pitch (uint2)
    constexpr int BSZ2 = 8 * BP2;

    __half* Ah = (__half*)sm;
    __half* Ab[3] = { Ah, Ah + AHSZ, Ah + 2 * AHSZ };
    float* after = sm + (3 * AHSZ) / 2;
    uint2* Bb[3] = { (uint2*)after, (uint2*)after + BSZ2, (uint2*)after + 2 * BSZ2 };
    float* sp = after + 3 * BSZ2 * 2;
    float* sln = sp + 3 * DOUT;           // [64][4] float2

    int t = threadIdx.x;
    int wid = t >> 5, lane = t & 31;
    int g = lane >> 2, tq = lane & 3;
    int mw = wid & 1, nq = wid >> 1;
    int nbase = nq * (DOUT / 4);
    int row0 = blockIdx.x * 64;
    uint32_t poff = (uint32_t)(((lane & 15) * APH + ((lane & 16) >> 1)) * 2);
    uint32_t abase_s[3] = { su32(Ab[0]), su32(Ab[1]), su32(Ab[2]) };

    for (int i = t; i < DOUT; i += 256) {
        sp[i] = bias[i];
        sp[DOUT + i] = gamma[i];
        sp[2 * DOUT + i] = beta[i];
    }
    __syncthreads();

    float acc[2][NT][4];
#pragma unroll
    for (int ms = 0; ms < 2; ms++)
#pragma unroll
        for (int nt = 0; nt < NT; nt++)
#pragma unroll
            for (int j = 0; j < 4; j++) acc[ms][nt][j] = 0.f;

    auto copy_chunk = [&](int c, int ib) {
        const __half* A = (c < NCH) ? A0 : A1;
        const uint2* W = (c < NCH) ? W0q : W1q;
        int cc = (c < NCH) ? c : c - NCH;
        int k0 = cc * 32;
        uint32_t abase = abase_s[ib];
        uint32_t bbase = su32(Bb[ib]);
        {   // A: 64 rows x 64B = 256 cp16, one per thread
            int r = t >> 2, seg = t & 3;
            int gr = row0 + r;
            bool ok = gr < n;
            int cr = ok ? gr : (n - 1);
            cpa16(abase + (uint32_t)(r * 80 + seg * 16),
                  A + (size_t)cr * DIN + k0 + seg * 8, ok);
        }
#pragma unroll
        for (int i = 0; i < DOUT / 64; i++) {  // B: 8 rows x DOUT uint2 (16B = 2 uint2)
            int s = t + i * 256;
            int kr = s / (DOUT / 2), c2 = (s % (DOUT / 2)) * 2;
            cpa16(bbase + (uint32_t)(kr * BP2 + c2) * 8,
                  W + (size_t)(cc * 8 + kr) * DOUT + c2, true);
        }
    };

    auto mma_chunk = [&](int ib) {
        const uint2* Bs = Bb[ib];
        uint32_t abase = abase_s[ib];
#pragma unroll
        for (int ks = 0; ks < 2; ks++) {
            int kb = ks * 16;
            uint2 bf[NT];
#pragma unroll
            for (int nt = 0; nt < NT; nt++)
                bf[nt] = Bs[(ks * 4 + tq) * BP2 + nbase + nt * 8 + g];
#pragma unroll
            for (int ms = 0; ms < 2; ms++) {
                int ar0 = mw * 32 + ms * 16;
                uint32_t a0, a1, a2, a3;
                ldsm_x4(a0, a1, a2, a3, abase + (uint32_t)((ar0 * APH + kb) * 2) + poff);
#pragma unroll
                for (int nt = 0; nt < NT; nt++)
                    mma_f16(acc[ms][nt], a0, a1, a2, a3, bf[nt].x, bf[nt].y);
            }
        }
    };

    copy_chunk(0, 0); CP_COMMIT();
    copy_chunk(1, 1); CP_COMMIT();
    for (int c = 0; c < TOT; c++) {
        if (c < TOT - 1) CP_WAIT1(); else CP_WAIT0();
        __syncthreads();
        if (c + 2 < TOT) { copy_chunk(c + 2, (c + 2) % 3); CP_COMMIT(); }
        mma_chunk(c % 3);
    }

    // ---- epilogue: +bias, LN over DOUT (4 n-quarter partials), ReLU, fp16 out ----
#pragma unroll
    for (int ms = 0; ms < 2; ms++) {
        float s0 = 0.f, ss0 = 0.f, s1 = 0.f, ss1 = 0.f;
#pragma unroll
        for (int nt = 0; nt < NT; nt++) {
            int col = nbase + nt * 8 + 2 * tq;
            float b0 = sp[col], b1 = sp[col + 1];
            acc[ms][nt][0] += b0; acc[ms][nt][1] += b1;
            acc[ms][nt][2] += b0; acc[ms][nt][3] += b1;
            s0 += acc[ms][nt][0] + acc[ms][nt][1];
            ss0 += acc[ms][nt][0] * acc[ms][nt][0] + acc[ms][nt][1] * acc[ms][nt][1];
            s1 += acc[ms][nt][2] + acc[ms][nt][3];
            ss1 += acc[ms][nt][2] * acc[ms][nt][2] + acc[ms][nt][3] * acc[ms][nt][3];
        }
#pragma unroll
        for (int o = 1; o <= 2; o <<= 1) {
            s0 += __shfl_xor_sync(0xffffffffu, s0, o);
            ss0 += __shfl_xor_sync(0xffffffffu, ss0, o);
            s1 += __shfl_xor_sync(0xffffffffu, s1, o);
            ss1 += __shfl_xor_sync(0xffffffffu, ss1, o);
        }
        if (tq == 0) {
            int r0 = mw * 32 + ms * 16 + g;
            ((float2*)sln)[r0 * 4 + nq] = make_float2(s0, ss0);
            ((float2*)sln)[(r0 + 8) * 4 + nq] = make_float2(s1, ss1);
        }
    }
    __syncthreads();
#pragma unroll
    for (int ms = 0; ms < 2; ms++) {
        int rl0 = mw * 32 + ms * 16 + g, rl1 = rl0 + 8;
        float s0 = 0.f, ss0 = 0.f, s1 = 0.f, ss1 = 0.f;
#pragma unroll
        for (int q = 0; q < 4; q++) {
            float2 p0 = ((float2*)sln)[rl0 * 4 + q];
            float2 p1 = ((float2*)sln)[rl1 * 4 + q];
            s0 += p0.x; ss0 += p0.y;
            s1 += p1.x; ss1 += p1.y;
        }
        float mu0 = s0 * (1.0f / DOUT);
        float rs0 = rsqrtf(ss0 * (1.0f / DOUT) - mu0 * mu0 + 1e-5f);
        float mu1 = s1 * (1.0f / DOUT);
        float rs1 = rsqrtf(ss1 * (1.0f / DOUT) - mu1 * mu1 + 1e-5f);
        int grow0 = row0 + rl0, grow1 = row0 + rl1;
#pragma unroll
        for (int nt = 0; nt < NT; nt++) {
            int col = nbase + nt * 8 + 2 * tq;
            float ga0 = sp[DOUT + col], ga1 = sp[DOUT + col + 1];
            float bt0 = sp[2 * DOUT + col], bt1 = sp[2 * DOUT + col + 1];
            if (grow0 < n) {
                float vx = fmaxf((acc[ms][nt][0] - mu0) * rs0 * ga0 + bt0, 0.f);
                float vy = fmaxf((acc[ms][nt][1] - mu0) * rs0 * ga1 + bt1, 0.f);
                *(__half2*)(out + (size_t)grow0 * DOUT + col) = __floats2half2_rn(vx, vy);
            }
            if (grow1 < n) {
                float vx = fmaxf((acc[ms][nt][2] - mu1) * rs1 * ga0 + bt0, 0.f);
                float vy = fmaxf((acc[ms][nt][3] - mu1) * rs1 * ga1 + bt1, 0.f);
                *(__half2*)(out + (size_t)grow1 * DOUT + col) = __floats2half2_rn(vx, vy);
            }
        }
    }
}

// ================= dual-output GEMM: YM = X@W0, YR = X@W1 + b (fp16 out) =================
template <int DIN, int DOUT>
__launch_bounds__(256, 2)
__global__ void k_gemm_dual(const __half* __restrict__ X,
                            const uint2* __restrict__ W0q, const uint2* __restrict__ W1q,
                            const float* __restrict__ bias,
                            __half* __restrict__ ym, __half* __restrict__ yr, int n) {
    extern __shared__ float sm[];
    constexpr int NCH = DIN / 32;
    constexpr int NT = DOUT / 32;
    constexpr int APH = 40;
    constexpr int AHSZ = 64 * APH;
    constexpr int BP2 = DOUT + 4;
    constexpr int BSZ2 = 8 * BP2;

    __half* Ah = (__half*)sm;
    __half* Ab[3] = { Ah, Ah + AHSZ, Ah + 2 * AHSZ };
    float* after = sm + (3 * AHSZ) / 2;
    uint2* B0b[3] = { (uint2*)after, (uint2*)after + BSZ2, (uint2*)after + 2 * BSZ2 };
    uint2* B1b[3] = { (uint2*)after + 3 * BSZ2, (uint2*)after + 4 * BSZ2, (uint2*)after + 5 * BSZ2 };
    float* sp = after + 6 * BSZ2 * 2;

    int t = threadIdx.x;
    int wid = t >> 5, lane = t & 31;
    int g = lane >> 2, tq = lane & 3;
    int mw = wid & 1, nq = wid >> 1;
    int nbase = nq * (DOUT / 4);
    int row0 = blockIdx.x * 64;
    uint32_t poff = (uint32_t)(((lane & 15) * APH + ((lane & 16) >> 1)) * 2);
    uint32_t abase_s[3] = { su32(Ab[0]), su32(Ab[1]), su32(Ab[2]) };

    for (int i = t; i < DOUT; i += 256) sp[i] = bias[i];
    __syncthreads();

    float accM[2][NT][4], accR[2][NT][4];
#pragma unroll
    for (int ms = 0; ms < 2; ms++)
#pragma unroll
        for (int nt = 0; nt < NT; nt++)
#pragma unroll
            for (int j = 0; j < 4; j++) { accM[ms][nt][j] = 0.f; accR[ms][nt][j] = 0.f; }

    auto copy_chunk = [&](int c, int ib) {
        int k0 = c * 32;
        uint32_t abase = abase_s[ib];
        uint32_t b0base = su32(B0b[ib]);
        uint32_t b1base = su32(B1b[ib]);
        {
            int r = t >> 2, seg = t & 3;
            int gr = row0 + r;
            bool ok = gr < n;
            int cr = ok ? gr : (n - 1);
            cpa16(abase + (uint32_t)(r * 80 + seg * 16),
                  X + (size_t)cr * DIN + k0 + seg * 8, ok);
        }
#pragma unroll
        for (int i = 0; i < DOUT / 64; i++) {
            int s = t + i * 256;
            int kr = s / (DOUT / 2), c2 = (s % (DOUT / 2)) * 2;
            size_t wo = (size_t)(c * 8 + kr) * DOUT + c2;
            uint32_t so = (uint32_t)(kr * BP2 + c2) * 8;
            cpa16(b0base + so, W0q + wo, true);
            cpa16(b1base + so, W1q + wo, true);
        }
    };

    auto mma_chunk = [&](int ib) {
        const uint2* B0s = B0b[ib];
        const uint2* B1s = B1b[ib];
        uint32_t abase = abase_s[ib];
#pragma unroll
        for (int ks = 0; ks < 2; ks++) {
            int kb = ks * 16;
            uint2 bfM[NT], bfR[NT];
#pragma unroll
            for (int nt = 0; nt < NT; nt++) {
                int bi = (ks * 4 + tq) * BP2 + nbase + nt * 8 + g;
                bfM[nt] = B0s[bi];
                bfR[nt] = B1s[bi];
            }
#pragma unroll
            for (int ms = 0; ms < 2; ms++) {
                int ar0 = mw * 32 + ms * 16;
                uint32_t a0, a1, a2, a3;
                ldsm_x4(a0, a1, a2, a3, abase + (uint32_t)((ar0 * APH + kb) * 2) + poff);
#pragma unroll
                for (int nt = 0; nt < NT; nt++) {
                    mma_f16(accM[ms][nt], a0, a1, a2, a3, bfM[nt].x, bfM[nt].y);
                    mma_f16(accR[ms][nt], a0, a1, a2, a3, bfR[nt].x, bfR[nt].y);
                }
            }
        }
    };

    copy_chunk(0, 0); CP_COMMIT();
    copy_chunk(1, 1); CP_COMMIT();
    for (int c = 0; c < NCH; c++) {
        if (c < NCH - 1) CP_WAIT1(); else CP_WAIT0();
        __syncthreads();
        if (c + 2 < NCH) { copy_chunk(c + 2, (c + 2) % 3); CP_COMMIT(); }
        mma_chunk(c % 3);
    }

#pragma unroll
    for (int ms = 0; ms < 2; ms++) {
        int rl0 = mw * 32 + ms * 16 + g, rl1 = rl0 + 8;
        int grow0 = row0 + rl0, grow1 = row0 + rl1;
#pragma unroll
        for (int nt = 0; nt < NT; nt++) {
            int col = nbase + nt * 8 + 2 * tq;
            float b0 = sp[col], b1 = sp[col + 1];
            if (grow0 < n) {
                *(__half2*)(ym + (size_t)grow0 * DOUT + col) = __floats2half2_rn(accM[ms][nt][0], accM[ms][nt][1]);
                *(__half2*)(yr + (size_t)grow0 * DOUT + col) = __floats2half2_rn(accR[ms][nt][0] + b0, accR[ms][nt][1] + b1);
            }
            if (grow1 < n) {
                *(__half2*)(ym + (size_t)grow1 * DOUT + col) = __floats2half2_rn(accM[ms][nt][2], accM[ms][nt][3]);
                *(__half2*)(yr + (size_t)grow1 * DOUT + col) = __floats2half2_rn(accR[ms][nt][2] + b0, accR[ms][nt][3] + b1);
            }
        }
    }
}

// ===== fused: x3 = ReLU(LN(mean + yr)); ym9 = x3@Wm4; yr9 = x3@Wr4 + b4 =====
__global__ void k_lnout(const __half* __restrict__ meanp, const __half* __restrict__ yr,
                        const float* __restrict__ gamma, const float* __restrict__ beta,
                        const float* __restrict__ wm, const float* __restrict__ wr,
                        const float* __restrict__ bias,
                        float* __restrict__ ym9, float* __restrict__ yr9, int n) {
    __shared__ float swm[128 * 9];
    __shared__ float swr[128 * 9];
    __shared__ float sb[9];
    for (int i = threadIdx.x; i < 128 * 9; i += blockDim.x) {
        swm[i] = wm[i];
        swr[i] = wr[i];
    }
    if (threadIdx.x < 9) sb[threadIdx.x] = bias[threadIdx.x];
    __syncthreads();

    int row = (blockIdx.x * blockDim.x + threadIdx.x) >> 5;
    int lane = threadIdx.x & 31;
    if (row >= n) return;

    uint2 mu2 = ((const uint2*)(meanp + (size_t)row * 128))[lane];
    uint2 yu2 = ((const uint2*)(yr + (size_t)row * 128))[lane];
    float2 m0 = __half22float2(*(__half2*)&mu2.x), m1 = __half22float2(*(__half2*)&mu2.y);
    float2 y0 = __half22float2(*(__half2*)&yu2.x), y1 = __half22float2(*(__half2*)&yu2.y);
    float v[4] = { m0.x + y0.x, m0.y + y0.y, m1.x + y1.x, m1.y + y1.y };
    float s = v[0] + v[1] + v[2] + v[3];
    float ss = v[0] * v[0] + v[1] * v[1] + v[2] * v[2] + v[3] * v[3];
#pragma unroll
    for (int o = 16; o; o >>= 1) {
        s += __shfl_xor_sync(0xffffffffu, s, o);
        ss += __shfl_xor_sync(0xffffffffu, ss, o);
    }
    float mu = s * (1.0f / 128.0f);
    float var = ss * (1.0f / 128.0f) - mu * mu;
    float rs = rsqrtf(var + 1e-5f);
    float4 g4 = ((const float4*)gamma)[lane];
    float4 b4 = ((const float4*)beta)[lane];
    float x4[4];
    x4[0] = fmaxf((v[0] - mu) * rs * g4.x + b4.x, 0.f);
    x4[1] = fmaxf((v[1] - mu) * rs * g4.y + b4.y, 0.f);
    x4[2] = fmaxf((v[2] - mu) * rs * g4.z + b4.z, 0.f);
    x4[3] = fmaxf((v[3] - mu) * rs * g4.w + b4.w, 0.f);

    float om[9], orr[9];
#pragma unroll
    for (int j = 0; j < 9; j++) { om[j] = 0.f; orr[j] = 0.f; }
#pragma unroll
    for (int q = 0; q < 4; q++) {
        int k = lane * 4 + q;
#pragma unroll
        for (int j = 0; j < 9; j++) {
            om[j] += x4[q] * swm[k * 9 + j];
            orr[j] += x4[q] * swr[k * 9 + j];
        }
    }
#pragma unroll
    for (int j = 0; j < 9; j++)
#pragma unroll
        for (int o = 16; o; o >>= 1) {
            om[j] += __shfl_xor_sync(0xffffffffu, om[j], o);
            orr[j] += __shfl_xor_sync(0xffffffffu, orr[j], o);
        }
    if (lane < 9) {
        ym9[(size_t)row * 9 + lane] = om[lane];
        yr9[(size_t)row * 9 + lane] = orr[lane] + sb[lane];
    }
}

// ================= final: out = mean(ym9[src]) + yr9; re-zero g_deg =================
__global__ void k_agg9(const float* __restrict__ ym9, const float* __restrict__ yr9,
                       float* __restrict__ out, int n) {
    int gt = blockIdx.x * blockDim.x + threadIdx.x;
    if (gt < NMAX) g_deg[gt] = 0;
    int gw = gt >> 5;
    int lane = threadIdx.x & 31;
    if (gw >= n) return;
    int b = g_off[gw], e = g_off[gw + 1];
    float acc[9];
#pragma unroll
    for (int j = 0; j < 9; j++) acc[j] = 0.f;
    for (int j = b + lane; j < e; j += 32) {
        const float* row = ym9 + (size_t)g_csr[j] * 9;
#pragma unroll
        for (int c = 0; c < 9; c++) acc[c] += row[c];
    }
#pragma unroll
    for (int c = 0; c < 9; c++)
#pragma unroll
        for (int s = 16; s; s >>= 1) acc[c] += __shfl_xor_sync(0xffffffffu, acc[c], s);
    if (lane < 9) {
        float inv = 1.0f / g_cnt[gw];
        out[(size_t)gw * 9 + lane] = acc[lane] * inv + yr9[(size_t)gw * 9 + lane];
    }
}

// ================= launch =================
extern "C" void kernel_launch(void* const* d_in, const int* in_sizes, int n_in,
                              void* d_out, int out_size) {
    const float* z = (const float*)d_in[0];
    const int* ei = (const int*)d_in[1];
    const float* wm1 = (const float*)d_in[2];
    const float* wr1 = (const float*)d_in[3];
    const float* b1 = (const float*)d_in[4];
    const float* g1 = (const float*)d_in[5];
    const float* be1 = (const float*)d_in[6];
    const float* wm2 = (const float*)d_in[7];
    const float* wr2 = (const float*)d_in[8];
    const float* b2 = (const float*)d_in[9];
    const float* g2 = (const float*)d_in[10];
    const float* be2 = (const float*)d_in[11];
    const float* wm3 = (const float*)d_in[12];
    const float* wr3 = (const float*)d_in[13];
    const float* b3 = (const float*)d_in[14];
    const float* g3 = (const float*)d_in[15];
    const float* be3 = (const float*)d_in[16];
    const float* wm4 = (const float*)d_in[17];
    const float* wr4 = (const float*)d_in[18];
    const float* b4 = (const float*)d_in[19];

    int N = in_sizes[0] / 128;
    int E = in_sizes[1] / 2;
    const int* src = ei;
    const int* dst = ei + E;

    __half *hz, *hA, *hB, *hM;
    float *ym9, *yr9;
    uint2 *w1m, *w1r, *w2m, *w2r, *w3m, *w3r;
    void* p;
    cudaGetSymbolAddress(&p, g_hz);  hz = (__half*)p;
    cudaGetSymbolAddress(&p, g_hA);  hA = (__half*)p;
    cudaGetSymbolAddress(&p, g_hB);  hB = (__half*)p;
    cudaGetSymbolAddress(&p, g_hM);  hM = (__half*)p;
    cudaGetSymbolAddress(&p, g_ym9); ym9 = (float*)p;
    cudaGetSymbolAddress(&p, g_yr9); yr9 = (float*)p;
    cudaGetSymbolAddress(&p, g_w1m); w1m = (uint2*)p;
    cudaGetSymbolAddress(&p, g_w1r); w1r = (uint2*)p;
    cudaGetSymbolAddress(&p, g_w2m); w2m = (uint2*)p;
    cudaGetSymbolAddress(&p, g_w2r); w2r = (uint2*)p;
    cudaGetSymbolAddress(&p, g_w3m); w3m = (uint2*)p;
    cudaGetSymbolAddress(&p, g_w3r); w3r = (uint2*)p;

    // smem words: A 3*64*40/2=3840; B 3(or 6) stages x 8*(DOUT+4)*2 words
    const int SM256 = (3840 + 48 * (256 + 4) + 3 * 256 + 512) * 4;   // 70,400 B
    const int SMD128 = (3840 + 96 * (128 + 4) + 128) * 4;            // 66,560 B
    cudaFuncSetAttribute(k_gemm_tc<128, 256>, cudaFuncAttributeMaxDynamicSharedMemorySize, SM256);
    cudaFuncSetAttribute(k_gemm_tc<256, 256>, cudaFuncAttributeMaxDynamicSharedMemorySize, SM256);
    cudaFuncSetAttribute(k_gemm_dual<256, 128>, cudaFuncAttributeMaxDynamicSharedMemorySize, SMD128);

    // fused prep: hist + z->fp16 + weight packs
    int histB = (E + 255) / 256;
    int zB = (N * 64 + 255) / 256;
    k_prep<<<histB + zB + 256, 256>>>(dst, E, z, N * 64, wm1, wr1, wm2, wr2, wm3, wr3, histB, zB);

    // CSR scan + scatter
    int nb = (N + 1023) / 1024;
    k_scan1<<<nb, 1024>>>(N);
    k_scan2<<<1, 128>>>(nb);
    k_scan3<<<(N + 255) / 256, 256>>>(N, E);
    k_scatter<<<(E + 255) / 256, 256>>>(src, dst, E);

    int aggBlocks = (N + 7) / 8;
    int gemmBlocks = (N + 63) / 64;

    // Layer 1 agg (mean of z, fp16)
    k_aggh<128><<<aggBlocks, 256>>>(hz, hM, N);
    // Layer 1: 128 -> 256 (aggregate-first)
    k_gemm_tc<128, 256><<<gemmBlocks, 256, SM256>>>(hM, hz, w1m, w1r, b1, g1, be1, hA, N);
    // Layer 2: 256 -> 256 (aggregate-first)
    k_aggh<256><<<aggBlocks, 256>>>(hA, hM, N);
    k_gemm_tc<256, 256><<<gemmBlocks, 256, SM256>>>(hM, hA, w2m, w2r, b2, g2, be2, hB, N);
    // Layer 3: 256 -> 128 (aggregate-AFTER): ym->hM, yr->hA
    k_gemm_dual<256, 128><<<gemmBlocks, 256, SMD128>>>(hB, w3m, w3r, b3, hM, hA, N);
    k_aggh<128><<<aggBlocks, 256>>>(hM, hB, N);                  // mean(ym) -> hB
    // Layer 3 LN + Layer 4 projection fused
    k_lnout<<<aggBlocks, 256>>>(hB, hA, g3, be3, wm4, wr4, b4, ym9, yr9, N);
    k_agg9<<<aggBlocks, 256>>>(ym9, yr9, (float*)d_out, N);
}